// round 6
// baseline (speedup 1.0000x reference)
#include <cuda_runtime.h>
#include <math.h>
#include <stdint.h>

#define NPAT 50000
#define NICD 591
#define NNDC 2042
#define NTOTAL 52633
#define NSOFT 102633   /* sum of destination counts over 4 relations */
#define CDIM 128
#define HH 8
#define DD 16
#define NEDGE 250000
#define OUTD 90

// block counts for merged-type GEMM grids
#define NBP 391   /* ceil(50000/128) */
#define NBI 5     /* ceil(591/128) */
#define NBN 16    /* ceil(2042/128) */
#define NBALL (NBP + NBI + NBN)   /* 412 */

// rel_transform merged grid ranges
#define RTP 1563  /* ceil(50000/32) */
#define RTI 19    /* ceil(591/32) */
#define RTN 64    /* ceil(2042/32) */
#define RTALL (RTP + RTI + RTN)   /* 1646 */

// ---------------- scratch (device globals; no allocation allowed) ----------------
__device__ float g_x[NTOTAL * CDIM];
__device__ float g_k[NTOTAL * CDIM];
__device__ float g_q[NTOTAL * CDIM];
__device__ float g_v[NTOTAL * CDIM];
__device__ float g_agg[NTOTAL * CDIM];
__device__ float g_krP0[NPAT * CDIM];
__device__ float g_vrP0[NPAT * CDIM];
__device__ float g_krP1[NPAT * CDIM];
__device__ float g_vrP1[NPAT * CDIM];
__device__ float g_krI[NICD * CDIM];
__device__ float g_vrI[NICD * CDIM];
__device__ float g_krN[NNDC * CDIM];
__device__ float g_vrN[NNDC * CDIM];
__device__ float g_alpha[4 * NEDGE * HH];
__device__ float g_ssum[NSOFT * HH];

__device__ __forceinline__ float geluf(float x) {
    float t = tanhf(0.7978845608028654f * (x + 0.044715f * x * x * x));
    return 0.5f * x * (1.0f + t);
}

// split a pair of floats into packed bf16x2 hi and lo parts (Ootomo 3xBF16)
__device__ __forceinline__ void split_pair(float v0, float v1, uint32_t& h, uint32_t& l) {
    uint32_t hh;
    asm("cvt.rn.bf16x2.f32 %0, %1, %2;" : "=r"(hh) : "f"(v1), "f"(v0));
    float h0 = __uint_as_float(hh << 16);
    float h1 = __uint_as_float(hh & 0xffff0000u);
    float l0 = v0 - h0;
    float l1 = v1 - h1;
    uint32_t ll;
    asm("cvt.rn.bf16x2.f32 %0, %1, %2;" : "=r"(ll) : "f"(l1), "f"(l0));
    h = hh; l = ll;
}

__device__ __forceinline__ void mma_bf16(float* c, const uint32_t* a, const uint32_t* b) {
    asm volatile("mma.sync.aligned.m16n8k16.row.col.f32.bf16.bf16.f32 "
                 "{%0,%1,%2,%3}, {%4,%5,%6,%7}, {%8,%9}, {%0,%1,%2,%3};"
                 : "+f"(c[0]), "+f"(c[1]), "+f"(c[2]), "+f"(c[3])
                 : "r"(a[0]), "r"(a[1]), "r"(a[2]), "r"(a[3]),
                   "r"(b[0]), "r"(b[1]));
}

#define SA 20   // smem stride in uint32 (conflict-free fragment loads)

// ---------------- GEMM mainloop core (shared by all GEMM kernels) ----------------
// Accumulates act(X)[row0:row0+128, :128] @ W[128, N] into c.
template<int INACT>
__device__ __forceinline__ void gemm_core(
    const float* __restrict__ X,
    const float* __restrict__ W, int ldw,
    int M, int N, int row0,
    float c[2][8][4],
    uint32_t (*Ah)[SA], uint32_t (*Al)[SA],
    uint32_t (*Bh)[SA], uint32_t (*Bl)[SA])
{
    const int tid = threadIdx.x;
    const int lane = tid & 31;
    const int wid = tid >> 5;
    const int warp_m = wid >> 1;
    const int warp_n = wid & 1;
    const int gi = lane >> 2;
    const int tig = lane & 3;

    const int ar = tid >> 1;
    const int akh = tid & 1;
    const bool arow_ok = (row0 + ar) < M;
    const float* xrow = X + (size_t)(row0 + ar) * CDIM;
    const int bkp = tid >> 4;
    const int bc0 = tid & 15;

    for (int kc = 0; kc < CDIM; kc += 32) {
#pragma unroll
        for (int i = 0; i < 4; i++) {
            float4 xv = make_float4(0.f, 0.f, 0.f, 0.f);
            if (arow_ok) xv = *reinterpret_cast<const float4*>(xrow + kc + akh * 16 + i * 4);
            if (INACT == 1) {
                xv.x = geluf(xv.x); xv.y = geluf(xv.y);
                xv.z = geluf(xv.z); xv.w = geluf(xv.w);
            }
            uint32_t h0, l0, h1, l1;
            split_pair(xv.x, xv.y, h0, l0);
            split_pair(xv.z, xv.w, h1, l1);
            int kp = akh * 8 + i * 2;
            Ah[ar][kp] = h0;     Al[ar][kp] = l0;
            Ah[ar][kp + 1] = h1; Al[ar][kp + 1] = l1;
        }
        {
            const float* w0 = W + (size_t)(kc + 2 * bkp) * ldw;
            const float* w1 = w0 + ldw;
#pragma unroll
            for (int i = 0; i < 8; i++) {
                int n = bc0 + 16 * i;
                float v0 = (n < N) ? w0[n] : 0.0f;
                float v1 = (n < N) ? w1[n] : 0.0f;
                uint32_t h, l;
                split_pair(v0, v1, h, l);
                Bh[n][bkp] = h;
                Bl[n][bkp] = l;
            }
        }
        __syncthreads();

#pragma unroll
        for (int ks = 0; ks < 2; ks++) {
            const int kb = ks * 8;
            uint32_t ah[2][4], al[2][4];
#pragma unroll
            for (int am = 0; am < 2; am++) {
                int rb = warp_m * 32 + am * 16 + gi;
                ah[am][0] = Ah[rb][kb + tig];
                ah[am][1] = Ah[rb + 8][kb + tig];
                ah[am][2] = Ah[rb][kb + 4 + tig];
                ah[am][3] = Ah[rb + 8][kb + 4 + tig];
                al[am][0] = Al[rb][kb + tig];
                al[am][1] = Al[rb + 8][kb + tig];
                al[am][2] = Al[rb][kb + 4 + tig];
                al[am][3] = Al[rb + 8][kb + 4 + tig];
            }
#pragma unroll
            for (int an = 0; an < 8; an++) {
                int nc = warp_n * 64 + an * 8 + gi;
                uint32_t bh[2], bl[2];
                bh[0] = Bh[nc][kb + tig];
                bh[1] = Bh[nc][kb + 4 + tig];
                bl[0] = Bl[nc][kb + tig];
                bl[1] = Bl[nc][kb + 4 + tig];
#pragma unroll
                for (int am = 0; am < 2; am++) {
                    mma_bf16(c[am][an], ah[am], bh);
                    mma_bf16(c[am][an], al[am], bh);
                    mma_bf16(c[am][an], ah[am], bl);
                }
            }
        }
        __syncthreads();
    }
}

// ---------------- generic GEMM kernel: MODE 0 relu, 1 none, 2 blend, 3 sigmoid ----------------
template<int INACT, int MODE>
__global__ __launch_bounds__(256, 2) void gemm_bf3(
    const float* __restrict__ X,
    const float* __restrict__ W, int ldw,
    const float* __restrict__ bias,
    float* __restrict__ Out, int ldo,
    int M, int N,
    const float* __restrict__ skipPtr,
    const float* __restrict__ xold)
{
    __shared__ uint32_t Ah[128][SA];
    __shared__ uint32_t Al[128][SA];
    __shared__ uint32_t Bh[128][SA];
    __shared__ uint32_t Bl[128][SA];

    const int tid = threadIdx.x;
    const int row0 = blockIdx.x * 128;
    const int lane = tid & 31;
    const int wid = tid >> 5;
    const int warp_m = wid >> 1;
    const int warp_n = wid & 1;
    const int gi = lane >> 2;
    const int tig = lane & 3;

    float c[2][8][4];
#pragma unroll
    for (int am = 0; am < 2; am++)
#pragma unroll
        for (int an = 0; an < 8; an++)
#pragma unroll
            for (int j = 0; j < 4; j++) c[am][an][j] = 0.0f;

    gemm_core<INACT>(X, W, ldw, M, N, row0, c, Ah, Al, Bh, Bl);

    float sa = 0.f, sb = 0.f;
    if (MODE == 2) {
        float s = 1.0f / (1.0f + __expf(-*skipPtr));
        sa = s; sb = 1.0f - s;
    }
#pragma unroll
    for (int am = 0; am < 2; am++) {
#pragma unroll
        for (int an = 0; an < 8; an++) {
            int col = warp_n * 64 + an * 8 + tig * 2;
#pragma unroll
            for (int half = 0; half < 2; half++) {
                int row = row0 + warp_m * 32 + am * 16 + gi + half * 8;
                if (row >= M) continue;
#pragma unroll
                for (int j = 0; j < 2; j++) {
                    int cc = col + j;
                    if (cc >= N) continue;
                    float v = c[am][an][half * 2 + j] + bias[cc];
                    if (MODE == 0) v = fmaxf(v, 0.0f);
                    else if (MODE == 2) v = sa * v + sb * xold[(size_t)row * CDIM + cc];
                    else if (MODE == 3) v = 1.0f / (1.0f + __expf(-v));
                    Out[(size_t)row * ldo + cc] = v;
                }
            }
        }
    }
}

// ---------------- merged K/Q/V GEMM: grid (412, 3); all types, all projections ----------------
struct KQVAll {
    const float* X[3];
    const float* W[9];   // [j*3 + t]
    const float* B[9];
    float* O[9];
};
__global__ __launch_bounds__(256, 2) void gemm_kqv_all(KQVAll t)
{
    __shared__ uint32_t Ah[128][SA];
    __shared__ uint32_t Al[128][SA];
    __shared__ uint32_t Bh[128][SA];
    __shared__ uint32_t Bl[128][SA];

    const int bx = blockIdx.x;
    int ty, bl;
    if (bx < NBP)            { ty = 0; bl = bx; }
    else if (bx < NBP + NBI) { ty = 1; bl = bx - NBP; }
    else                     { ty = 2; bl = bx - NBP - NBI; }
    const int M = (ty == 0) ? NPAT : (ty == 1) ? NICD : NNDC;
    const int j = blockIdx.y;
    const float* __restrict__ X = t.X[ty];
    const float* __restrict__ W = t.W[j * 3 + ty];
    const float* __restrict__ bias = t.B[j * 3 + ty];
    float* __restrict__ Out = t.O[j * 3 + ty];
    const int row0 = bl * 128;

    const int tid = threadIdx.x;
    const int lane = tid & 31;
    const int wid = tid >> 5;
    const int warp_m = wid >> 1;
    const int warp_n = wid & 1;
    const int gi = lane >> 2;
    const int tig = lane & 3;

    float c[2][8][4];
#pragma unroll
    for (int am = 0; am < 2; am++)
#pragma unroll
        for (int an = 0; an < 8; an++)
#pragma unroll
            for (int jj = 0; jj < 4; jj++) c[am][an][jj] = 0.0f;

    gemm_core<0>(X, W, CDIM, M, CDIM, row0, c, Ah, Al, Bh, Bl);

#pragma unroll
    for (int am = 0; am < 2; am++) {
#pragma unroll
        for (int an = 0; an < 8; an++) {
            int col = warp_n * 64 + an * 8 + tig * 2;
#pragma unroll
            for (int half = 0; half < 2; half++) {
                int row = row0 + warp_m * 32 + am * 16 + gi + half * 8;
                if (row >= M) continue;
                Out[(size_t)row * CDIM + col]     = c[am][an][half * 2 + 0] + bias[col];
                Out[(size_t)row * CDIM + col + 1] = c[am][an][half * 2 + 1] + bias[col + 1];
            }
        }
    }
}

// ---------------- merged A-proj GEMM: grid (412); gelu input, skip blend ----------------
struct AprojAll {
    const float* X[3];       // g_agg + toff
    const float* W[3];
    const float* B[3];
    const float* skipP[3];
    float* XO[3];            // g_x + toff (in/out)
};
__global__ __launch_bounds__(256, 2) void gemm_aproj_all(AprojAll t)
{
    __shared__ uint32_t Ah[128][SA];
    __shared__ uint32_t Al[128][SA];
    __shared__ uint32_t Bh[128][SA];
    __shared__ uint32_t Bl[128][SA];

    const int bx = blockIdx.x;
    int ty, bl;
    if (bx < NBP)            { ty = 0; bl = bx; }
    else if (bx < NBP + NBI) { ty = 1; bl = bx - NBP; }
    else                     { ty = 2; bl = bx - NBP - NBI; }
    const int M = (ty == 0) ? NPAT : (ty == 1) ? NICD : NNDC;
    const int row0 = bl * 128;
    const float* __restrict__ X = t.X[ty];
    const float* __restrict__ W = t.W[ty];
    const float* __restrict__ bias = t.B[ty];
    float* __restrict__ Out = t.XO[ty];

    const int tid = threadIdx.x;
    const int lane = tid & 31;
    const int wid = tid >> 5;
    const int warp_m = wid >> 1;
    const int warp_n = wid & 1;
    const int gi = lane >> 2;
    const int tig = lane & 3;

    float c[2][8][4];
#pragma unroll
    for (int am = 0; am < 2; am++)
#pragma unroll
        for (int an = 0; an < 8; an++)
#pragma unroll
            for (int jj = 0; jj < 4; jj++) c[am][an][jj] = 0.0f;

    gemm_core<1>(X, W, CDIM, M, CDIM, row0, c, Ah, Al, Bh, Bl);

    float s = 1.0f / (1.0f + __expf(-*t.skipP[ty]));
    float sa = s, sb = 1.0f - s;
#pragma unroll
    for (int am = 0; am < 2; am++) {
#pragma unroll
        for (int an = 0; an < 8; an++) {
            int col = warp_n * 64 + an * 8 + tig * 2;
#pragma unroll
            for (int half = 0; half < 2; half++) {
                int row = row0 + warp_m * 32 + am * 16 + gi + half * 8;
                if (row >= M) continue;
                size_t o0 = (size_t)row * CDIM + col;
                float v0 = sa * (c[am][an][half * 2 + 0] + bias[col])     + sb * Out[o0];
                float v1 = sa * (c[am][an][half * 2 + 1] + bias[col + 1]) + sb * Out[o0 + 1];
                Out[o0]     = v0;
                Out[o0 + 1] = v1;
            }
        }
    }
}

// ---------------- merged fills ----------------
__global__ void fill_all() {
    int i = blockIdx.x * blockDim.x + threadIdx.x;
    const int n1 = NTOTAL * CDIM / 4;
    const int n2 = NSOFT * HH / 4;
    float4 z = make_float4(0.f, 0.f, 0.f, 0.f);
    if (i < n1) reinterpret_cast<float4*>(g_agg)[i] = z;
    else if (i < n1 + n2) reinterpret_cast<float4*>(g_ssum)[i - n1] = z;
}

// ---------------- merged relu(embedding gather) for icd + ndc ----------------
__global__ void embed2(const float* __restrict__ ei, const int* __restrict__ xi,
                       const float* __restrict__ en, const int* __restrict__ xn) {
    int i = blockIdx.x * blockDim.x + threadIdx.x;
    if (i < NICD * CDIM) {
        int r = i >> 7, c = i & 127;
        g_x[(size_t)(NPAT + r) * CDIM + c] = fmaxf(ei[(size_t)xi[r] * CDIM + c], 0.0f);
    } else {
        int jj = i - NICD * CDIM;
        if (jj < NNDC * CDIM) {
            int r = jj >> 7, c = jj & 127;
            g_x[(size_t)(NPAT + NICD + r) * CDIM + c] = fmaxf(en[(size_t)xn[r] * CDIM + c], 0.0f);
        }
    }
}

// ---------------- merged per-relation K/V transform (all 3 source types) ----------------
struct ReltAll {
    const float* A[4];
    const float* Mw[4];
};
__global__ __launch_bounds__(128) void relt_all(ReltAll ra)
{
    __shared__ float ks[32][128];
    __shared__ float vs[32][128];
    const int tid = threadIdx.x;
    const int bx = blockIdx.x;
    const int h = tid >> 4;
    const int e = tid & 15;

    int node0, nsrc, srcoff;
    const float *A0, *M0, *A1, *M1;
    float *kr0, *vr0, *kr1, *vr1;
    bool two;
    if (bx < RTP) {
        node0 = bx * 32; nsrc = NPAT; srcoff = 0; two = true;
        A0 = ra.A[0]; M0 = ra.Mw[0]; A1 = ra.A[2]; M1 = ra.Mw[2];
        kr0 = g_krP0; vr0 = g_vrP0; kr1 = g_krP1; vr1 = g_vrP1;
    } else if (bx < RTP + RTI) {
        node0 = (bx - RTP) * 32; nsrc = NICD; srcoff = NPAT; two = false;
        A0 = ra.A[1]; M0 = ra.Mw[1]; A1 = nullptr; M1 = nullptr;
        kr0 = g_krI; vr0 = g_vrI; kr1 = nullptr; vr1 = nullptr;
    } else {
        node0 = (bx - RTP - RTI) * 32; nsrc = NNDC; srcoff = NPAT + NICD; two = false;
        A0 = ra.A[3]; M0 = ra.Mw[3]; A1 = nullptr; M1 = nullptr;
        kr0 = g_krN; vr0 = g_vrN; kr1 = nullptr; vr1 = nullptr;
    }

    float areg0[16], mreg0[16], areg1[16], mreg1[16];
#pragma unroll
    for (int d = 0; d < 16; d++) {
        areg0[d] = A0[(h * 16 + d) * 16 + e];
        mreg0[d] = M0[(h * 16 + d) * 16 + e];
        if (two) {
            areg1[d] = A1[(h * 16 + d) * 16 + e];
            mreg1[d] = M1[(h * 16 + d) * 16 + e];
        }
    }

    const float* kbase = g_k + (size_t)srcoff * CDIM;
    const float* vbase = g_v + (size_t)srcoff * CDIM;
    for (int i = tid; i < 32 * 32; i += 128) {
        int r = i >> 5;
        int cidx = (i & 31) * 4;
        if (node0 + r < nsrc) {
            *reinterpret_cast<float4*>(&ks[r][cidx]) =
                *reinterpret_cast<const float4*>(&kbase[(size_t)(node0 + r) * CDIM + cidx]);
            *reinterpret_cast<float4*>(&vs[r][cidx]) =
                *reinterpret_cast<const float4*>(&vbase[(size_t)(node0 + r) * CDIM + cidx]);
        }
    }
    __syncthreads();

    int nmax = nsrc - node0; if (nmax > 32) nmax = 32;
    for (int n = 0; n < nmax; n++) {
        float acck0 = 0.f, accv0 = 0.f, acck1 = 0.f, accv1 = 0.f;
#pragma unroll
        for (int d4 = 0; d4 < 4; d4++) {
            float4 kq = *reinterpret_cast<const float4*>(&ks[n][h * 16 + d4 * 4]);
            float4 vq = *reinterpret_cast<const float4*>(&vs[n][h * 16 + d4 * 4]);
            float kk[4] = {kq.x, kq.y, kq.z, kq.w};
            float vv[4] = {vq.x, vq.y, vq.z, vq.w};
#pragma unroll
            for (int j = 0; j < 4; j++) {
                int d = d4 * 4 + j;
                acck0 = fmaf(kk[j], areg0[d], acck0);
                accv0 = fmaf(vv[j], mreg0[d], accv0);
                if (two) {
                    acck1 = fmaf(kk[j], areg1[d], acck1);
                    accv1 = fmaf(vv[j], mreg1[d], accv1);
                }
            }
        }
        size_t o = (size_t)(node0 + n) * CDIM + h * 16 + e;
        kr0[o] = acck0; vr0[o] = accv0;
        if (two) { kr1[o] = acck1; vr1[o] = accv1; }
    }
}

// ---------------- merged edge pass A: exp(alpha) + segment sum (grid.y = relation) ----------------
struct EdgeA {
    const int* src[4];
    const int* dst[4];
    const float* qb[4];
    const float* kr[4];
    const float* prel;   // + l*32
    float* ssum;
    int soff[4];
};
__global__ __launch_bounds__(256) void edge_alpha_all(EdgeA a, float* __restrict__ alpha)
{
    const int r = blockIdx.y;
    int warp = (blockIdx.x * blockDim.x + threadIdx.x) >> 5;
    int lane = threadIdx.x & 31;
    if (warp >= NEDGE) return;
    int s = a.src[r][warp], d = a.dst[r][warp];
    float4 qv = *reinterpret_cast<const float4*>(&a.qb[r][(size_t)d * CDIM + lane * 4]);
    float4 kv = *reinterpret_cast<const float4*>(&a.kr[r][(size_t)s * CDIM + lane * 4]);
    float dot = qv.x * kv.x + qv.y * kv.y + qv.z * kv.z + qv.w * kv.w;
    dot += __shfl_xor_sync(0xffffffff, dot, 1);
    dot += __shfl_xor_sync(0xffffffff, dot, 2);
    int h = lane >> 2;
    float e = __expf(dot * a.prel[r * 8 + h] * 0.25f);
    if ((lane & 3) == 0) {
        alpha[((size_t)r * NEDGE + warp) * HH + h] = e;
        atomicAdd(&a.ssum[(size_t)(a.soff[r] + d) * HH + h], e);
    }
}

// ---------------- edge pass B for relations 1..3 (grid.y + 1 = relation) ----------------
struct EdgeB {
    const int* src[4];
    const int* dst[4];
    const float* vr[4];
    float* aggb[4];
    const float* ssum;
    int soff[4];
};
__global__ __launch_bounds__(256) void edge_agg_all(EdgeB a, const float* __restrict__ alpha)
{
    const int r = blockIdx.y + 1;
    int warp = (blockIdx.x * blockDim.x + threadIdx.x) >> 5;
    int lane = threadIdx.x & 31;
    if (warp >= NEDGE) return;
    int s = a.src[r][warp], d = a.dst[r][warp];
    int h = lane >> 2;
    float w = alpha[((size_t)r * NEDGE + warp) * HH + h]
            / a.ssum[(size_t)(a.soff[r] + d) * HH + h];
    float4 vv = *reinterpret_cast<const float4*>(&a.vr[r][(size_t)s * CDIM + lane * 4]);
    float* p = &a.aggb[r][(size_t)d * CDIM + lane * 4];
    float r0 = vv.x * w, r1 = vv.y * w, r2 = vv.z * w, r3 = vv.w * w;
    asm volatile("red.global.add.v4.f32 [%0], {%1,%2,%3,%4};"
                 :: "l"(p), "f"(r0), "f"(r1), "f"(r2), "f"(r3) : "memory");
}

// ---------------- edge pass B for relation 0 (pat->icd): smem-staged aggregation ----------------
// grid (32 chunks, 8 heads). 591 dst x 16 dims per head staged in smem, flushed once.
__global__ __launch_bounds__(256) void edge_agg_icd(
    const int* __restrict__ src, const int* __restrict__ dst,
    const float* __restrict__ alpha,    // relation-0 slice of g_alpha
    const float* __restrict__ ssum,     // relation-0 region (offset 0)
    const float* __restrict__ vr,       // g_vrP0
    float* __restrict__ aggb)           // g_agg + toff[icd]*CDIM
{
    __shared__ float acc[NICD * 16];
    const int h = blockIdx.y;
    for (int i = threadIdx.x; i < NICD * 16; i += 256) acc[i] = 0.0f;
    __syncthreads();

    const int chunk = (NEDGE + gridDim.x - 1) / gridDim.x;
    const int e0 = blockIdx.x * chunk;
    int e1 = e0 + chunk; if (e1 > NEDGE) e1 = NEDGE;

    const int warp = threadIdx.x >> 5;
    const int lane = threadIdx.x & 31;
    const int sub = lane >> 3;   // edge-in-group 0..3
    const int ll = lane & 7;     // 8 lanes per edge, 2 floats each

    for (int e = e0 + warp * 4 + sub; e < e1; e += 32) {
        int s = src[e], d = dst[e];
        float w = alpha[(size_t)e * HH + h] / ssum[(size_t)d * HH + h];
        float2 vv = *reinterpret_cast<const float2*>(&vr[(size_t)s * CDIM + h * 16 + ll * 2]);
        atomicAdd(&acc[d * 16 + ll * 2 + 0], vv.x * w);
        atomicAdd(&acc[d * 16 + ll * 2 + 1], vv.y * w);
    }
    __syncthreads();

    for (int i = threadIdx.x; i < NICD * 4; i += 256) {
        int d = i >> 2, q = (i & 3) * 4;
        float4 v = *reinterpret_cast<float4*>(&acc[d * 16 + q]);
        float* pdst = &aggb[(size_t)d * CDIM + h * 16 + q];
        asm volatile("red.global.add.v4.f32 [%0], {%1,%2,%3,%4};"
                     :: "l"(pdst), "f"(v.x), "f"(v.y), "f"(v.z), "f"(v.w) : "memory");
    }
}

// ---------------- host ----------------
extern "C" void kernel_launch(void* const* d_in, const int* in_sizes, int n_in,
                              void* d_out, int out_size)
{
    const float* x_patient = (const float*)d_in[0];
    const float* w_in      = (const float*)d_in[1];
    const float* b_in      = (const float*)d_in[2];
    const float* emb_icd   = (const float*)d_in[3];
    const float* emb_ndc   = (const float*)d_in[4];
    const float* kw = (const float*)d_in[5];
    const float* kb = (const float*)d_in[6];
    const float* qw = (const float*)d_in[7];
    const float* qb = (const float*)d_in[8];
    const float* vw = (const float*)d_in[9];
    const float* vb = (const float*)d_in[10];
    const float* aw = (const float*)d_in[11];
    const float* ab = (const float*)d_in[12];
    const float* skip  = (const float*)d_in[13];
    const float* a_rel = (const float*)d_in[14];
    const float* m_rel = (const float*)d_in[15];
    const float* p_rel = (const float*)d_in[16];
    const float* w_out = (const float*)d_in[17];
    const float* b_out = (const float*)d_in[18];
    const int* x_icd = (const int*)d_in[19];
    const int* x_ndc = (const int*)d_in[20];
    const int* esrc[4] = {(const int*)d_in[21], (const int*)d_in[23],
                          (const int*)d_in[25], (const int*)d_in[27]};
    const int* edst[4] = {(const int*)d_in[22], (const int*)d_in[24],
                          (const int*)d_in[26], (const int*)d_in[28]};
    float* out = (float*)d_out;

    void* p;
    cudaGetSymbolAddress(&p, g_x);     float* px    = (float*)p;
    cudaGetSymbolAddress(&p, g_k);     float* pk    = (float*)p;
    cudaGetSymbolAddress(&p, g_q);     float* pq    = (float*)p;
    cudaGetSymbolAddress(&p, g_v);     float* pv    = (float*)p;
    cudaGetSymbolAddress(&p, g_agg);   float* pagg  = (float*)p;
    cudaGetSymbolAddress(&p, g_krP0);  float* pkrP0 = (float*)p;
    cudaGetSymbolAddress(&p, g_vrP0);  float* pvrP0 = (float*)p;
    cudaGetSymbolAddress(&p, g_krP1);  float* pkrP1 = (float*)p;
    cudaGetSymbolAddress(&p, g_vrP1);  float* pvrP1 = (float*)p;
    cudaGetSymbolAddress(&p, g_krI);   float* pkrI  = (float*)p;
    cudaGetSymbolAddress(&p, g_vrI);   float* pvrI  = (float*)p;
    cudaGetSymbolAddress(&p, g_krN);   float* pkrN  = (float*)p;
    cudaGetSymbolAddress(&p, g_vrN);   float* pvrN  = (float*)p;
    cudaGetSymbolAddress(&p, g_alpha); float* palpha = (float*)p;
    cudaGetSymbolAddress(&p, g_ssum);  float* pssum = (float*)p;

    const int sizes[3] = {NPAT, NICD, NNDC};
    const int toff[3]  = {0, NPAT, NPAT + NICD};
    const int soff[4] = {0, NICD, NICD + NPAT, NICD + NPAT + NNDC};
    const int dt[4] = {1, 0, 2, 0};

    const int EW_GRID = (NEDGE * 32 + 255) / 256;
    const int FILL_N = NTOTAL * CDIM / 4 + NSOFT * HH / 4;

    // 1: input projection (patients)
    gemm_bf3<0, 0><<<NBP, 256>>>(
        x_patient, w_in, CDIM, b_in, px, CDIM, NPAT, CDIM, nullptr, nullptr);
    // 2: embeddings (icd + ndc merged)
    embed2<<<((NICD + NNDC) * CDIM + 255) / 256, 256>>>(emb_icd, x_icd, emb_ndc, x_ndc);
    // 3: fills for layer 0
    fill_all<<<(FILL_N + 255) / 256, 256>>>();

    for (int l = 0; l < 2; l++) {
        if (l > 0) fill_all<<<(FILL_N + 255) / 256, 256>>>();

        // 4 (layer 0): merged K/Q/V GEMM — profiled slot
        {
            KQVAll t;
            const float* ws[3] = {kw, qw, vw};
            const float* bs[3] = {kb, qb, vb};
            float* os[3] = {pk, pq, pv};
            for (int ty = 0; ty < 3; ty++) {
                t.X[ty] = px + (size_t)toff[ty] * CDIM;
                for (int j = 0; j < 3; j++) {
                    t.W[j * 3 + ty] = ws[j] + (size_t)(l * 3 + ty) * CDIM * CDIM;
                    t.B[j * 3 + ty] = bs[j] + (size_t)(l * 3 + ty) * CDIM;
                    t.O[j * 3 + ty] = os[j] + (size_t)toff[ty] * CDIM;
                }
            }
            dim3 grid(NBALL, 3);
            gemm_kqv_all<<<grid, 256>>>(t);
        }

        // merged relation K/V transforms
        {
            ReltAll ra;
            for (int r = 0; r < 4; r++) {
                ra.A[r]  = a_rel + (size_t)(l * 4 + r) * HH * DD * DD;
                ra.Mw[r] = m_rel + (size_t)(l * 4 + r) * HH * DD * DD;
            }
            relt_all<<<RTALL, 128>>>(ra);
        }

        // edge pass A (all 4 relations)
        {
            EdgeA ea;
            const float* krs[4] = {pkrP0, pkrI, pkrP1, pkrN};
            for (int r = 0; r < 4; r++) {
                ea.src[r] = esrc[r]; ea.dst[r] = edst[r];
                ea.qb[r] = pq + (size_t)toff[dt[r]] * CDIM;
                ea.kr[r] = krs[r];
                ea.soff[r] = soff[r];
            }
            ea.prel = p_rel + l * 32;
            ea.ssum = pssum;
            dim3 eg(EW_GRID, 4);
            edge_alpha_all<<<eg, 256>>>(ea, palpha);
        }

        // edge pass B: staged for relation 0, direct for 1..3
        {
            dim3 sg(32, 8);
            edge_agg_icd<<<sg, 256>>>(esrc[0], edst[0], palpha, pssum, pvrP0,
                                      pagg + (size_t)toff[1] * CDIM);
            EdgeB eb;
            const float* vrs[4] = {pvrP0, pvrI, pvrP1, pvrN};
            for (int r = 0; r < 4; r++) {
                eb.src[r] = esrc[r]; eb.dst[r] = edst[r];
                eb.vr[r] = vrs[r];
                eb.aggb[r] = pagg + (size_t)toff[dt[r]] * CDIM;
                eb.soff[r] = soff[r];
            }
            eb.ssum = pssum;
            dim3 eg(EW_GRID, 3);
            edge_agg_all<<<eg, 256>>>(eb, palpha);
        }

        // merged A-proj GEMM (gelu + skip blend)
        {
            AprojAll t;
            for (int ty = 0; ty < 3; ty++) {
                t.X[ty] = pagg + (size_t)toff[ty] * CDIM;
                t.W[ty] = aw + (size_t)(l * 3 + ty) * CDIM * CDIM;
                t.B[ty] = ab + (size_t)(l * 3 + ty) * CDIM;
                t.skipP[ty] = skip + (l * 3 + ty);
                t.XO[ty] = px + (size_t)toff[ty] * CDIM;
            }
            gemm_aproj_all<<<NBALL, 256>>>(t);
        }
    }

    // output projection + sigmoid
    gemm_bf3<0, 3><<<NBP, 256>>>(
        px, w_out, OUTD, b_out, out, OUTD, NPAT, OUTD, nullptr, nullptr);
}

// round 7
// speedup vs baseline: 1.4508x; 1.4508x over previous
#include <cuda_runtime.h>
#include <math.h>
#include <stdint.h>

#define NPAT 50000
#define NICD 591
#define NNDC 2042
#define NTOTAL 52633
#define NSOFT 102633
#define CDIM 128
#define HH 8
#define DD 16
#define NEDGE 250000
#define OUTD 90

#define NBP 391
#define NBI 5
#define NBN 16
#define NBALL (NBP + NBI + NBN)

#define RTP 1563
#define RTI 19
#define RTN 64
#define RTALL (RTP + RTI + RTN)

// ---------------- scratch ----------------
__device__ float g_x[NTOTAL * CDIM];
__device__ float g_k[NTOTAL * CDIM];
__device__ float g_q[NTOTAL * CDIM];
__device__ float g_v[NTOTAL * CDIM];
__device__ float g_agg[NTOTAL * CDIM];
__device__ float g_krP0[NPAT * CDIM];
__device__ float g_vrP0[NPAT * CDIM];
__device__ float g_krP1[NPAT * CDIM];
__device__ float g_vrP1[NPAT * CDIM];
__device__ float g_krI[NICD * CDIM];
__device__ float g_vrI[NICD * CDIM];
__device__ float g_krN[NNDC * CDIM];
__device__ float g_vrN[NNDC * CDIM];
__device__ float g_alpha[4 * NEDGE * HH];
__device__ float g_ssum[NSOFT * HH];

__device__ __forceinline__ float geluf(float x) {
    float t = tanhf(0.7978845608028654f * (x + 0.044715f * x * x * x));
    return 0.5f * x * (1.0f + t);
}

__device__ __forceinline__ void split_pair(float v0, float v1, uint32_t& h, uint32_t& l) {
    uint32_t hh;
    asm("cvt.rn.bf16x2.f32 %0, %1, %2;" : "=r"(hh) : "f"(v1), "f"(v0));
    float h0 = __uint_as_float(hh << 16);
    float h1 = __uint_as_float(hh & 0xffff0000u);
    float l0 = v0 - h0;
    float l1 = v1 - h1;
    uint32_t ll;
    asm("cvt.rn.bf16x2.f32 %0, %1, %2;" : "=r"(ll) : "f"(l1), "f"(l0));
    h = hh; l = ll;
}

__device__ __forceinline__ void mma_bf16(float* c, const uint32_t* a, const uint32_t* b) {
    asm volatile("mma.sync.aligned.m16n8k16.row.col.f32.bf16.bf16.f32 "
                 "{%0,%1,%2,%3}, {%4,%5,%6,%7}, {%8,%9}, {%0,%1,%2,%3};"
                 : "+f"(c[0]), "+f"(c[1]), "+f"(c[2]), "+f"(c[3])
                 : "r"(a[0]), "r"(a[1]), "r"(a[2]), "r"(a[3]),
                   "r"(b[0]), "r"(b[1]));
}

#define SA 20

// ---------------- GEMM core: 128(M) x 64(N) tile, 8 warps, warp tile 32x32 ----------------
// 4 blocks/SM (<=64 regs) for 50% occupancy — profile showed latency-bound at 25%.
template<int INACT>
__device__ __forceinline__ void gemm_core64(
    const float* __restrict__ X,
    const float* __restrict__ W, int ldw,
    int M, int N, int row0, int ncol0,
    float c[2][4][4],
    uint32_t (*Ah)[SA], uint32_t (*Al)[SA],
    uint32_t (*Bh)[SA], uint32_t (*Bl)[SA])
{
    const int tid = threadIdx.x;
    const int lane = tid & 31;
    const int wid = tid >> 5;
    const int warp_m = wid >> 1;   // 0..3 -> 32 rows
    const int warp_n = wid & 1;    // 0..1 -> 32 cols
    const int gi = lane >> 2;
    const int tig = lane & 3;

    const int ar = tid >> 1;
    const int akh = tid & 1;
    const bool arow_ok = (row0 + ar) < M;
    const float* xrow = X + (size_t)(row0 + ar) * CDIM;
    const int bkp = tid >> 4;      // 0..15 k-pair
    const int bc0 = tid & 15;      // col base

    for (int kc = 0; kc < CDIM; kc += 32) {
        // stage A [128 x 32]
#pragma unroll
        for (int i = 0; i < 4; i++) {
            float4 xv = make_float4(0.f, 0.f, 0.f, 0.f);
            if (arow_ok) xv = *reinterpret_cast<const float4*>(xrow + kc + akh * 16 + i * 4);
            if (INACT == 1) {
                xv.x = geluf(xv.x); xv.y = geluf(xv.y);
                xv.z = geluf(xv.z); xv.w = geluf(xv.w);
            }
            uint32_t h0, l0, h1, l1;
            split_pair(xv.x, xv.y, h0, l0);
            split_pair(xv.z, xv.w, h1, l1);
            int kp = akh * 8 + i * 2;
            Ah[ar][kp] = h0;     Al[ar][kp] = l0;
            Ah[ar][kp + 1] = h1; Al[ar][kp + 1] = l1;
        }
        // stage B [32 x 64]
        {
            const float* w0 = W + (size_t)(kc + 2 * bkp) * ldw;
            const float* w1 = w0 + ldw;
#pragma unroll
            for (int i = 0; i < 4; i++) {
                int nl = bc0 + 16 * i;
                int n = ncol0 + nl;
                float v0 = (n < N) ? w0[n] : 0.0f;
                float v1 = (n < N) ? w1[n] : 0.0f;
                uint32_t h, l;
                split_pair(v0, v1, h, l);
                Bh[nl][bkp] = h;
                Bl[nl][bkp] = l;
            }
        }
        __syncthreads();

#pragma unroll
        for (int ks = 0; ks < 2; ks++) {
            const int kb = ks * 8;
            uint32_t ah[2][4], al[2][4];
#pragma unroll
            for (int am = 0; am < 2; am++) {
                int rb = warp_m * 32 + am * 16 + gi;
                ah[am][0] = Ah[rb][kb + tig];
                ah[am][1] = Ah[rb + 8][kb + tig];
                ah[am][2] = Ah[rb][kb + 4 + tig];
                ah[am][3] = Ah[rb + 8][kb + 4 + tig];
                al[am][0] = Al[rb][kb + tig];
                al[am][1] = Al[rb + 8][kb + tig];
                al[am][2] = Al[rb][kb + 4 + tig];
                al[am][3] = Al[rb + 8][kb + 4 + tig];
            }
#pragma unroll
            for (int an = 0; an < 4; an++) {
                int nc = warp_n * 32 + an * 8 + gi;
                uint32_t bh[2], bl[2];
                bh[0] = Bh[nc][kb + tig];
                bh[1] = Bh[nc][kb + 4 + tig];
                bl[0] = Bl[nc][kb + tig];
                bl[1] = Bl[nc][kb + 4 + tig];
#pragma unroll
                for (int am = 0; am < 2; am++) {
                    mma_bf16(c[am][an], ah[am], bh);
                    mma_bf16(c[am][an], al[am], bh);
                    mma_bf16(c[am][an], ah[am], bl);
                }
            }
        }
        __syncthreads();
    }
}

#define GEMM_SMEM \
    __shared__ uint32_t Ah[128][SA]; \
    __shared__ uint32_t Al[128][SA]; \
    __shared__ uint32_t Bh[64][SA];  \
    __shared__ uint32_t Bl[64][SA];

#define ACC_INIT \
    float c[2][4][4]; \
    _Pragma("unroll") for (int am = 0; am < 2; am++) \
    _Pragma("unroll") for (int an = 0; an < 4; an++) \
    _Pragma("unroll") for (int j = 0; j < 4; j++) c[am][an][j] = 0.0f;

// ---------------- generic GEMM: grid (mblocks, 2=N-half) ----------------
// MODE: 0 relu, 1 none, 2 blend, 3 sigmoid
template<int INACT, int MODE>
__global__ __launch_bounds__(256, 4) void gemm_bf3(
    const float* __restrict__ X,
    const float* __restrict__ W, int ldw,
    const float* __restrict__ bias,
    float* __restrict__ Out, int ldo,
    int M, int N,
    const float* __restrict__ skipPtr,
    const float* __restrict__ xold)
{
    GEMM_SMEM
    const int tid = threadIdx.x;
    const int row0 = blockIdx.x * 128;
    const int ncol0 = blockIdx.y * 64;
    const int lane = tid & 31;
    const int wid = tid >> 5;
    const int warp_m = wid >> 1;
    const int warp_n = wid & 1;
    const int gi = lane >> 2;
    const int tig = lane & 3;

    ACC_INIT
    gemm_core64<INACT>(X, W, ldw, M, N, row0, ncol0, c, Ah, Al, Bh, Bl);

    float sa = 0.f, sb = 0.f;
    if (MODE == 2) {
        float s = 1.0f / (1.0f + __expf(-*skipPtr));
        sa = s; sb = 1.0f - s;
    }
#pragma unroll
    for (int am = 0; am < 2; am++) {
#pragma unroll
        for (int an = 0; an < 4; an++) {
            int col = ncol0 + warp_n * 32 + an * 8 + tig * 2;
#pragma unroll
            for (int half = 0; half < 2; half++) {
                int row = row0 + warp_m * 32 + am * 16 + gi + half * 8;
                if (row >= M) continue;
#pragma unroll
                for (int j = 0; j < 2; j++) {
                    int cc = col + j;
                    if (cc >= N) continue;
                    float v = c[am][an][half * 2 + j] + bias[cc];
                    if (MODE == 0) v = fmaxf(v, 0.0f);
                    else if (MODE == 2) v = sa * v + sb * xold[(size_t)row * CDIM + cc];
                    else if (MODE == 3) v = 1.0f / (1.0f + __expf(-v));
                    Out[(size_t)row * ldo + cc] = v;
                }
            }
        }
    }
}

// ---------------- merged K/Q/V GEMM: grid (NBALL, 3, 2) ----------------
struct KQVAll {
    const float* X[3];
    const float* W[9];
    const float* B[9];
    float* O[9];
};
__global__ __launch_bounds__(256, 4) void gemm_kqv_all(KQVAll t)
{
    GEMM_SMEM
    const int bx = blockIdx.x;
    int ty, bl;
    if (bx < NBP)            { ty = 0; bl = bx; }
    else if (bx < NBP + NBI) { ty = 1; bl = bx - NBP; }
    else                     { ty = 2; bl = bx - NBP - NBI; }
    const int M = (ty == 0) ? NPAT : (ty == 1) ? NICD : NNDC;
    const int j = blockIdx.y;
    const int ncol0 = blockIdx.z * 64;
    const float* __restrict__ X = t.X[ty];
    const float* __restrict__ W = t.W[j * 3 + ty];
    const float* __restrict__ bias = t.B[j * 3 + ty];
    float* __restrict__ Out = t.O[j * 3 + ty];
    const int row0 = bl * 128;

    const int tid = threadIdx.x;
    const int lane = tid & 31;
    const int wid = tid >> 5;
    const int warp_m = wid >> 1;
    const int warp_n = wid & 1;
    const int gi = lane >> 2;
    const int tig = lane & 3;

    ACC_INIT
    gemm_core64<0>(X, W, CDIM, M, CDIM, row0, ncol0, c, Ah, Al, Bh, Bl);

#pragma unroll
    for (int am = 0; am < 2; am++) {
#pragma unroll
        for (int an = 0; an < 4; an++) {
            int col = ncol0 + warp_n * 32 + an * 8 + tig * 2;
#pragma unroll
            for (int half = 0; half < 2; half++) {
                int row = row0 + warp_m * 32 + am * 16 + gi + half * 8;
                if (row >= M) continue;
                Out[(size_t)row * CDIM + col]     = c[am][an][half * 2 + 0] + bias[col];
                Out[(size_t)row * CDIM + col + 1] = c[am][an][half * 2 + 1] + bias[col + 1];
            }
        }
    }
}

// ---------------- merged A-proj GEMM: grid (NBALL, 2) ----------------
struct AprojAll {
    const float* X[3];
    const float* W[3];
    const float* B[3];
    const float* skipP[3];
    float* XO[3];
};
__global__ __launch_bounds__(256, 4) void gemm_aproj_all(AprojAll t)
{
    GEMM_SMEM
    const int bx = blockIdx.x;
    int ty, bl;
    if (bx < NBP)            { ty = 0; bl = bx; }
    else if (bx < NBP + NBI) { ty = 1; bl = bx - NBP; }
    else                     { ty = 2; bl = bx - NBP - NBI; }
    const int M = (ty == 0) ? NPAT : (ty == 1) ? NICD : NNDC;
    const int row0 = bl * 128;
    const int ncol0 = blockIdx.y * 64;
    const float* __restrict__ X = t.X[ty];
    const float* __restrict__ W = t.W[ty];
    const float* __restrict__ bias = t.B[ty];
    float* __restrict__ Out = t.XO[ty];

    const int tid = threadIdx.x;
    const int lane = tid & 31;
    const int wid = tid >> 5;
    const int warp_m = wid >> 1;
    const int warp_n = wid & 1;
    const int gi = lane >> 2;
    const int tig = lane & 3;

    ACC_INIT
    gemm_core64<1>(X, W, CDIM, M, CDIM, row0, ncol0, c, Ah, Al, Bh, Bl);

    float s = 1.0f / (1.0f + __expf(-*t.skipP[ty]));
    float sa = s, sb = 1.0f - s;
#pragma unroll
    for (int am = 0; am < 2; am++) {
#pragma unroll
        for (int an = 0; an < 4; an++) {
            int col = ncol0 + warp_n * 32 + an * 8 + tig * 2;
#pragma unroll
            for (int half = 0; half < 2; half++) {
                int row = row0 + warp_m * 32 + am * 16 + gi + half * 8;
                if (row >= M) continue;
                size_t o0 = (size_t)row * CDIM + col;
                float v0 = sa * (c[am][an][half * 2 + 0] + bias[col])     + sb * Out[o0];
                float v1 = sa * (c[am][an][half * 2 + 1] + bias[col + 1]) + sb * Out[o0 + 1];
                Out[o0]     = v0;
                Out[o0 + 1] = v1;
            }
        }
    }
}

// ---------------- merged fills ----------------
__global__ void fill_all() {
    int i = blockIdx.x * blockDim.x + threadIdx.x;
    const int n1 = NTOTAL * CDIM / 4;
    const int n2 = NSOFT * HH / 4;
    float4 z = make_float4(0.f, 0.f, 0.f, 0.f);
    if (i < n1) reinterpret_cast<float4*>(g_agg)[i] = z;
    else if (i < n1 + n2) reinterpret_cast<float4*>(g_ssum)[i - n1] = z;
}

// ---------------- merged relu(embedding gather) ----------------
__global__ void embed2(const float* __restrict__ ei, const int* __restrict__ xi,
                       const float* __restrict__ en, const int* __restrict__ xn) {
    int i = blockIdx.x * blockDim.x + threadIdx.x;
    if (i < NICD * CDIM) {
        int r = i >> 7, c = i & 127;
        g_x[(size_t)(NPAT + r) * CDIM + c] = fmaxf(ei[(size_t)xi[r] * CDIM + c], 0.0f);
    } else {
        int jj = i - NICD * CDIM;
        if (jj < NNDC * CDIM) {
            int r = jj >> 7, c = jj & 127;
            g_x[(size_t)(NPAT + NICD + r) * CDIM + c] = fmaxf(en[(size_t)xn[r] * CDIM + c], 0.0f);
        }
    }
}

// ---------------- merged per-relation K/V transform ----------------
struct ReltAll {
    const float* A[4];
    const float* Mw[4];
};
__global__ __launch_bounds__(128) void relt_all(ReltAll ra)
{
    __shared__ float ks[32][128];
    __shared__ float vs[32][128];
    const int tid = threadIdx.x;
    const int bx = blockIdx.x;
    const int h = tid >> 4;
    const int e = tid & 15;

    int node0, nsrc, srcoff;
    const float *A0, *M0, *A1, *M1;
    float *kr0, *vr0, *kr1, *vr1;
    bool two;
    if (bx < RTP) {
        node0 = bx * 32; nsrc = NPAT; srcoff = 0; two = true;
        A0 = ra.A[0]; M0 = ra.Mw[0]; A1 = ra.A[2]; M1 = ra.Mw[2];
        kr0 = g_krP0; vr0 = g_vrP0; kr1 = g_krP1; vr1 = g_vrP1;
    } else if (bx < RTP + RTI) {
        node0 = (bx - RTP) * 32; nsrc = NICD; srcoff = NPAT; two = false;
        A0 = ra.A[1]; M0 = ra.Mw[1]; A1 = nullptr; M1 = nullptr;
        kr0 = g_krI; vr0 = g_vrI; kr1 = nullptr; vr1 = nullptr;
    } else {
        node0 = (bx - RTP - RTI) * 32; nsrc = NNDC; srcoff = NPAT + NICD; two = false;
        A0 = ra.A[3]; M0 = ra.Mw[3]; A1 = nullptr; M1 = nullptr;
        kr0 = g_krN; vr0 = g_vrN; kr1 = nullptr; vr1 = nullptr;
    }

    float areg0[16], mreg0[16], areg1[16], mreg1[16];
#pragma unroll
    for (int d = 0; d < 16; d++) {
        areg0[d] = A0[(h * 16 + d) * 16 + e];
        mreg0[d] = M0[(h * 16 + d) * 16 + e];
        if (two) {
            areg1[d] = A1[(h * 16 + d) * 16 + e];
            mreg1[d] = M1[(h * 16 + d) * 16 + e];
        }
    }

    const float* kbase = g_k + (size_t)srcoff * CDIM;
    const float* vbase = g_v + (size_t)srcoff * CDIM;
    for (int i = tid; i < 32 * 32; i += 128) {
        int r = i >> 5;
        int cidx = (i & 31) * 4;
        if (node0 + r < nsrc) {
            *reinterpret_cast<float4*>(&ks[r][cidx]) =
                *reinterpret_cast<const float4*>(&kbase[(size_t)(node0 + r) * CDIM + cidx]);
            *reinterpret_cast<float4*>(&vs[r][cidx]) =
                *reinterpret_cast<const float4*>(&vbase[(size_t)(node0 + r) * CDIM + cidx]);
        }
    }
    __syncthreads();

    int nmax = nsrc - node0; if (nmax > 32) nmax = 32;
    for (int n = 0; n < nmax; n++) {
        float acck0 = 0.f, accv0 = 0.f, acck1 = 0.f, accv1 = 0.f;
#pragma unroll
        for (int d4 = 0; d4 < 4; d4++) {
            float4 kq = *reinterpret_cast<const float4*>(&ks[n][h * 16 + d4 * 4]);
            float4 vq = *reinterpret_cast<const float4*>(&vs[n][h * 16 + d4 * 4]);
            float kk[4] = {kq.x, kq.y, kq.z, kq.w};
            float vv[4] = {vq.x, vq.y, vq.z, vq.w};
#pragma unroll
            for (int j = 0; j < 4; j++) {
                int d = d4 * 4 + j;
                acck0 = fmaf(kk[j], areg0[d], acck0);
                accv0 = fmaf(vv[j], mreg0[d], accv0);
                if (two) {
                    acck1 = fmaf(kk[j], areg1[d], acck1);
                    accv1 = fmaf(vv[j], mreg1[d], accv1);
                }
            }
        }
        size_t o = (size_t)(node0 + n) * CDIM + h * 16 + e;
        kr0[o] = acck0; vr0[o] = accv0;
        if (two) { kr1[o] = acck1; vr1[o] = accv1; }
    }
}

// ---------------- edge pass A: exp(alpha) + segment sum (grid.y = relation) ----------------
struct EdgeA {
    const int* src[4];
    const int* dst[4];
    const float* qb[4];
    const float* kr[4];
    const float* prel;
    float* ssum;
    int soff[4];
};
__global__ __launch_bounds__(256) void edge_alpha_all(EdgeA a, float* __restrict__ alpha)
{
    const int r = blockIdx.y;
    int warp = (blockIdx.x * blockDim.x + threadIdx.x) >> 5;
    int lane = threadIdx.x & 31;
    if (warp >= NEDGE) return;
    int s = a.src[r][warp], d = a.dst[r][warp];
    float4 qv = *reinterpret_cast<const float4*>(&a.qb[r][(size_t)d * CDIM + lane * 4]);
    float4 kv = *reinterpret_cast<const float4*>(&a.kr[r][(size_t)s * CDIM + lane * 4]);
    float dot = qv.x * kv.x + qv.y * kv.y + qv.z * kv.z + qv.w * kv.w;
    dot += __shfl_xor_sync(0xffffffff, dot, 1);
    dot += __shfl_xor_sync(0xffffffff, dot, 2);
    int h = lane >> 2;
    float e = __expf(dot * a.prel[r * 8 + h] * 0.25f);
    if ((lane & 3) == 0) {
        alpha[((size_t)r * NEDGE + warp) * HH + h] = e;
        atomicAdd(&a.ssum[(size_t)(a.soff[r] + d) * HH + h], e);
    }
}

// ---------------- edge pass B: normalize + scatter-add (grid.y = relation, all 4) ----------------
struct EdgeB {
    const int* src[4];
    const int* dst[4];
    const float* vr[4];
    float* aggb[4];
    const float* ssum;
    int soff[4];
};
__global__ __launch_bounds__(256) void edge_agg_all(EdgeB a, const float* __restrict__ alpha)
{
    const int r = blockIdx.y;
    int warp = (blockIdx.x * blockDim.x + threadIdx.x) >> 5;
    int lane = threadIdx.x & 31;
    if (warp >= NEDGE) return;
    int s = a.src[r][warp], d = a.dst[r][warp];
    int h = lane >> 2;
    float w = alpha[((size_t)r * NEDGE + warp) * HH + h]
            / a.ssum[(size_t)(a.soff[r] + d) * HH + h];
    float4 vv = *reinterpret_cast<const float4*>(&a.vr[r][(size_t)s * CDIM + lane * 4]);
    float* p = &a.aggb[r][(size_t)d * CDIM + lane * 4];
    float r0 = vv.x * w, r1 = vv.y * w, r2 = vv.z * w, r3 = vv.w * w;
    asm volatile("red.global.add.v4.f32 [%0], {%1,%2,%3,%4};"
                 :: "l"(p), "f"(r0), "f"(r1), "f"(r2), "f"(r3) : "memory");
}

// ---------------- host ----------------
extern "C" void kernel_launch(void* const* d_in, const int* in_sizes, int n_in,
                              void* d_out, int out_size)
{
    const float* x_patient = (const float*)d_in[0];
    const float* w_in      = (const float*)d_in[1];
    const float* b_in      = (const float*)d_in[2];
    const float* emb_icd   = (const float*)d_in[3];
    const float* emb_ndc   = (const float*)d_in[4];
    const float* kw = (const float*)d_in[5];
    const float* kb = (const float*)d_in[6];
    const float* qw = (const float*)d_in[7];
    const float* qb = (const float*)d_in[8];
    const float* vw = (const float*)d_in[9];
    const float* vb = (const float*)d_in[10];
    const float* aw = (const float*)d_in[11];
    const float* ab = (const float*)d_in[12];
    const float* skip  = (const float*)d_in[13];
    const float* a_rel = (const float*)d_in[14];
    const float* m_rel = (const float*)d_in[15];
    const float* p_rel = (const float*)d_in[16];
    const float* w_out = (const float*)d_in[17];
    const float* b_out = (const float*)d_in[18];
    const int* x_icd = (const int*)d_in[19];
    const int* x_ndc = (const int*)d_in[20];
    const int* esrc[4] = {(const int*)d_in[21], (const int*)d_in[23],
                          (const int*)d_in[25], (const int*)d_in[27]};
    const int* edst[4] = {(const int*)d_in[22], (const int*)d_in[24],
                          (const int*)d_in[26], (const int*)d_in[28]};
    float* out = (float*)d_out;

    void* p;
    cudaGetSymbolAddress(&p, g_x);     float* px    = (float*)p;
    cudaGetSymbolAddress(&p, g_k);     float* pk    = (float*)p;
    cudaGetSymbolAddress(&p, g_q);     float* pq    = (float*)p;
    cudaGetSymbolAddress(&p, g_v);     float* pv    = (float*)p;
    cudaGetSymbolAddress(&p, g_agg);   float* pagg  = (float*)p;
    cudaGetSymbolAddress(&p, g_krP0);  float* pkrP0 = (float*)p;
    cudaGetSymbolAddress(&p, g_vrP0);  float* pvrP0 = (float*)p;
    cudaGetSymbolAddress(&p, g_krP1);  float* pkrP1 = (float*)p;
    cudaGetSymbolAddress(&p, g_vrP1);  float* pvrP1 = (float*)p;
    cudaGetSymbolAddress(&p, g_krI);   float* pkrI  = (float*)p;
    cudaGetSymbolAddress(&p, g_vrI);   float* pvrI  = (float*)p;
    cudaGetSymbolAddress(&p, g_krN);   float* pkrN  = (float*)p;
    cudaGetSymbolAddress(&p, g_vrN);   float* pvrN  = (float*)p;
    cudaGetSymbolAddress(&p, g_alpha); float* palpha = (float*)p;
    cudaGetSymbolAddress(&p, g_ssum);  float* pssum = (float*)p;

    const int toff[3]  = {0, NPAT, NPAT + NICD};
    const int soff[4] = {0, NICD, NICD + NPAT, NICD + NPAT + NNDC};
    const int dt[4] = {1, 0, 2, 0};

    const int EW_GRID = (NEDGE * 32 + 255) / 256;
    const int FILL_N = NTOTAL * CDIM / 4 + NSOFT * HH / 4;

    // 1: input projection (patients)
    {
        dim3 g(NBP, 2);
        gemm_bf3<0, 0><<<g, 256>>>(
            x_patient, w_in, CDIM, b_in, px, CDIM, NPAT, CDIM, nullptr, nullptr);
    }
    // 2: embeddings
    embed2<<<((NICD + NNDC) * CDIM + 255) / 256, 256>>>(emb_icd, x_icd, emb_ndc, x_ndc);
    // 3: fills for layer 0
    fill_all<<<(FILL_N + 255) / 256, 256>>>();

    for (int l = 0; l < 2; l++) {
        if (l > 0) fill_all<<<(FILL_N + 255) / 256, 256>>>();

        // merged K/Q/V GEMM (slot 4 on layer 0 — profiled)
        {
            KQVAll t;
            const float* ws[3] = {kw, qw, vw};
            const float* bs[3] = {kb, qb, vb};
            float* os[3] = {pk, pq, pv};
            for (int ty = 0; ty < 3; ty++) {
                t.X[ty] = px + (size_t)toff[ty] * CDIM;
                for (int j = 0; j < 3; j++) {
                    t.W[j * 3 + ty] = ws[j] + (size_t)(l * 3 + ty) * CDIM * CDIM;
                    t.B[j * 3 + ty] = bs[j] + (size_t)(l * 3 + ty) * CDIM;
                    t.O[j * 3 + ty] = os[j] + (size_t)toff[ty] * CDIM;
                }
            }
            dim3 grid(NBALL, 3, 2);
            gemm_kqv_all<<<grid, 256>>>(t);
        }

        // merged relation K/V transforms
        {
            ReltAll ra;
            for (int r = 0; r < 4; r++) {
                ra.A[r]  = a_rel + (size_t)(l * 4 + r) * HH * DD * DD;
                ra.Mw[r] = m_rel + (size_t)(l * 4 + r) * HH * DD * DD;
            }
            relt_all<<<RTALL, 128>>>(ra);
        }

        // edge pass A (all 4 relations)
        {
            EdgeA ea;
            const float* krs[4] = {pkrP0, pkrI, pkrP1, pkrN};
            for (int r = 0; r < 4; r++) {
                ea.src[r] = esrc[r]; ea.dst[r] = edst[r];
                ea.qb[r] = pq + (size_t)toff[dt[r]] * CDIM;
                ea.kr[r] = krs[r];
                ea.soff[r] = soff[r];
            }
            ea.prel = p_rel + l * 32;
            ea.ssum = pssum;
            dim3 eg(EW_GRID, 4);
            edge_alpha_all<<<eg, 256>>>(ea, palpha);
        }

        // edge pass B (all 4 relations, direct red.global — R5 behavior)
        {
            EdgeB eb;
            const float* vrs[4] = {pvrP0, pvrI, pvrP1, pvrN};
            for (int r = 0; r < 4; r++) {
                eb.src[r] = esrc[r]; eb.dst[r] = edst[r];
                eb.vr[r] = vrs[r];
                eb.aggb[r] = pagg + (size_t)toff[dt[r]] * CDIM;
                eb.soff[r] = soff[r];
            }
            eb.ssum = pssum;
            dim3 eg(EW_GRID, 4);
            edge_agg_all<<<eg, 256>>>(eb, palpha);
        }

        // merged A-proj GEMM
        {
            AprojAll t;
            for (int ty = 0; ty < 3; ty++) {
                t.X[ty] = pagg + (size_t)toff[ty] * CDIM;
                t.W[ty] = aw + (size_t)(l * 3 + ty) * CDIM * CDIM;
                t.B[ty] = ab + (size_t)(l * 3 + ty) * CDIM;
                t.skipP[ty] = skip + (l * 3 + ty);
                t.XO[ty] = px + (size_t)toff[ty] * CDIM;
            }
            dim3 grid(NBALL, 2);
            gemm_aproj_all<<<grid, 256>>>(t);
        }
    }

    // output projection + sigmoid
    {
        dim3 g(NBP, 2);
        gemm_bf3<0, 3><<<g, 256>>>(
            px, w_out, OUTD, b_out, out, OUTD, NPAT, OUTD, nullptr, nullptr);
    }
}

// round 8
// speedup vs baseline: 1.7706x; 1.2204x over previous
#include <cuda_runtime.h>
#include <math.h>
#include <stdint.h>

#define NPAT 50000
#define NICD 591
#define NNDC 2042
#define NTOTAL 52633
#define NSOFT 102633
#define CDIM 128
#define HH 8
#define DD 16
#define NEDGE 250000
#define OUTD 90

#define SOFF0 0
#define SOFF1 NICD
#define SOFF2 (NICD + NPAT)
#define SOFF3 (NICD + NPAT + NNDC)

#define NBP 391
#define NBI 5
#define NBN 16
#define NBALL (NBP + NBI + NBN)

#define RTP 1563
#define RTI 19
#define RTN 64
#define RTALL (RTP + RTI + RTN)

// patient-warp blocks then icd+ndc blocks
#define EPB 6250                    /* 50000/8 patients, warp each */
#define EBLK (NICD + NNDC)          /* 2633 block-per-dst */
#define EALL (EPB + EBLK)

// ---------------- scratch ----------------
__device__ float g_x[NTOTAL * CDIM];
__device__ float g_k[NTOTAL * CDIM];
__device__ float g_q[NTOTAL * CDIM];
__device__ float g_v[NTOTAL * CDIM];
__device__ float g_agg[NTOTAL * CDIM];
__device__ float g_krP0[NPAT * CDIM];
__device__ float g_vrP0[NPAT * CDIM];
__device__ float g_krP1[NPAT * CDIM];
__device__ float g_vrP1[NPAT * CDIM];
__device__ float g_krI[NICD * CDIM];
__device__ float g_vrI[NICD * CDIM];
__device__ float g_krN[NNDC * CDIM];
__device__ float g_vrN[NNDC * CDIM];
// CSR structures (built once per call; layer-invariant)
__device__ int g_cnt[NSOFT];
__device__ int g_off[NSOFT];
__device__ int g_cur[NSOFT];
__device__ int g_csr[4 * NEDGE];

__device__ __forceinline__ float geluf(float x) {
    float t = tanhf(0.7978845608028654f * (x + 0.044715f * x * x * x));
    return 0.5f * x * (1.0f + t);
}

__device__ __forceinline__ void split_pair(float v0, float v1, uint32_t& h, uint32_t& l) {
    uint32_t hh;
    asm("cvt.rn.bf16x2.f32 %0, %1, %2;" : "=r"(hh) : "f"(v1), "f"(v0));
    float h0 = __uint_as_float(hh << 16);
    float h1 = __uint_as_float(hh & 0xffff0000u);
    float l0 = v0 - h0;
    float l1 = v1 - h1;
    uint32_t ll;
    asm("cvt.rn.bf16x2.f32 %0, %1, %2;" : "=r"(ll) : "f"(l1), "f"(l0));
    h = hh; l = ll;
}

__device__ __forceinline__ void mma_bf16(float* c, const uint32_t* a, const uint32_t* b) {
    asm volatile("mma.sync.aligned.m16n8k16.row.col.f32.bf16.bf16.f32 "
                 "{%0,%1,%2,%3}, {%4,%5,%6,%7}, {%8,%9}, {%0,%1,%2,%3};"
                 : "+f"(c[0]), "+f"(c[1]), "+f"(c[2]), "+f"(c[3])
                 : "r"(a[0]), "r"(a[1]), "r"(a[2]), "r"(a[3]),
                   "r"(b[0]), "r"(b[1]));
}

#define SA 20

// ---------------- GEMM core: 128(M) x 64(N) tile, 8 warps, warp tile 32x32 ----------------
template<int INACT>
__device__ __forceinline__ void gemm_core64(
    const float* __restrict__ X,
    const float* __restrict__ W, int ldw,
    int M, int N, int row0, int ncol0,
    float c[2][4][4],
    uint32_t (*Ah)[SA], uint32_t (*Al)[SA],
    uint32_t (*Bh)[SA], uint32_t (*Bl)[SA])
{
    const int tid = threadIdx.x;
    const int lane = tid & 31;
    const int wid = tid >> 5;
    const int warp_m = wid >> 1;
    const int warp_n = wid & 1;
    const int gi = lane >> 2;
    const int tig = lane & 3;

    const int ar = tid >> 1;
    const int akh = tid & 1;
    const bool arow_ok = (row0 + ar) < M;
    const float* xrow = X + (size_t)(row0 + ar) * CDIM;
    const int bkp = tid >> 4;
    const int bc0 = tid & 15;

    for (int kc = 0; kc < CDIM; kc += 32) {
#pragma unroll
        for (int i = 0; i < 4; i++) {
            float4 xv = make_float4(0.f, 0.f, 0.f, 0.f);
            if (arow_ok) xv = *reinterpret_cast<const float4*>(xrow + kc + akh * 16 + i * 4);
            if (INACT == 1) {
                xv.x = geluf(xv.x); xv.y = geluf(xv.y);
                xv.z = geluf(xv.z); xv.w = geluf(xv.w);
            }
            uint32_t h0, l0, h1, l1;
            split_pair(xv.x, xv.y, h0, l0);
            split_pair(xv.z, xv.w, h1, l1);
            int kp = akh * 8 + i * 2;
            Ah[ar][kp] = h0;     Al[ar][kp] = l0;
            Ah[ar][kp + 1] = h1; Al[ar][kp + 1] = l1;
        }
        {
            const float* w0 = W + (size_t)(kc + 2 * bkp) * ldw;
            const float* w1 = w0 + ldw;
#pragma unroll
            for (int i = 0; i < 4; i++) {
                int nl = bc0 + 16 * i;
                int n = ncol0 + nl;
                float v0 = (n < N) ? w0[n] : 0.0f;
                float v1 = (n < N) ? w1[n] : 0.0f;
                uint32_t h, l;
                split_pair(v0, v1, h, l);
                Bh[nl][bkp] = h;
                Bl[nl][bkp] = l;
            }
        }
        __syncthreads();

#pragma unroll
        for (int ks = 0; ks < 2; ks++) {
            const int kb = ks * 8;
            uint32_t ah[2][4], al[2][4];
#pragma unroll
            for (int am = 0; am < 2; am++) {
                int rb = warp_m * 32 + am * 16 + gi;
                ah[am][0] = Ah[rb][kb + tig];
                ah[am][1] = Ah[rb + 8][kb + tig];
                ah[am][2] = Ah[rb][kb + 4 + tig];
                ah[am][3] = Ah[rb + 8][kb + 4 + tig];
                al[am][0] = Al[rb][kb + tig];
                al[am][1] = Al[rb + 8][kb + tig];
                al[am][2] = Al[rb][kb + 4 + tig];
                al[am][3] = Al[rb + 8][kb + 4 + tig];
            }
#pragma unroll
            for (int an = 0; an < 4; an++) {
                int nc = warp_n * 32 + an * 8 + gi;
                uint32_t bh[2], bl[2];
                bh[0] = Bh[nc][kb + tig];
                bh[1] = Bh[nc][kb + 4 + tig];
                bl[0] = Bl[nc][kb + tig];
                bl[1] = Bl[nc][kb + 4 + tig];
#pragma unroll
                for (int am = 0; am < 2; am++) {
                    mma_bf16(c[am][an], ah[am], bh);
                    mma_bf16(c[am][an], al[am], bh);
                    mma_bf16(c[am][an], ah[am], bl);
                }
            }
        }
        __syncthreads();
    }
}

#define GEMM_SMEM \
    __shared__ uint32_t Ah[128][SA]; \
    __shared__ uint32_t Al[128][SA]; \
    __shared__ uint32_t Bh[64][SA];  \
    __shared__ uint32_t Bl[64][SA];

#define ACC_INIT \
    float c[2][4][4]; \
    _Pragma("unroll") for (int am = 0; am < 2; am++) \
    _Pragma("unroll") for (int an = 0; an < 4; an++) \
    _Pragma("unroll") for (int j = 0; j < 4; j++) c[am][an][j] = 0.0f;

template<int INACT, int MODE>
__global__ __launch_bounds__(256, 4) void gemm_bf3(
    const float* __restrict__ X,
    const float* __restrict__ W, int ldw,
    const float* __restrict__ bias,
    float* __restrict__ Out, int ldo,
    int M, int N,
    const float* __restrict__ skipPtr,
    const float* __restrict__ xold)
{
    GEMM_SMEM
    const int tid = threadIdx.x;
    const int row0 = blockIdx.x * 128;
    const int ncol0 = blockIdx.y * 64;
    const int lane = tid & 31;
    const int wid = tid >> 5;
    const int warp_m = wid >> 1;
    const int warp_n = wid & 1;
    const int gi = lane >> 2;
    const int tig = lane & 3;

    ACC_INIT
    gemm_core64<INACT>(X, W, ldw, M, N, row0, ncol0, c, Ah, Al, Bh, Bl);

    float sa = 0.f, sb = 0.f;
    if (MODE == 2) {
        float s = 1.0f / (1.0f + __expf(-*skipPtr));
        sa = s; sb = 1.0f - s;
    }
#pragma unroll
    for (int am = 0; am < 2; am++) {
#pragma unroll
        for (int an = 0; an < 4; an++) {
            int col = ncol0 + warp_n * 32 + an * 8 + tig * 2;
#pragma unroll
            for (int half = 0; half < 2; half++) {
                int row = row0 + warp_m * 32 + am * 16 + gi + half * 8;
                if (row >= M) continue;
#pragma unroll
                for (int j = 0; j < 2; j++) {
                    int cc = col + j;
                    if (cc >= N) continue;
                    float v = c[am][an][half * 2 + j] + bias[cc];
                    if (MODE == 0) v = fmaxf(v, 0.0f);
                    else if (MODE == 2) v = sa * v + sb * xold[(size_t)row * CDIM + cc];
                    else if (MODE == 3) v = 1.0f / (1.0f + __expf(-v));
                    Out[(size_t)row * ldo + cc] = v;
                }
            }
        }
    }
}

struct KQVAll {
    const float* X[3];
    const float* W[9];
    const float* B[9];
    float* O[9];
};
__global__ __launch_bounds__(256, 4) void gemm_kqv_all(KQVAll t)
{
    GEMM_SMEM
    const int bx = blockIdx.x;
    int ty, bl;
    if (bx < NBP)            { ty = 0; bl = bx; }
    else if (bx < NBP + NBI) { ty = 1; bl = bx - NBP; }
    else                     { ty = 2; bl = bx - NBP - NBI; }
    const int M = (ty == 0) ? NPAT : (ty == 1) ? NICD : NNDC;
    const int j = blockIdx.y;
    const int ncol0 = blockIdx.z * 64;
    const float* __restrict__ X = t.X[ty];
    const float* __restrict__ W = t.W[j * 3 + ty];
    const float* __restrict__ bias = t.B[j * 3 + ty];
    float* __restrict__ Out = t.O[j * 3 + ty];
    const int row0 = bl * 128;

    const int tid = threadIdx.x;
    const int lane = tid & 31;
    const int wid = tid >> 5;
    const int warp_m = wid >> 1;
    const int warp_n = wid & 1;
    const int gi = lane >> 2;
    const int tig = lane & 3;

    ACC_INIT
    gemm_core64<0>(X, W, CDIM, M, CDIM, row0, ncol0, c, Ah, Al, Bh, Bl);

#pragma unroll
    for (int am = 0; am < 2; am++) {
#pragma unroll
        for (int an = 0; an < 4; an++) {
            int col = ncol0 + warp_n * 32 + an * 8 + tig * 2;
#pragma unroll
            for (int half = 0; half < 2; half++) {
                int row = row0 + warp_m * 32 + am * 16 + gi + half * 8;
                if (row >= M) continue;
                Out[(size_t)row * CDIM + col]     = c[am][an][half * 2 + 0] + bias[col];
                Out[(size_t)row * CDIM + col + 1] = c[am][an][half * 2 + 1] + bias[col + 1];
            }
        }
    }
}

struct AprojAll {
    const float* X[3];
    const float* W[3];
    const float* B[3];
    const float* skipP[3];
    float* XO[3];
};
__global__ __launch_bounds__(256, 4) void gemm_aproj_all(AprojAll t)
{
    GEMM_SMEM
    const int bx = blockIdx.x;
    int ty, bl;
    if (bx < NBP)            { ty = 0; bl = bx; }
    else if (bx < NBP + NBI) { ty = 1; bl = bx - NBP; }
    else                     { ty = 2; bl = bx - NBP - NBI; }
    const int M = (ty == 0) ? NPAT : (ty == 1) ? NICD : NNDC;
    const int row0 = bl * 128;
    const int ncol0 = blockIdx.y * 64;
    const float* __restrict__ X = t.X[ty];
    const float* __restrict__ W = t.W[ty];
    const float* __restrict__ bias = t.B[ty];
    float* __restrict__ Out = t.XO[ty];

    const int tid = threadIdx.x;
    const int lane = tid & 31;
    const int wid = tid >> 5;
    const int warp_m = wid >> 1;
    const int warp_n = wid & 1;
    const int gi = lane >> 2;
    const int tig = lane & 3;

    ACC_INIT
    gemm_core64<1>(X, W, CDIM, M, CDIM, row0, ncol0, c, Ah, Al, Bh, Bl);

    float s = 1.0f / (1.0f + __expf(-*t.skipP[ty]));
    float sa = s, sb = 1.0f - s;
#pragma unroll
    for (int am = 0; am < 2; am++) {
#pragma unroll
        for (int an = 0; an < 4; an++) {
            int col = ncol0 + warp_n * 32 + an * 8 + tig * 2;
#pragma unroll
            for (int half = 0; half < 2; half++) {
                int row = row0 + warp_m * 32 + am * 16 + gi + half * 8;
                if (row >= M) continue;
                size_t o0 = (size_t)row * CDIM + col;
                float v0 = sa * (c[am][an][half * 2 + 0] + bias[col])     + sb * Out[o0];
                float v1 = sa * (c[am][an][half * 2 + 1] + bias[col + 1]) + sb * Out[o0 + 1];
                Out[o0]     = v0;
                Out[o0 + 1] = v1;
            }
        }
    }
}

// ---------------- merged relu(embedding gather) ----------------
__global__ void embed2(const float* __restrict__ ei, const int* __restrict__ xi,
                       const float* __restrict__ en, const int* __restrict__ xn) {
    int i = blockIdx.x * blockDim.x + threadIdx.x;
    if (i < NICD * CDIM) {
        int r = i >> 7, c = i & 127;
        g_x[(size_t)(NPAT + r) * CDIM + c] = fmaxf(ei[(size_t)xi[r] * CDIM + c], 0.0f);
    } else {
        int jj = i - NICD * CDIM;
        if (jj < NNDC * CDIM) {
            int r = jj >> 7, c = jj & 127;
            g_x[(size_t)(NPAT + NICD + r) * CDIM + c] = fmaxf(en[(size_t)xn[r] * CDIM + c], 0.0f);
        }
    }
}

// ---------------- CSR build ----------------
struct EP { const int* src[4]; const int* dst[4]; };

__device__ __forceinline__ int soff_of(int r) {
    return (r == 0) ? SOFF0 : (r == 1) ? SOFF1 : (r == 2) ? SOFF2 : SOFF3;
}

__global__ void csr_clear() {
    int i = blockIdx.x * blockDim.x + threadIdx.x;
    if (i < NSOFT) { g_cnt[i] = 0; g_cur[i] = 0; }
}

__global__ void csr_hist(EP ep) {
    int r = blockIdx.y;
    int i = blockIdx.x * blockDim.x + threadIdx.x;
    if (i < NEDGE) atomicAdd(&g_cnt[soff_of(r) + ep.dst[r][i]], 1);
}

// single-block exclusive scan over NSOFT counters
__global__ __launch_bounds__(1024) void csr_scan() {
    __shared__ int partial[1024];
    const int CH = (NSOFT + 1023) / 1024;   // 101
    int t = threadIdx.x;
    int s0 = t * CH;
    int s1 = s0 + CH; if (s1 > NSOFT) s1 = NSOFT;
    int sum = 0;
    for (int i = s0; i < s1; i++) sum += g_cnt[i];
    partial[t] = sum;
    __syncthreads();
    for (int d = 1; d < 1024; d <<= 1) {
        int v = (t >= d) ? partial[t - d] : 0;
        __syncthreads();
        partial[t] += v;
        __syncthreads();
    }
    int pre = (t == 0) ? 0 : partial[t - 1];
    for (int i = s0; i < s1; i++) { g_off[i] = pre; pre += g_cnt[i]; }
}

__global__ void csr_scatter(EP ep) {
    int r = blockIdx.y;
    int i = blockIdx.x * blockDim.x + threadIdx.x;
    if (i < NEDGE) {
        int b = soff_of(r) + ep.dst[r][i];
        int pos = g_off[b] + atomicAdd(&g_cur[b], 1);
        g_csr[pos] = ep.src[r][i];
    }
}

// ---------------- fused edge kernel: per-dst softmax + aggregation, no atomics ----------------
// blocks [0, EPB): 8 patient-warps each (relations 1 and 3)
// blocks [EPB, EALL): one dst (icd r0 / ndc r2) per block, 8 warps over its edge list
__global__ __launch_bounds__(256) void edge_fused(const float* __restrict__ prel)
{
    __shared__ float sacc[8][128];
    __shared__ float ses[8][8];
    const int b = blockIdx.x;
    const int tid = threadIdx.x;
    const int w = tid >> 5;
    const int lane = tid & 31;
    const int h = lane >> 2;

    if (b < EPB) {
        int d = b * 8 + w;   // patient id (EPB*8 == NPAT exactly)
        float4 qv = *reinterpret_cast<const float4*>(&g_q[(size_t)d * CDIM + lane * 4]);
        float ax = 0.f, ay = 0.f, az = 0.f, aw2 = 0.f;
#pragma unroll
        for (int rr = 0; rr < 2; rr++) {
            const int rel = rr ? 3 : 1;
            const float* krb = rr ? g_krN : g_krI;
            const float* vrb = rr ? g_vrN : g_vrI;
            int base = (rr ? SOFF3 : SOFF1) + d;
            int st = g_off[base], n = g_cnt[base];
            float pf = prel[rel * 8 + h] * 0.25f;
            float es = 0.f, a0 = 0.f, a1 = 0.f, a2 = 0.f, a3 = 0.f;
            for (int i = 0; i < n; i++) {
                int s = g_csr[st + i];
                float4 kv = *reinterpret_cast<const float4*>(&krb[(size_t)s * CDIM + lane * 4]);
                float dot = qv.x * kv.x + qv.y * kv.y + qv.z * kv.z + qv.w * kv.w;
                dot += __shfl_xor_sync(0xffffffff, dot, 1);
                dot += __shfl_xor_sync(0xffffffff, dot, 2);
                float e = __expf(dot * pf);
                float4 vv = *reinterpret_cast<const float4*>(&vrb[(size_t)s * CDIM + lane * 4]);
                es += e;
                a0 += e * vv.x; a1 += e * vv.y; a2 += e * vv.z; a3 += e * vv.w;
            }
            if (n > 0) {
                float inv = 1.0f / es;
                ax += a0 * inv; ay += a1 * inv; az += a2 * inv; aw2 += a3 * inv;
            }
        }
        *reinterpret_cast<float4*>(&g_agg[(size_t)d * CDIM + lane * 4]) =
            make_float4(ax, ay, az, aw2);
    } else {
        int bb = b - EPB;
        int base;
        size_t nodeoff;
        const float *krb, *vrb;
        float pf;
        if (bb < NICD) {
            base = SOFF0 + bb;
            nodeoff = (size_t)(NPAT + bb);
            krb = g_krP0; vrb = g_vrP0;
            pf = prel[0 * 8 + h] * 0.25f;
        } else {
            int d = bb - NICD;
            base = SOFF2 + d;
            nodeoff = (size_t)(NPAT + NICD + d);
            krb = g_krP1; vrb = g_vrP1;
            pf = prel[2 * 8 + h] * 0.25f;
        }
        float4 qv = *reinterpret_cast<const float4*>(&g_q[nodeoff * CDIM + lane * 4]);
        int st = g_off[base], n = g_cnt[base];
        float es = 0.f, a0 = 0.f, a1 = 0.f, a2 = 0.f, a3 = 0.f;
        for (int i = w; i < n; i += 8) {
            int s = g_csr[st + i];
            float4 kv = *reinterpret_cast<const float4*>(&krb[(size_t)s * CDIM + lane * 4]);
            float dot = qv.x * kv.x + qv.y * kv.y + qv.z * kv.z + qv.w * kv.w;
            dot += __shfl_xor_sync(0xffffffff, dot, 1);
            dot += __shfl_xor_sync(0xffffffff, dot, 2);
            float e = __expf(dot * pf);
            float4 vv = *reinterpret_cast<const float4*>(&vrb[(size_t)s * CDIM + lane * 4]);
            es += e;
            a0 += e * vv.x; a1 += e * vv.y; a2 += e * vv.z; a3 += e * vv.w;
        }
        *reinterpret_cast<float4*>(&sacc[w][lane * 4]) = make_float4(a0, a1, a2, a3);
        if ((lane & 3) == 0) ses[w][h] = es;
        __syncthreads();
        if (tid < 128) {
            float s = 0.f, e = 0.f;
#pragma unroll
            for (int ww = 0; ww < 8; ww++) {
                s += sacc[ww][tid];
                e += ses[ww][tid >> 4];
            }
            g_agg[nodeoff * CDIM + tid] = (e > 0.f) ? s / e : 0.0f;
        }
    }
}

// ---------------- merged per-relation K/V transform ----------------
struct ReltAll {
    const float* A[4];
    const float* Mw[4];
};
__global__ __launch_bounds__(128) void relt_all(ReltAll ra)
{
    __shared__ float ks[32][128];
    __shared__ float vs[32][128];
    const int tid = threadIdx.x;
    const int bx = blockIdx.x;
    const int h = tid >> 4;
    const int e = tid & 15;

    int node0, nsrc, srcoff;
    const float *A0, *M0, *A1, *M1;
    float *kr0, *vr0, *kr1, *vr1;
    bool two;
    if (bx < RTP) {
        node0 = bx * 32; nsrc = NPAT; srcoff = 0; two = true;
        A0 = ra.A[0]; M0 = ra.Mw[0]; A1 = ra.A[2]; M1 = ra.Mw[2];
        kr0 = g_krP0; vr0 = g_vrP0; kr1 = g_krP1; vr1 = g_vrP1;
    } else if (bx < RTP + RTI) {
        node0 = (bx - RTP) * 32; nsrc = NICD; srcoff = NPAT; two = false;
        A0 = ra.A[1]; M0 = ra.Mw[1]; A1 = nullptr; M1 = nullptr;
        kr0 = g_krI; vr0 = g_vrI; kr1 = nullptr; vr1 = nullptr;
    } else {
        node0 = (bx - RTP - RTI) * 32; nsrc = NNDC; srcoff = NPAT + NICD; two = false;
        A0 = ra.A[3]; M0 = ra.Mw[3]; A1 = nullptr; M1 = nullptr;
        kr0 = g_krN; vr0 = g_vrN; kr1 = nullptr; vr1 = nullptr;
    }

    float areg0[16], mreg0[16], areg1[16], mreg1[16];
#pragma unroll
    for (int d = 0; d < 16; d++) {
        areg0[d] = A0[(h * 16 + d) * 16 + e];
        mreg0[d] = M0[(h * 16 + d) * 16 + e];
        if (two) {
            areg1[d] = A1[(h * 16 + d) * 16 + e];
            mreg1[d] = M1[(h * 16 + d) * 16 + e];
        }
    }

    const float* kbase = g_k + (size_t)srcoff * CDIM;
    const float* vbase = g_v + (size_t)srcoff * CDIM;
    for (int i = tid; i < 32 * 32; i += 128) {
        int r = i >> 5;
        int cidx = (i & 31) * 4;
        if (node0 + r < nsrc) {
            *reinterpret_cast<float4*>(&ks[r][cidx]) =
                *reinterpret_cast<const float4*>(&kbase[(size_t)(node0 + r) * CDIM + cidx]);
            *reinterpret_cast<float4*>(&vs[r][cidx]) =
                *reinterpret_cast<const float4*>(&vbase[(size_t)(node0 + r) * CDIM + cidx]);
        }
    }
    __syncthreads();

    int nmax = nsrc - node0; if (nmax > 32) nmax = 32;
    for (int n = 0; n < nmax; n++) {
        float acck0 = 0.f, accv0 = 0.f, acck1 = 0.f, accv1 = 0.f;
#pragma unroll
        for (int d4 = 0; d4 < 4; d4++) {
            float4 kq = *reinterpret_cast<const float4*>(&ks[n][h * 16 + d4 * 4]);
            float4 vq = *reinterpret_cast<const float4*>(&vs[n][h * 16 + d4 * 4]);
            float kk[4] = {kq.x, kq.y, kq.z, kq.w};
            float vv[4] = {vq.x, vq.y, vq.z, vq.w};
#pragma unroll
            for (int j = 0; j < 4; j++) {
                int d = d4 * 4 + j;
                acck0 = fmaf(kk[j], areg0[d], acck0);
                accv0 = fmaf(vv[j], mreg0[d], accv0);
                if (two) {
                    acck1 = fmaf(kk[j], areg1[d], acck1);
                    accv1 = fmaf(vv[j], mreg1[d], accv1);
                }
            }
        }
        size_t o = (size_t)(node0 + n) * CDIM + h * 16 + e;
        kr0[o] = acck0; vr0[o] = accv0;
        if (two) { kr1[o] = acck1; vr1[o] = accv1; }
    }
}

// ---------------- host ----------------
extern "C" void kernel_launch(void* const* d_in, const int* in_sizes, int n_in,
                              void* d_out, int out_size)
{
    const float* x_patient = (const float*)d_in[0];
    const float* w_in      = (const float*)d_in[1];
    const float* b_in      = (const float*)d_in[2];
    const float* emb_icd   = (const float*)d_in[3];
    const float* emb_ndc   = (const float*)d_in[4];
    const float* kw = (const float*)d_in[5];
    const float* kb = (const float*)d_in[6];
    const float* qw = (const float*)d_in[7];
    const float* qb = (const float*)d_in[8];
    const float* vw = (const float*)d_in[9];
    const float* vb = (const float*)d_in[10];
    const float* aw = (const float*)d_in[11];
    const float* ab = (const float*)d_in[12];
    const float* skip  = (const float*)d_in[13];
    const float* a_rel = (const float*)d_in[14];
    const float* m_rel = (const float*)d_in[15];
    const float* p_rel = (const float*)d_in[16];
    const float* w_out = (const float*)d_in[17];
    const float* b_out = (const float*)d_in[18];
    const int* x_icd = (const int*)d_in[19];
    const int* x_ndc = (const int*)d_in[20];
    const int* esrc[4] = {(const int*)d_in[21], (const int*)d_in[23],
                          (const int*)d_in[25], (const int*)d_in[27]};
    const int* edst[4] = {(const int*)d_in[22], (const int*)d_in[24],
                          (const int*)d_in[26], (const int*)d_in[28]};
    float* out = (float*)d_out;

    void* p;
    cudaGetSymbolAddress(&p, g_x);     float* px    = (float*)p;
    cudaGetSymbolAddress(&p, g_k);     float* pk    = (float*)p;
    cudaGetSymbolAddress(&p, g_q);     float* pq    = (float*)p;
    cudaGetSymbolAddress(&p, g_v);     float* pv    = (float*)p;
    cudaGetSymbolAddress(&p, g_agg);   float* pagg  = (float*)p;

    const int toff[3] = {0, NPAT, NPAT + NICD};

    EP ep;
    for (int r = 0; r < 4; r++) { ep.src[r] = esrc[r]; ep.dst[r] = edst[r]; }

    // input projection / embeddings
    {
        dim3 g(NBP, 2);
        gemm_bf3<0, 0><<<g, 256>>>(
            x_patient, w_in, CDIM, b_in, px, CDIM, NPAT, CDIM, nullptr, nullptr);
    }
    embed2<<<((NICD + NNDC) * CDIM + 255) / 256, 256>>>(emb_icd, x_icd, emb_ndc, x_ndc);

    // CSR build (once; indices are layer-invariant)
    csr_clear<<<(NSOFT + 255) / 256, 256>>>();
    {
        dim3 g((NEDGE + 255) / 256, 4);
        csr_hist<<<g, 256>>>(ep);
        csr_scan<<<1, 1024>>>();
        csr_scatter<<<g, 256>>>(ep);
    }

    for (int l = 0; l < 2; l++) {
        // merged K/Q/V GEMM
        {
            KQVAll t;
            const float* ws[3] = {kw, qw, vw};
            const float* bs[3] = {kb, qb, vb};
            float* os[3] = {pk, pq, pv};
            for (int ty = 0; ty < 3; ty++) {
                t.X[ty] = px + (size_t)toff[ty] * CDIM;
                for (int j = 0; j < 3; j++) {
                    t.W[j * 3 + ty] = ws[j] + (size_t)(l * 3 + ty) * CDIM * CDIM;
                    t.B[j * 3 + ty] = bs[j] + (size_t)(l * 3 + ty) * CDIM;
                    t.O[j * 3 + ty] = os[j] + (size_t)toff[ty] * CDIM;
                }
            }
            dim3 grid(NBALL, 3, 2);
            gemm_kqv_all<<<grid, 256>>>(t);
        }

        // merged relation K/V transforms
        {
            ReltAll ra;
            for (int r = 0; r < 4; r++) {
                ra.A[r]  = a_rel + (size_t)(l * 4 + r) * HH * DD * DD;
                ra.Mw[r] = m_rel + (size_t)(l * 4 + r) * HH * DD * DD;
            }
            relt_all<<<RTALL, 128>>>(ra);
        }

        // fused edge phase: per-dst softmax + aggregation (no atomics, no fills)
        edge_fused<<<EALL, 256>>>(p_rel + l * 32);

        // merged A-proj GEMM
        {
            AprojAll t;
            for (int ty = 0; ty < 3; ty++) {
                t.X[ty] = pagg + (size_t)toff[ty] * CDIM;
                t.W[ty] = aw + (size_t)(l * 3 + ty) * CDIM * CDIM;
                t.B[ty] = ab + (size_t)(l * 3 + ty) * CDIM;
                t.skipP[ty] = skip + (l * 3 + ty);
                t.XO[ty] = px + (size_t)toff[ty] * CDIM;
            }
            dim3 grid(NBALL, 2);
            gemm_aproj_all<<<grid, 256>>>(t);
        }
    }

    // output projection + sigmoid
    {
        dim3 g(NBP, 2);
        gemm_bf3<0, 3><<<g, 256>>>(
            px, w_out, OUTD, b_out, out, OUTD, NPAT, OUTD, nullptr, nullptr);
    }
}

// round 9
// speedup vs baseline: 1.8982x; 1.0721x over previous
#include <cuda_runtime.h>
#include <math.h>
#include <stdint.h>

#define NPAT 50000
#define NICD 591
#define NNDC 2042
#define NTOTAL 52633
#define NSOFT 102633
#define CDIM 128
#define HH 8
#define DD 16
#define NEDGE 250000
#define OUTD 90

#define SOFF0 0
#define SOFF1 NICD
#define SOFF2 (NICD + NPAT)
#define SOFF3 (NICD + NPAT + NNDC)

#define NBP 391
#define NBI 5
#define NBN 16
#define NBALL (NBP + NBI + NBN)

#define RTP 1563
#define RTI 19
#define RTN 64
#define RTALL (RTP + RTI + RTN)

#define EPB 6250
#define EBLK (NICD + NNDC)
#define EALL (EPB + EBLK)

// ---------------- scratch ----------------
__device__ float g_x[NTOTAL * CDIM];
__device__ float g_k[NTOTAL * CDIM];
__device__ float g_q[NTOTAL * CDIM];
__device__ float g_v[NTOTAL * CDIM];
__device__ float g_agg[NTOTAL * CDIM];
__device__ float g_krP0[NPAT * CDIM];
__device__ float g_vrP0[NPAT * CDIM];
__device__ float g_krP1[NPAT * CDIM];
__device__ float g_vrP1[NPAT * CDIM];
__device__ float g_krI[NICD * CDIM];
__device__ float g_vrI[NICD * CDIM];
__device__ float g_krN[NNDC * CDIM];
__device__ float g_vrN[NNDC * CDIM];
__device__ int g_cnt[NSOFT];
__device__ int g_off[NSOFT];
__device__ int g_cur[NSOFT];
__device__ int g_csr[4 * NEDGE];

__device__ __forceinline__ float geluf(float x) {
    float t = tanhf(0.7978845608028654f * (x + 0.044715f * x * x * x));
    return 0.5f * x * (1.0f + t);
}

__device__ __forceinline__ void split_pair(float v0, float v1, uint32_t& h, uint32_t& l) {
    uint32_t hh;
    asm("cvt.rn.bf16x2.f32 %0, %1, %2;" : "=r"(hh) : "f"(v1), "f"(v0));
    float h0 = __uint_as_float(hh << 16);
    float h1 = __uint_as_float(hh & 0xffff0000u);
    float l0 = v0 - h0;
    float l1 = v1 - h1;
    uint32_t ll;
    asm("cvt.rn.bf16x2.f32 %0, %1, %2;" : "=r"(ll) : "f"(l1), "f"(l0));
    h = hh; l = ll;
}

__device__ __forceinline__ void mma_bf16(float* c, const uint32_t* a, const uint32_t* b) {
    asm volatile("mma.sync.aligned.m16n8k16.row.col.f32.bf16.bf16.f32 "
                 "{%0,%1,%2,%3}, {%4,%5,%6,%7}, {%8,%9}, {%0,%1,%2,%3};"
                 : "+f"(c[0]), "+f"(c[1]), "+f"(c[2]), "+f"(c[3])
                 : "r"(a[0]), "r"(a[1]), "r"(a[2]), "r"(a[3]),
                   "r"(b[0]), "r"(b[1]));
}

#define SA 20

// ---------------- GEMM core: 128(M) x 64(N), 8 warps, warp tile 32x32 ----------------
template<int INACT>
__device__ __forceinline__ void gemm_core64(
    const float* __restrict__ X,
    const float* __restrict__ W, int ldw,
    int M, int N, int row0, int ncol0,
    float c[2][4][4],
    uint32_t (*Ah)[SA], uint32_t (*Al)[SA],
    uint32_t (*Bh)[SA], uint32_t (*Bl)[SA])
{
    const int tid = threadIdx.x;
    const int lane = tid & 31;
    const int wid = tid >> 5;
    const int warp_m = wid >> 1;
    const int warp_n = wid & 1;
    const int gi = lane >> 2;
    const int tig = lane & 3;

    const int ar = tid >> 1;
    const int akh = tid & 1;
    const bool arow_ok = (row0 + ar) < M;
    const float* xrow = X + (size_t)(row0 + ar) * CDIM;
    const int bkp = tid >> 4;
    const int bc0 = tid & 15;

    for (int kc = 0; kc < CDIM; kc += 32) {
#pragma unroll
        for (int i = 0; i < 4; i++) {
            float4 xv = make_float4(0.f, 0.f, 0.f, 0.f);
            if (arow_ok) xv = *reinterpret_cast<const float4*>(xrow + kc + akh * 16 + i * 4);
            if (INACT == 1) {
                xv.x = geluf(xv.x); xv.y = geluf(xv.y);
                xv.z = geluf(xv.z); xv.w = geluf(xv.w);
            }
            uint32_t h0, l0, h1, l1;
            split_pair(xv.x, xv.y, h0, l0);
            split_pair(xv.z, xv.w, h1, l1);
            int kp = akh * 8 + i * 2;
            Ah[ar][kp] = h0;     Al[ar][kp] = l0;
            Ah[ar][kp + 1] = h1; Al[ar][kp + 1] = l1;
        }
        {
            const float* w0 = W + (size_t)(kc + 2 * bkp) * ldw;
            const float* w1 = w0 + ldw;
#pragma unroll
            for (int i = 0; i < 4; i++) {
                int nl = bc0 + 16 * i;
                int n = ncol0 + nl;
                float v0 = (n < N) ? w0[n] : 0.0f;
                float v1 = (n < N) ? w1[n] : 0.0f;
                uint32_t h, l;
                split_pair(v0, v1, h, l);
                Bh[nl][bkp] = h;
                Bl[nl][bkp] = l;
            }
        }
        __syncthreads();

#pragma unroll
        for (int ks = 0; ks < 2; ks++) {
            const int kb = ks * 8;
            uint32_t ah[2][4], al[2][4];
#pragma unroll
            for (int am = 0; am < 2; am++) {
                int rb = warp_m * 32 + am * 16 + gi;
                ah[am][0] = Ah[rb][kb + tig];
                ah[am][1] = Ah[rb + 8][kb + tig];
                ah[am][2] = Ah[rb][kb + 4 + tig];
                ah[am][3] = Ah[rb + 8][kb + 4 + tig];
                al[am][0] = Al[rb][kb + tig];
                al[am][1] = Al[rb + 8][kb + tig];
                al[am][2] = Al[rb][kb + 4 + tig];
                al[am][3] = Al[rb + 8][kb + 4 + tig];
            }
#pragma unroll
            for (int an = 0; an < 4; an++) {
                int nc = warp_n * 32 + an * 8 + gi;
                uint32_t bh[2], bl[2];
                bh[0] = Bh[nc][kb + tig];
                bh[1] = Bh[nc][kb + 4 + tig];
                bl[0] = Bl[nc][kb + tig];
                bl[1] = Bl[nc][kb + 4 + tig];
#pragma unroll
                for (int am = 0; am < 2; am++) {
                    mma_bf16(c[am][an], ah[am], bh);
                    mma_bf16(c[am][an], al[am], bh);
                    mma_bf16(c[am][an], ah[am], bl);
                }
            }
        }
        __syncthreads();
    }
}

#define GEMM_SMEM \
    __shared__ uint32_t Ah[128][SA]; \
    __shared__ uint32_t Al[128][SA]; \
    __shared__ uint32_t Bh[64][SA];  \
    __shared__ uint32_t Bl[64][SA];

#define ACC_INIT \
    float c[2][4][4]; \
    _Pragma("unroll") for (int am = 0; am < 2; am++) \
    _Pragma("unroll") for (int an = 0; an < 4; an++) \
    _Pragma("unroll") for (int j = 0; j < 4; j++) c[am][an][j] = 0.0f;

template<int INACT, int MODE>
__global__ __launch_bounds__(256, 4) void gemm_bf3(
    const float* __restrict__ X,
    const float* __restrict__ W, int ldw,
    const float* __restrict__ bias,
    float* __restrict__ Out, int ldo,
    int M, int N,
    const float* __restrict__ skipPtr,
    const float* __restrict__ xold)
{
    GEMM_SMEM
    const int tid = threadIdx.x;
    const int row0 = blockIdx.x * 128;
    const int ncol0 = blockIdx.y * 64;
    const int lane = tid & 31;
    const int wid = tid >> 5;
    const int warp_m = wid >> 1;
    const int warp_n = wid & 1;
    const int gi = lane >> 2;
    const int tig = lane & 3;

    ACC_INIT
    gemm_core64<INACT>(X, W, ldw, M, N, row0, ncol0, c, Ah, Al, Bh, Bl);

    float sa = 0.f, sb = 0.f;
    if (MODE == 2) {
        float s = 1.0f / (1.0f + __expf(-*skipPtr));
        sa = s; sb = 1.0f - s;
    }
#pragma unroll
    for (int am = 0; am < 2; am++) {
#pragma unroll
        for (int an = 0; an < 4; an++) {
            int col = ncol0 + warp_n * 32 + an * 8 + tig * 2;
#pragma unroll
            for (int half = 0; half < 2; half++) {
                int row = row0 + warp_m * 32 + am * 16 + gi + half * 8;
                if (row >= M) continue;
#pragma unroll
                for (int j = 0; j < 2; j++) {
                    int cc = col + j;
                    if (cc >= N) continue;
                    float v = c[am][an][half * 2 + j] + bias[cc];
                    if (MODE == 0) v = fmaxf(v, 0.0f);
                    else if (MODE == 2) v = sa * v + sb * xold[(size_t)row * CDIM + cc];
                    else if (MODE == 3) v = 1.0f / (1.0f + __expf(-v));
                    Out[(size_t)row * ldo + cc] = v;
                }
            }
        }
    }
}

struct KQVAll {
    const float* X[3];
    const float* W[9];
    const float* B[9];
    float* O[9];
};
__global__ __launch_bounds__(256, 4) void gemm_kqv_all(KQVAll t)
{
    GEMM_SMEM
    const int bx = blockIdx.x;
    int ty, bl;
    if (bx < NBP)            { ty = 0; bl = bx; }
    else if (bx < NBP + NBI) { ty = 1; bl = bx - NBP; }
    else                     { ty = 2; bl = bx - NBP - NBI; }
    const int M = (ty == 0) ? NPAT : (ty == 1) ? NICD : NNDC;
    const int j = blockIdx.y;
    const int ncol0 = blockIdx.z * 64;
    const float* __restrict__ X = t.X[ty];
    const float* __restrict__ W = t.W[j * 3 + ty];
    const float* __restrict__ bias = t.B[j * 3 + ty];
    float* __restrict__ Out = t.O[j * 3 + ty];
    const int row0 = bl * 128;

    const int tid = threadIdx.x;
    const int lane = tid & 31;
    const int wid = tid >> 5;
    const int warp_m = wid >> 1;
    const int warp_n = wid & 1;
    const int gi = lane >> 2;
    const int tig = lane & 3;

    ACC_INIT
    gemm_core64<0>(X, W, CDIM, M, CDIM, row0, ncol0, c, Ah, Al, Bh, Bl);

#pragma unroll
    for (int am = 0; am < 2; am++) {
#pragma unroll
        for (int an = 0; an < 4; an++) {
            int col = ncol0 + warp_n * 32 + an * 8 + tig * 2;
#pragma unroll
            for (int half = 0; half < 2; half++) {
                int row = row0 + warp_m * 32 + am * 16 + gi + half * 8;
                if (row >= M) continue;
                Out[(size_t)row * CDIM + col]     = c[am][an][half * 2 + 0] + bias[col];
                Out[(size_t)row * CDIM + col + 1] = c[am][an][half * 2 + 1] + bias[col + 1];
            }
        }
    }
}

struct AprojAll {
    const float* X[3];
    const float* W[3];
    const float* B[3];
    const float* skipP[3];
    float* XO[3];
};
__global__ __launch_bounds__(256, 4) void gemm_aproj_all(AprojAll t)
{
    GEMM_SMEM
    const int bx = blockIdx.x;
    int ty, bl;
    if (bx < NBP)            { ty = 0; bl = bx; }
    else if (bx < NBP + NBI) { ty = 1; bl = bx - NBP; }
    else                     { ty = 2; bl = bx - NBP - NBI; }
    const int M = (ty == 0) ? NPAT : (ty == 1) ? NICD : NNDC;
    const int row0 = bl * 128;
    const int ncol0 = blockIdx.y * 64;
    const float* __restrict__ X = t.X[ty];
    const float* __restrict__ W = t.W[ty];
    const float* __restrict__ bias = t.B[ty];
    float* __restrict__ Out = t.XO[ty];

    const int tid = threadIdx.x;
    const int lane = tid & 31;
    const int wid = tid >> 5;
    const int warp_m = wid >> 1;
    const int warp_n = wid & 1;
    const int gi = lane >> 2;
    const int tig = lane & 3;

    ACC_INIT
    gemm_core64<1>(X, W, CDIM, M, CDIM, row0, ncol0, c, Ah, Al, Bh, Bl);

    float s = 1.0f / (1.0f + __expf(-*t.skipP[ty]));
    float sa = s, sb = 1.0f - s;
#pragma unroll
    for (int am = 0; am < 2; am++) {
#pragma unroll
        for (int an = 0; an < 4; an++) {
            int col = ncol0 + warp_n * 32 + an * 8 + tig * 2;
#pragma unroll
            for (int half = 0; half < 2; half++) {
                int row = row0 + warp_m * 32 + am * 16 + gi + half * 8;
                if (row >= M) continue;
                size_t o0 = (size_t)row * CDIM + col;
                float v0 = sa * (c[am][an][half * 2 + 0] + bias[col])     + sb * Out[o0];
                float v1 = sa * (c[am][an][half * 2 + 1] + bias[col + 1]) + sb * Out[o0 + 1];
                Out[o0]     = v0;
                Out[o0 + 1] = v1;
            }
        }
    }
}

// ---------------- merged relu(embedding gather) ----------------
__global__ void embed2(const float* __restrict__ ei, const int* __restrict__ xi,
                       const float* __restrict__ en, const int* __restrict__ xn) {
    int i = blockIdx.x * blockDim.x + threadIdx.x;
    if (i < NICD * CDIM) {
        int r = i >> 7, c = i & 127;
        g_x[(size_t)(NPAT + r) * CDIM + c] = fmaxf(ei[(size_t)xi[r] * CDIM + c], 0.0f);
    } else {
        int jj = i - NICD * CDIM;
        if (jj < NNDC * CDIM) {
            int r = jj >> 7, c = jj & 127;
            g_x[(size_t)(NPAT + NICD + r) * CDIM + c] = fmaxf(en[(size_t)xn[r] * CDIM + c], 0.0f);
        }
    }
}

// ---------------- CSR build ----------------
__global__ void csr_clear() {
    int i = blockIdx.x * blockDim.x + threadIdx.x;
    if (i < NSOFT) { g_cnt[i] = 0; g_cur[i] = 0; }
}

// patient-dst relations (r1, r3): uncontended, direct atomics, int4 loads
__global__ void csr_hist_pat(const int* __restrict__ d1, const int* __restrict__ d3) {
    int i = blockIdx.x * blockDim.x + threadIdx.x;
    if (i < NEDGE / 4) {
        int4 a = reinterpret_cast<const int4*>(d1)[i];
        atomicAdd(&g_cnt[SOFF1 + a.x], 1);
        atomicAdd(&g_cnt[SOFF1 + a.y], 1);
        atomicAdd(&g_cnt[SOFF1 + a.z], 1);
        atomicAdd(&g_cnt[SOFF1 + a.w], 1);
        int4 b = reinterpret_cast<const int4*>(d3)[i];
        atomicAdd(&g_cnt[SOFF3 + b.x], 1);
        atomicAdd(&g_cnt[SOFF3 + b.y], 1);
        atomicAdd(&g_cnt[SOFF3 + b.z], 1);
        atomicAdd(&g_cnt[SOFF3 + b.w], 1);
    }
}

// contended relations (r0 icd 591, r2 ndc 2042): smem-privatized histogram
__global__ __launch_bounds__(256) void csr_hist_sm(const int* __restrict__ dst0,
                                                   const int* __restrict__ dst2) {
    __shared__ int h[NNDC];
    const int r = blockIdx.y;
    const int ndst = r ? NNDC : NICD;
    const int so = r ? SOFF2 : SOFF0;
    const int* __restrict__ dst = r ? dst2 : dst0;
    for (int i = threadIdx.x; i < ndst; i += 256) h[i] = 0;
    __syncthreads();
    const int tot = NEDGE / 4;
    for (int i = blockIdx.x * 256 + threadIdx.x; i < tot; i += gridDim.x * 256) {
        int4 a = reinterpret_cast<const int4*>(dst)[i];
        atomicAdd(&h[a.x], 1); atomicAdd(&h[a.y], 1);
        atomicAdd(&h[a.z], 1); atomicAdd(&h[a.w], 1);
    }
    __syncthreads();
    for (int i = threadIdx.x; i < ndst; i += 256)
        if (h[i]) atomicAdd(&g_cnt[so + i], h[i]);
}

__global__ __launch_bounds__(1024) void csr_scan() {
    __shared__ int partial[1024];
    const int CH = (NSOFT + 1023) / 1024;
    int t = threadIdx.x;
    int s0 = t * CH;
    int s1 = s0 + CH; if (s1 > NSOFT) s1 = NSOFT;
    int sum = 0;
    for (int i = s0; i < s1; i++) sum += g_cnt[i];
    partial[t] = sum;
    __syncthreads();
    for (int d = 1; d < 1024; d <<= 1) {
        int v = (t >= d) ? partial[t - d] : 0;
        __syncthreads();
        partial[t] += v;
        __syncthreads();
    }
    int pre = (t == 0) ? 0 : partial[t - 1];
    for (int i = s0; i < s1; i++) { g_off[i] = pre; pre += g_cnt[i]; }
}

__global__ void csr_scatter_pat(const int* __restrict__ s1, const int* __restrict__ d1,
                                const int* __restrict__ s3, const int* __restrict__ d3) {
    int i = blockIdx.x * blockDim.x + threadIdx.x;
    if (i < NEDGE) {
        int b1 = SOFF1 + d1[i];
        g_csr[g_off[b1] + atomicAdd(&g_cur[b1], 1)] = s1[i];
        int b3 = SOFF3 + d3[i];
        g_csr[g_off[b3] + atomicAdd(&g_cur[b3], 1)] = s3[i];
    }
}

// privatized two-pass scatter for contended relations; any within-list order is valid
__global__ __launch_bounds__(256) void csr_scatter_sm(
    const int* __restrict__ src0, const int* __restrict__ dst0,
    const int* __restrict__ src2, const int* __restrict__ dst2) {
    __shared__ int h[NNDC];
    __shared__ int base[NNDC];
    const int r = blockIdx.y;
    const int ndst = r ? NNDC : NICD;
    const int so = r ? SOFF2 : SOFF0;
    const int* __restrict__ dst = r ? dst2 : dst0;
    const int* __restrict__ src = r ? src2 : src0;
    const int chunk = (NEDGE + gridDim.x - 1) / gridDim.x;
    const int e0 = blockIdx.x * chunk;
    int e1 = e0 + chunk; if (e1 > NEDGE) e1 = NEDGE;

    for (int i = threadIdx.x; i < ndst; i += 256) h[i] = 0;
    __syncthreads();
    for (int e = e0 + threadIdx.x; e < e1; e += 256) atomicAdd(&h[dst[e]], 1);
    __syncthreads();
    for (int i = threadIdx.x; i < ndst; i += 256) {
        int cc = h[i];
        base[i] = cc ? atomicAdd(&g_cur[so + i], cc) : 0;
    }
    __syncthreads();
    for (int i = threadIdx.x; i < ndst; i += 256) h[i] = 0;
    __syncthreads();
    for (int e = e0 + threadIdx.x; e < e1; e += 256) {
        int d = dst[e];
        int loc = atomicAdd(&h[d], 1);
        g_csr[g_off[so + d] + base[d] + loc] = src[e];
    }
}

// ---------------- fused edge kernel ----------------
__global__ __launch_bounds__(256) void edge_fused(const float* __restrict__ prel)
{
    __shared__ float sacc[8][128];
    __shared__ float ses[8][8];
    const int b = blockIdx.x;
    const int tid = threadIdx.x;
    const int w = tid >> 5;
    const int lane = tid & 31;
    const int h = lane >> 2;

    if (b < EPB) {
        int d = b * 8 + w;
        float4 qv = *reinterpret_cast<const float4*>(&g_q[(size_t)d * CDIM + lane * 4]);
        float ax = 0.f, ay = 0.f, az = 0.f, aw2 = 0.f;
#pragma unroll
        for (int rr = 0; rr < 2; rr++) {
            const int rel = rr ? 3 : 1;
            const float* krb = rr ? g_krN : g_krI;
            const float* vrb = rr ? g_vrN : g_vrI;
            int base = (rr ? SOFF3 : SOFF1) + d;
            int st = g_off[base], n = g_cnt[base];
            float pf = prel[rel * 8 + h] * 0.25f;
            float es = 0.f, a0 = 0.f, a1 = 0.f, a2 = 0.f, a3 = 0.f;
            for (int i = 0; i < n; i++) {
                int s = g_csr[st + i];
                float4 kv = *reinterpret_cast<const float4*>(&krb[(size_t)s * CDIM + lane * 4]);
                float dot = qv.x * kv.x + qv.y * kv.y + qv.z * kv.z + qv.w * kv.w;
                dot += __shfl_xor_sync(0xffffffff, dot, 1);
                dot += __shfl_xor_sync(0xffffffff, dot, 2);
                float e = __expf(dot * pf);
                float4 vv = *reinterpret_cast<const float4*>(&vrb[(size_t)s * CDIM + lane * 4]);
                es += e;
                a0 += e * vv.x; a1 += e * vv.y; a2 += e * vv.z; a3 += e * vv.w;
            }
            if (n > 0) {
                float inv = 1.0f / es;
                ax += a0 * inv; ay += a1 * inv; az += a2 * inv; aw2 += a3 * inv;
            }
        }
        *reinterpret_cast<float4*>(&g_agg[(size_t)d * CDIM + lane * 4]) =
            make_float4(ax, ay, az, aw2);
    } else {
        int bb = b - EPB;
        int base;
        size_t nodeoff;
        const float *krb, *vrb;
        float pf;
        if (bb < NICD) {
            base = SOFF0 + bb;
            nodeoff = (size_t)(NPAT + bb);
            krb = g_krP0; vrb = g_vrP0;
            pf = prel[0 * 8 + h] * 0.25f;
        } else {
            int d = bb - NICD;
            base = SOFF2 + d;
            nodeoff = (size_t)(NPAT + NICD + d);
            krb = g_krP1; vrb = g_vrP1;
            pf = prel[2 * 8 + h] * 0.25f;
        }
        float4 qv = *reinterpret_cast<const float4*>(&g_q[nodeoff * CDIM + lane * 4]);
        int st = g_off[base], n = g_cnt[base];
        float es = 0.f, a0 = 0.f, a1 = 0.f, a2 = 0.f, a3 = 0.f;
        for (int i = w; i < n; i += 8) {
            int s = g_csr[st + i];
            float4 kv = *reinterpret_cast<const float4*>(&krb[(size_t)s * CDIM + lane * 4]);
            float dot = qv.x * kv.x + qv.y * kv.y + qv.z * kv.z + qv.w * kv.w;
            dot += __shfl_xor_sync(0xffffffff, dot, 1);
            dot += __shfl_xor_sync(0xffffffff, dot, 2);
            float e = __expf(dot * pf);
            float4 vv = *reinterpret_cast<const float4*>(&vrb[(size_t)s * CDIM + lane * 4]);
            es += e;
            a0 += e * vv.x; a1 += e * vv.y; a2 += e * vv.z; a3 += e * vv.w;
        }
        *reinterpret_cast<float4*>(&sacc[w][lane * 4]) = make_float4(a0, a1, a2, a3);
        if ((lane & 3) == 0) ses[w][h] = es;
        __syncthreads();
        if (tid < 128) {
            float s = 0.f, e = 0.f;
#pragma unroll
            for (int ww = 0; ww < 8; ww++) {
                s += sacc[ww][tid];
                e += ses[ww][tid >> 4];
            }
            g_agg[nodeoff * CDIM + tid] = (e > 0.f) ? s / e : 0.0f;
        }
    }
}

// ---------------- merged per-relation K/V transform ----------------
struct ReltAll {
    const float* A[4];
    const float* Mw[4];
};
__global__ __launch_bounds__(128) void relt_all(ReltAll ra)
{
    __shared__ float ks[32][128];
    __shared__ float vs[32][128];
    const int tid = threadIdx.x;
    const int bx = blockIdx.x;
    const int h = tid >> 4;
    const int e = tid & 15;

    int node0, nsrc, srcoff;
    const float *A0, *M0, *A1, *M1;
    float *kr0, *vr0, *kr1, *vr1;
    bool two;
    if (bx < RTP) {
        node0 = bx * 32; nsrc = NPAT; srcoff = 0; two = true;
        A0 = ra.A[0]; M0 = ra.Mw[0]; A1 = ra.A[2]; M1 = ra.Mw[2];
        kr0 = g_krP0; vr0 = g_vrP0; kr1 = g_krP1; vr1 = g_vrP1;
    } else if (bx < RTP + RTI) {
        node0 = (bx - RTP) * 32; nsrc = NICD; srcoff = NPAT; two = false;
        A0 = ra.A[1]; M0 = ra.Mw[1]; A1 = nullptr; M1 = nullptr;
        kr0 = g_krI; vr0 = g_vrI; kr1 = nullptr; vr1 = nullptr;
    } else {
        node0 = (bx - RTP - RTI) * 32; nsrc = NNDC; srcoff = NPAT + NICD; two = false;
        A0 = ra.A[3]; M0 = ra.Mw[3]; A1 = nullptr; M1 = nullptr;
        kr0 = g_krN; vr0 = g_vrN; kr1 = nullptr; vr1 = nullptr;
    }

    float areg0[16], mreg0[16], areg1[16], mreg1[16];
#pragma unroll
    for (int d = 0; d < 16; d++) {
        areg0[d] = A0[(h * 16 + d) * 16 + e];
        mreg0[d] = M0[(h * 16 + d) * 16 + e];
        if (two) {
            areg1[d] = A1[(h * 16 + d) * 16 + e];
            mreg1[d] = M1[(h * 16 + d) * 16 + e];
        }
    }

    const float* kbase = g_k + (size_t)srcoff * CDIM;
    const float* vbase = g_v + (size_t)srcoff * CDIM;
    for (int i = tid; i < 32 * 32; i += 128) {
        int r = i >> 5;
        int cidx = (i & 31) * 4;
        if (node0 + r < nsrc) {
            *reinterpret_cast<float4*>(&ks[r][cidx]) =
                *reinterpret_cast<const float4*>(&kbase[(size_t)(node0 + r) * CDIM + cidx]);
            *reinterpret_cast<float4*>(&vs[r][cidx]) =
                *reinterpret_cast<const float4*>(&vbase[(size_t)(node0 + r) * CDIM + cidx]);
        }
    }
    __syncthreads();

    int nmax = nsrc - node0; if (nmax > 32) nmax = 32;
    for (int n = 0; n < nmax; n++) {
        float acck0 = 0.f, accv0 = 0.f, acck1 = 0.f, accv1 = 0.f;
#pragma unroll
        for (int d4 = 0; d4 < 4; d4++) {
            float4 kq = *reinterpret_cast<const float4*>(&ks[n][h * 16 + d4 * 4]);
            float4 vq = *reinterpret_cast<const float4*>(&vs[n][h * 16 + d4 * 4]);
            float kk[4] = {kq.x, kq.y, kq.z, kq.w};
            float vv[4] = {vq.x, vq.y, vq.z, vq.w};
#pragma unroll
            for (int j = 0; j < 4; j++) {
                int d = d4 * 4 + j;
                acck0 = fmaf(kk[j], areg0[d], acck0);
                accv0 = fmaf(vv[j], mreg0[d], accv0);
                if (two) {
                    acck1 = fmaf(kk[j], areg1[d], acck1);
                    accv1 = fmaf(vv[j], mreg1[d], accv1);
                }
            }
        }
        size_t o = (size_t)(node0 + n) * CDIM + h * 16 + e;
        kr0[o] = acck0; vr0[o] = accv0;
        if (two) { kr1[o] = acck1; vr1[o] = accv1; }
    }
}

// ---------------- host ----------------
extern "C" void kernel_launch(void* const* d_in, const int* in_sizes, int n_in,
                              void* d_out, int out_size)
{
    const float* x_patient = (const float*)d_in[0];
    const float* w_in      = (const float*)d_in[1];
    const float* b_in      = (const float*)d_in[2];
    const float* emb_icd   = (const float*)d_in[3];
    const float* emb_ndc   = (const float*)d_in[4];
    const float* kw = (const float*)d_in[5];
    const float* kb = (const float*)d_in[6];
    const float* qw = (const float*)d_in[7];
    const float* qb = (const float*)d_in[8];
    const float* vw = (const float*)d_in[9];
    const float* vb = (const float*)d_in[10];
    const float* aw = (const float*)d_in[11];
    const float* ab = (const float*)d_in[12];
    const float* skip  = (const float*)d_in[13];
    const float* a_rel = (const float*)d_in[14];
    const float* m_rel = (const float*)d_in[15];
    const float* p_rel = (const float*)d_in[16];
    const float* w_out = (const float*)d_in[17];
    const float* b_out = (const float*)d_in[18];
    const int* x_icd = (const int*)d_in[19];
    const int* x_ndc = (const int*)d_in[20];
    const int* esrc[4] = {(const int*)d_in[21], (const int*)d_in[23],
                          (const int*)d_in[25], (const int*)d_in[27]};
    const int* edst[4] = {(const int*)d_in[22], (const int*)d_in[24],
                          (const int*)d_in[26], (const int*)d_in[28]};
    float* out = (float*)d_out;

    void* p;
    cudaGetSymbolAddress(&p, g_x);     float* px    = (float*)p;
    cudaGetSymbolAddress(&p, g_k);     float* pk    = (float*)p;
    cudaGetSymbolAddress(&p, g_q);     float* pq    = (float*)p;
    cudaGetSymbolAddress(&p, g_v);     float* pv    = (float*)p;
    cudaGetSymbolAddress(&p, g_agg);   float* pagg  = (float*)p;

    const int toff[3] = {0, NPAT, NPAT + NICD};

    // input projection / embeddings
    {
        dim3 g(NBP, 2);
        gemm_bf3<0, 0><<<g, 256>>>(
            x_patient, w_in, CDIM, b_in, px, CDIM, NPAT, CDIM, nullptr, nullptr);
    }
    embed2<<<((NICD + NNDC) * CDIM + 255) / 256, 256>>>(emb_icd, x_icd, emb_ndc, x_ndc);

    // CSR build (once; indices are layer-invariant)
    csr_clear<<<(NSOFT + 255) / 256, 256>>>();
    csr_hist_pat<<<(NEDGE / 4 + 255) / 256, 256>>>(edst[1], edst[3]);
    {
        dim3 g(48, 2);
        csr_hist_sm<<<g, 256>>>(edst[0], edst[2]);
    }
    csr_scan<<<1, 1024>>>();
    csr_scatter_pat<<<(NEDGE + 255) / 256, 256>>>(esrc[1], edst[1], esrc[3], edst[3]);
    {
        dim3 g(64, 2);
        csr_scatter_sm<<<g, 256>>>(esrc[0], edst[0], esrc[2], edst[2]);
    }

    for (int l = 0; l < 2; l++) {
        // merged K/Q/V GEMM
        {
            KQVAll t;
            const float* ws[3] = {kw, qw, vw};
            const float* bs[3] = {kb, qb, vb};
            float* os[3] = {pk, pq, pv};
            for (int ty = 0; ty < 3; ty++) {
                t.X[ty] = px + (size_t)toff[ty] * CDIM;
                for (int j = 0; j < 3; j++) {
                    t.W[j * 3 + ty] = ws[j] + (size_t)(l * 3 + ty) * CDIM * CDIM;
                    t.B[j * 3 + ty] = bs[j] + (size_t)(l * 3 + ty) * CDIM;
                    t.O[j * 3 + ty] = os[j] + (size_t)toff[ty] * CDIM;
                }
            }
            dim3 grid(NBALL, 3, 2);
            gemm_kqv_all<<<grid, 256>>>(t);
        }

        // merged relation K/V transforms
        {
            ReltAll ra;
            for (int r = 0; r < 4; r++) {
                ra.A[r]  = a_rel + (size_t)(l * 4 + r) * HH * DD * DD;
                ra.Mw[r] = m_rel + (size_t)(l * 4 + r) * HH * DD * DD;
            }
            relt_all<<<RTALL, 128>>>(ra);
        }

        // fused edge phase
        edge_fused<<<EALL, 256>>>(p_rel + l * 32);

        // merged A-proj GEMM
        {
            AprojAll t;
            for (int ty = 0; ty < 3; ty++) {
                t.X[ty] = pagg + (size_t)toff[ty] * CDIM;
                t.W[ty] = aw + (size_t)(l * 3 + ty) * CDIM * CDIM;
                t.B[ty] = ab + (size_t)(l * 3 + ty) * CDIM;
                t.skipP[ty] = skip + (l * 3 + ty);
                t.XO[ty] = px + (size_t)toff[ty] * CDIM;
            }
            dim3 grid(NBALL, 2);
            gemm_aproj_all<<<grid, 256>>>(t);
        }
    }

    // output projection + sigmoid
    {
        dim3 g(NBP, 2);
        gemm_bf3<0, 3><<<g, 256>>>(
            px, w_out, OUTD, b_out, out, OUTD, NPAT, OUTD, nullptr, nullptr);
    }
}

// round 11
// speedup vs baseline: 1.9055x; 1.0038x over previous
#include <cuda_runtime.h>
#include <math.h>
#include <stdint.h>

#define NPAT 50000
#define NICD 591
#define NNDC 2042
#define NTOTAL 52633
#define NSOFT 102633
#define CDIM 128
#define HH 8
#define DD 16
#define NEDGE 250000
#define OUTD 90

#define SOFF0 0
#define SOFF1 NICD
#define SOFF2 (NICD + NPAT)
#define SOFF3 (NICD + NPAT + NNDC)

#define NBP 391
#define NBI 5
#define NBN 16
#define NBALL (NBP + NBI + NBN)

#define RTP 1563
#define RTI 19
#define RTN 64
#define RTALL (RTP + RTI + RTN)

#define EPB 6250
#define EBLK (NICD + NNDC)
#define EALL (EPB + EBLK)

#define NWMAT 26   /* pre-split weight matrices */

// ---------------- scratch ----------------
__device__ float g_x[NTOTAL * CDIM];
__device__ float g_k[NTOTAL * CDIM];
__device__ float g_q[NTOTAL * CDIM];
__device__ float g_v[NTOTAL * CDIM];
__device__ float g_krP0[NPAT * CDIM];
__device__ float g_vrP0[NPAT * CDIM];
__device__ float g_krP1[NPAT * CDIM];
__device__ float g_vrP1[NPAT * CDIM];
__device__ float g_krI[NICD * CDIM];
__device__ float g_vrI[NICD * CDIM];
__device__ float g_krN[NNDC * CDIM];
__device__ float g_vrN[NNDC * CDIM];
// split (bf16 hi/lo packed pairs, kp = col/2)
__device__ uint32_t g_xh[NTOTAL * 64];
__device__ uint32_t g_xl[NTOTAL * 64];
__device__ uint32_t g_gh[NTOTAL * 64];   // split(gelu(agg)); reused for split(x_patient) pre-inproj
__device__ uint32_t g_gl[NTOTAL * 64];
__device__ uint32_t g_wh[NWMAT * 8192];
__device__ uint32_t g_wl[NWMAT * 8192];
// CSR
__device__ int g_cnt[NSOFT];
__device__ int g_off[NSOFT];
__device__ int g_cur[NSOFT];
__device__ int g_csr[4 * NEDGE];

__device__ __forceinline__ float geluf(float x) {
    float t = tanhf(0.7978845608028654f * (x + 0.044715f * x * x * x));
    return 0.5f * x * (1.0f + t);
}

__device__ __forceinline__ void split_pair(float v0, float v1, uint32_t& h, uint32_t& l) {
    uint32_t hh;
    asm("cvt.rn.bf16x2.f32 %0, %1, %2;" : "=r"(hh) : "f"(v1), "f"(v0));
    float h0 = __uint_as_float(hh << 16);
    float h1 = __uint_as_float(hh & 0xffff0000u);
    float l0 = v0 - h0;
    float l1 = v1 - h1;
    uint32_t ll;
    asm("cvt.rn.bf16x2.f32 %0, %1, %2;" : "=r"(ll) : "f"(l1), "f"(l0));
    h = hh; l = ll;
}

__device__ __forceinline__ void mma_bf16(float* c, const uint32_t* a, const uint32_t* b) {
    asm volatile("mma.sync.aligned.m16n8k16.row.col.f32.bf16.bf16.f32 "
                 "{%0,%1,%2,%3}, {%4,%5,%6,%7}, {%8,%9}, {%0,%1,%2,%3};"
                 : "+f"(c[0]), "+f"(c[1]), "+f"(c[2]), "+f"(c[3])
                 : "r"(a[0]), "r"(a[1]), "r"(a[2]), "r"(a[3]),
                   "r"(b[0]), "r"(b[1]));
}

// ---------------- pre-split weights ----------------
struct WSplit { const float* src[NWMAT]; int nn[NWMAT]; };
__global__ void split_weights(WSplit ws) {
    int m = blockIdx.y;
    int idx = blockIdx.x * 256 + threadIdx.x;   // 0..8191 (grid.x = 32)
    int kp = idx >> 7, n = idx & 127;
    const float* s = ws.src[m];
    int N = ws.nn[m];
    float v0 = (n < N) ? s[(size_t)(2 * kp) * N + n] : 0.0f;
    float v1 = (n < N) ? s[(size_t)(2 * kp + 1) * N + n] : 0.0f;
    uint32_t h, l;
    split_pair(v0, v1, h, l);
    g_wh[m * 8192 + idx] = h;
    g_wl[m * 8192 + idx] = l;
}

// ---------------- input prep: split(x_patient) + relu(embed)+split ----------------
__global__ void prep_inputs(const float* __restrict__ xp,
                            const float* __restrict__ ei, const int* __restrict__ xi,
                            const float* __restrict__ en, const int* __restrict__ xn) {
    int idx = blockIdx.x * 256 + threadIdx.x;
    const int n1 = NPAT * 64;
    const int n2 = n1 + NICD * 64;
    const int n3 = n2 + NNDC * 64;
    if (idx < n1) {
        int node = idx >> 6, kp = idx & 63;
        float2 v = *reinterpret_cast<const float2*>(&xp[(size_t)node * CDIM + 2 * kp]);
        uint32_t h, l;
        split_pair(v.x, v.y, h, l);
        g_gh[idx] = h; g_gl[idx] = l;
    } else if (idx < n3) {
        int j, node;
        const float* emb;
        const int* map;
        if (idx < n2) { j = idx - n1; emb = ei; map = xi; node = NPAT + (j >> 6); }
        else          { j = idx - n2; emb = en; map = xn; node = NPAT + NICD + (j >> 6); }
        int r = j >> 6, kp = j & 63;
        float2 v = *reinterpret_cast<const float2*>(&emb[(size_t)map[r] * CDIM + 2 * kp]);
        v.x = fmaxf(v.x, 0.0f);
        v.y = fmaxf(v.y, 0.0f);
        g_x[(size_t)node * CDIM + 2 * kp] = v.x;
        g_x[(size_t)node * CDIM + 2 * kp + 1] = v.y;
        uint32_t h, l;
        split_pair(v.x, v.y, h, l);
        g_xh[(size_t)node * 64 + kp] = h;
        g_xl[(size_t)node * 64 + kp] = l;
    }
}

// ---------------- GEMM body: 128(M) x 64(N) x 128(K), pre-split operands ----------------
// MODE: 0 plain fp32 out (kqv), 1 relu + split out (inproj),
//       2 skip-blend + split out (aproj), 3 sigmoid N=90 (out-proj)
template<int MODE>
__device__ __forceinline__ void gemm_body(
    const uint32_t* __restrict__ XH, const uint32_t* __restrict__ XL,
    const uint32_t* __restrict__ WH, const uint32_t* __restrict__ WL,
    const float* __restrict__ bias,
    float* __restrict__ OutF, int ldo,
    uint32_t* __restrict__ OutH, uint32_t* __restrict__ OutL,
    const float* __restrict__ skipPtr, const float* __restrict__ xold,
    int M, int row0, int ncol0)
{
    __shared__ uint32_t Ah[128][20];
    __shared__ uint32_t Al[128][20];
    __shared__ uint32_t Bh[16][72];
    __shared__ uint32_t Bl[16][72];

    const int tid = threadIdx.x;
    const int lane = tid & 31;
    const int wid = tid >> 5;
    const int warp_m = wid >> 1;
    const int warp_n = wid & 1;
    const int gi = lane >> 2;
    const int tig = lane & 3;

    float c[2][4][4];
#pragma unroll
    for (int am = 0; am < 2; am++)
#pragma unroll
        for (int an = 0; an < 4; an++)
#pragma unroll
            for (int j = 0; j < 4; j++) c[am][an][j] = 0.0f;

    const int ar = tid >> 1;
    const int akh = tid & 1;
    const bool aok = (row0 + ar) < M;
    const int bkp = tid >> 4;
    const int nl0 = (tid & 15) * 4;

    for (int kc2 = 0; kc2 < 64; kc2 += 16) {   // kp units, 4 chunks x 16 kp
        uint4 ha = make_uint4(0, 0, 0, 0), hb = ha, la = ha, lb = ha;
        if (aok) {
            const uint32_t* ph = &XH[(size_t)(row0 + ar) * 64 + kc2 + akh * 8];
            const uint32_t* pl = &XL[(size_t)(row0 + ar) * 64 + kc2 + akh * 8];
            ha = *reinterpret_cast<const uint4*>(ph);
            hb = *reinterpret_cast<const uint4*>(ph + 4);
            la = *reinterpret_cast<const uint4*>(pl);
            lb = *reinterpret_cast<const uint4*>(pl + 4);
        }
        *reinterpret_cast<uint4*>(&Ah[ar][akh * 8]) = ha;
        *reinterpret_cast<uint4*>(&Ah[ar][akh * 8 + 4]) = hb;
        *reinterpret_cast<uint4*>(&Al[ar][akh * 8]) = la;
        *reinterpret_cast<uint4*>(&Al[ar][akh * 8 + 4]) = lb;
        *reinterpret_cast<uint4*>(&Bh[bkp][nl0]) =
            *reinterpret_cast<const uint4*>(&WH[(size_t)(kc2 + bkp) * 128 + ncol0 + nl0]);
        *reinterpret_cast<uint4*>(&Bl[bkp][nl0]) =
            *reinterpret_cast<const uint4*>(&WL[(size_t)(kc2 + bkp) * 128 + ncol0 + nl0]);
        __syncthreads();

#pragma unroll
        for (int ks = 0; ks < 2; ks++) {
            const int kb = ks * 8;
            uint32_t ah[2][4], al[2][4];
#pragma unroll
            for (int am = 0; am < 2; am++) {
                int rb = warp_m * 32 + am * 16 + gi;
                ah[am][0] = Ah[rb][kb + tig];
                ah[am][1] = Ah[rb + 8][kb + tig];
                ah[am][2] = Ah[rb][kb + 4 + tig];
                ah[am][3] = Ah[rb + 8][kb + 4 + tig];
                al[am][0] = Al[rb][kb + tig];
                al[am][1] = Al[rb + 8][kb + tig];
                al[am][2] = Al[rb][kb + 4 + tig];
                al[am][3] = Al[rb + 8][kb + 4 + tig];
            }
#pragma unroll
            for (int an = 0; an < 4; an++) {
                int nc = warp_n * 32 + an * 8 + gi;
                uint32_t bh[2], bl[2];
                bh[0] = Bh[kb + tig][nc];
                bh[1] = Bh[kb + 4 + tig][nc];
                bl[0] = Bl[kb + tig][nc];
                bl[1] = Bl[kb + 4 + tig][nc];
#pragma unroll
                for (int am = 0; am < 2; am++) {
                    mma_bf16(c[am][an], ah[am], bh);
                    mma_bf16(c[am][an], al[am], bh);
                    mma_bf16(c[am][an], ah[am], bl);
                }
            }
        }
        __syncthreads();
    }

    float sa = 0.f, sb = 0.f;
    if (MODE == 2) {
        float s = 1.0f / (1.0f + __expf(-*skipPtr));
        sa = s; sb = 1.0f - s;
    }
#pragma unroll
    for (int am = 0; am < 2; am++) {
#pragma unroll
        for (int an = 0; an < 4; an++) {
            int col = ncol0 + warp_n * 32 + an * 8 + tig * 2;
#pragma unroll
            for (int half = 0; half < 2; half++) {
                int row = row0 + warp_m * 32 + am * 16 + gi + half * 8;
                if (row >= M) continue;
                float b0 = (MODE == 3) ? ((col < OUTD) ? bias[col] : 0.0f) : bias[col];
                float b1 = (MODE == 3) ? ((col + 1 < OUTD) ? bias[col + 1] : 0.0f) : bias[col + 1];
                float v0 = c[am][an][half * 2 + 0] + b0;
                float v1 = c[am][an][half * 2 + 1] + b1;
                if (MODE == 1) { v0 = fmaxf(v0, 0.0f); v1 = fmaxf(v1, 0.0f); }
                else if (MODE == 2) {
                    v0 = sa * v0 + sb * xold[(size_t)row * CDIM + col];
                    v1 = sa * v1 + sb * xold[(size_t)row * CDIM + col + 1];
                } else if (MODE == 3) {
                    v0 = 1.0f / (1.0f + __expf(-v0));
                    v1 = 1.0f / (1.0f + __expf(-v1));
                }
                if (MODE == 3) {
                    if (col < OUTD)     OutF[(size_t)row * ldo + col] = v0;
                    if (col + 1 < OUTD) OutF[(size_t)row * ldo + col + 1] = v1;
                } else {
                    OutF[(size_t)row * CDIM + col] = v0;
                    OutF[(size_t)row * CDIM + col + 1] = v1;
                    if (MODE == 1 || MODE == 2) {
                        uint32_t h, l;
                        split_pair(v0, v1, h, l);
                        OutH[(size_t)row * 64 + (col >> 1)] = h;
                        OutL[(size_t)row * 64 + (col >> 1)] = l;
                    }
                }
            }
        }
    }
}

// ---------------- GEMM wrappers ----------------
__global__ __launch_bounds__(256, 4) void gemm_in(const float* __restrict__ bias)
{
    gemm_body<1>(g_gh, g_gl, g_wh, g_wl, bias,
                 g_x, CDIM, g_xh, g_xl, nullptr, nullptr,
                 NPAT, blockIdx.x * 128, blockIdx.y * 64);
}

__global__ __launch_bounds__(256, 4) void gemm_kqv(
    const float* __restrict__ kb, const float* __restrict__ qb,
    const float* __restrict__ vb, int l)
{
    const int bx = blockIdx.x;
    int ty, bl;
    if (bx < NBP)            { ty = 0; bl = bx; }
    else if (bx < NBP + NBI) { ty = 1; bl = bx - NBP; }
    else                     { ty = 2; bl = bx - NBP - NBI; }
    const int M = (ty == 0) ? NPAT : (ty == 1) ? NICD : NNDC;
    const int toff = (ty == 0) ? 0 : (ty == 1) ? NPAT : NPAT + NICD;
    const int j = blockIdx.y;
    const int widx = 1 + l * 9 + j * 3 + ty;
    const float* bias = ((j == 0) ? kb : (j == 1) ? qb : vb) + (size_t)(l * 3 + ty) * CDIM;
    float* outp = ((j == 0) ? g_k : (j == 1) ? g_q : g_v) + (size_t)toff * CDIM;
    gemm_body<0>(g_xh + (size_t)toff * 64, g_xl + (size_t)toff * 64,
                 g_wh + (size_t)widx * 8192, g_wl + (size_t)widx * 8192, bias,
                 outp, CDIM, nullptr, nullptr, nullptr, nullptr,
                 M, bl * 128, blockIdx.z * 64);
}

__global__ __launch_bounds__(256, 4) void gemm_ap(
    const float* __restrict__ ab, const float* __restrict__ skip, int l)
{
    const int bx = blockIdx.x;
    int ty, bl;
    if (bx < NBP)            { ty = 0; bl = bx; }
    else if (bx < NBP + NBI) { ty = 1; bl = bx - NBP; }
    else                     { ty = 2; bl = bx - NBP - NBI; }
    const int M = (ty == 0) ? NPAT : (ty == 1) ? NICD : NNDC;
    const int toff = (ty == 0) ? 0 : (ty == 1) ? NPAT : NPAT + NICD;
    const int widx = 19 + l * 3 + ty;
    gemm_body<2>(g_gh + (size_t)toff * 64, g_gl + (size_t)toff * 64,
                 g_wh + (size_t)widx * 8192, g_wl + (size_t)widx * 8192,
                 ab + (size_t)(l * 3 + ty) * CDIM,
                 g_x + (size_t)toff * CDIM, CDIM,
                 g_xh + (size_t)toff * 64, g_xl + (size_t)toff * 64,
                 skip + (l * 3 + ty), g_x + (size_t)toff * CDIM,
                 M, bl * 128, blockIdx.y * 64);
}

__global__ __launch_bounds__(256, 4) void gemm_o(
    const float* __restrict__ bias, float* __restrict__ out)
{
    gemm_body<3>(g_xh, g_xl, g_wh + (size_t)25 * 8192, g_wl + (size_t)25 * 8192, bias,
                 out, OUTD, nullptr, nullptr, nullptr, nullptr,
                 NPAT, blockIdx.x * 128, blockIdx.y * 64);
}

// ---------------- CSR build ----------------
__global__ void csr_clear() {
    int i = blockIdx.x * blockDim.x + threadIdx.x;
    if (i < NSOFT) { g_cnt[i] = 0; g_cur[i] = 0; }
}

__global__ void csr_hist_pat(const int* __restrict__ d1, const int* __restrict__ d3) {
    int i = blockIdx.x * blockDim.x + threadIdx.x;
    if (i < NEDGE / 4) {
        int4 a = reinterpret_cast<const int4*>(d1)[i];
        atomicAdd(&g_cnt[SOFF1 + a.x], 1);
        atomicAdd(&g_cnt[SOFF1 + a.y], 1);
        atomicAdd(&g_cnt[SOFF1 + a.z], 1);
        atomicAdd(&g_cnt[SOFF1 + a.w], 1);
        int4 b = reinterpret_cast<const int4*>(d3)[i];
        atomicAdd(&g_cnt[SOFF3 + b.x], 1);
        atomicAdd(&g_cnt[SOFF3 + b.y], 1);
        atomicAdd(&g_cnt[SOFF3 + b.z], 1);
        atomicAdd(&g_cnt[SOFF3 + b.w], 1);
    }
}

__global__ __launch_bounds__(256) void csr_hist_sm(const int* __restrict__ dst0,
                                                   const int* __restrict__ dst2) {
    __shared__ int h[NNDC];
    const int r = blockIdx.y;
    const int ndst = r ? NNDC : NICD;
    const int so = r ? SOFF2 : SOFF0;
    const int* __restrict__ dst = r ? dst2 : dst0;
    for (int i = threadIdx.x; i < ndst; i += 256) h[i] = 0;
    __syncthreads();
    const int tot = NEDGE / 4;
    for (int i = blockIdx.x * 256 + threadIdx.x; i < tot; i += gridDim.x * 256) {
        int4 a = reinterpret_cast<const int4*>(dst)[i];
        atomicAdd(&h[a.x], 1); atomicAdd(&h[a.y], 1);
        atomicAdd(&h[a.z], 1); atomicAdd(&h[a.w], 1);
    }
    __syncthreads();
    for (int i = threadIdx.x; i < ndst; i += 256)
        if (h[i]) atomicAdd(&g_cnt[so + i], h[i]);
}

__global__ __launch_bounds__(1024) void csr_scan() {
    __shared__ int partial[1024];
    const int CH = (NSOFT + 1023) / 1024;
    int t = threadIdx.x;
    int s0 = t * CH;
    int s1 = s0 + CH; if (s1 > NSOFT) s1 = NSOFT;
    int sum = 0;
    for (int i = s0; i < s1; i++) sum += g_cnt[i];
    partial[t] = sum;
    __syncthreads();
    for (int d = 1; d < 1024; d <<= 1) {
        int v = (t >= d) ? partial[t - d] : 0;
        __syncthreads();
        partial[t] += v;
        __syncthreads();
    }
    int pre = (t == 0) ? 0 : partial[t - 1];
    for (int i = s0; i < s1; i++) { g_off[i] = pre; pre += g_cnt[i]; }
}

__global__ void csr_scatter_pat(const int* __restrict__ s1, const int* __restrict__ d1,
                                const int* __restrict__ s3, const int* __restrict__ d3) {
    int i = blockIdx.x * blockDim.x + threadIdx.x;
    if (i < NEDGE) {
        int b1 = SOFF1 + d1[i];
        g_csr[g_off[b1] + atomicAdd(&g_cur[b1], 1)] = s1[i];
        int b3 = SOFF3 + d3[i];
        g_csr[g_off[b3] + atomicAdd(&g_cur[b3], 1)] = s3[i];
    }
}

__global__ __launch_bounds__(256) void csr_scatter_sm(
    const int* __restrict__ src0, const int* __restrict__ dst0,
    const int* __restrict__ src2, const int* __restrict__ dst2) {
    __shared__ int h[NNDC];
    __shared__ int base[NNDC];
    const int r = blockIdx.y;
    const int ndst = r ? NNDC : NICD;
    const int so = r ? SOFF2 : SOFF0;
    const int* __restrict__ dst = r ? dst2 : dst0;
    const int* __restrict__ src = r ? src2 : src0;
    const int chunk = (NEDGE + gridDim.x - 1) / gridDim.x;
    const int e0 = blockIdx.x * chunk;
    int e1 = e0 + chunk; if (e1 > NEDGE) e1 = NEDGE;

    for (int i = threadIdx.x; i < ndst; i += 256) h[i] = 0;
    __syncthreads();
    for (int e = e0 + threadIdx.x; e < e1; e += 256) atomicAdd(&h[dst[e]], 1);
    __syncthreads();
    for (int i = threadIdx.x; i < ndst; i += 256) {
        int cc = h[i];
        base[i] = cc ? atomicAdd(&g_cur[so + i], cc) : 0;
    }
    __syncthreads();
    for (int i = threadIdx.x; i < ndst; i += 256) h[i] = 0;
    __syncthreads();
    for (int e = e0 + threadIdx.x; e < e1; e += 256) {
        int d = dst[e];
        int loc = atomicAdd(&h[d], 1);
        g_csr[g_off[so + d] + base[d] + loc] = src[e];
    }
}

// ---------------- fused edge kernel: softmax+agg, emits split(gelu(agg)) ----------------
__global__ __launch_bounds__(256) void edge_fused(const float* __restrict__ prel)
{
    __shared__ float sacc[8][128];
    __shared__ float ses[8][8];
    const int b = blockIdx.x;
    const int tid = threadIdx.x;
    const int w = tid >> 5;
    const int lane = tid & 31;
    const int h = lane >> 2;

    if (b < EPB) {
        int d = b * 8 + w;
        float4 qv = *reinterpret_cast<const float4*>(&g_q[(size_t)d * CDIM + lane * 4]);
        float ax = 0.f, ay = 0.f, az = 0.f, aw2 = 0.f;
#pragma unroll
        for (int rr = 0; rr < 2; rr++) {
            const int rel = rr ? 3 : 1;
            const float* krb = rr ? g_krN : g_krI;
            const float* vrb = rr ? g_vrN : g_vrI;
            int base = (rr ? SOFF3 : SOFF1) + d;
            int st = g_off[base], n = g_cnt[base];
            float pf = prel[rel * 8 + h] * 0.25f;
            float es = 0.f, a0 = 0.f, a1 = 0.f, a2 = 0.f, a3 = 0.f;
            for (int i = 0; i < n; i++) {
                int s = g_csr[st + i];
                float4 kv = *reinterpret_cast<const float4*>(&krb[(size_t)s * CDIM + lane * 4]);
                float dot = qv.x * kv.x + qv.y * kv.y + qv.z * kv.z + qv.w * kv.w;
                dot += __shfl_xor_sync(0xffffffff, dot, 1);
                dot += __shfl_xor_sync(0xffffffff, dot, 2);
                float e = __expf(dot * pf);
                float4 vv = *reinterpret_cast<const float4*>(&vrb[(size_t)s * CDIM + lane * 4]);
                es += e;
                a0 += e * vv.x; a1 += e * vv.y; a2 += e * vv.z; a3 += e * vv.w;
            }
            if (n > 0) {
                float inv = 1.0f / es;
                ax += a0 * inv; ay += a1 * inv; az += a2 * inv; aw2 += a3 * inv;
            }
        }
        // gelu + split; cols lane*4..lane*4+3 -> kp lane*2, lane*2+1
        float v0 = geluf(ax), v1 = geluf(ay), v2 = geluf(az), v3 = geluf(aw2);
        uint32_t h0, l0, h1, l1;
        split_pair(v0, v1, h0, l0);
        split_pair(v2, v3, h1, l1);
        *reinterpret_cast<uint2*>(&g_gh[(size_t)d * 64 + lane * 2]) = make_uint2(h0, h1);
        *reinterpret_cast<uint2*>(&g_gl[(size_t)d * 64 + lane * 2]) = make_uint2(l0, l1);
    } else {
        int bb = b - EPB;
        int base;
        size_t nodeoff;
        const float *krb, *vrb;
        float pf;
        if (bb < NICD) {
            base = SOFF0 + bb;
            nodeoff = (size_t)(NPAT + bb);
            krb = g_krP0; vrb = g_vrP0;
            pf = prel[0 * 8 + h] * 0.25f;
        } else {
            int d = bb - NICD;
            base = SOFF2 + d;
            nodeoff = (size_t)(NPAT + NICD + d);
            krb = g_krP1; vrb = g_vrP1;
            pf = prel[2 * 8 + h] * 0.25f;
        }
        float4 qv = *reinterpret_cast<const float4*>(&g_q[nodeoff * CDIM + lane * 4]);
        int st = g_off[base], n = g_cnt[base];
        float es = 0.f, a0 = 0.f, a1 = 0.f, a2 = 0.f, a3 = 0.f;
        for (int i = w; i < n; i += 8) {
            int s = g_csr[st + i];
            float4 kv = *reinterpret_cast<const float4*>(&krb[(size_t)s * CDIM + lane * 4]);
            float dot = qv.x * kv.x + qv.y * kv.y + qv.z * kv.z + qv.w * kv.w;
            dot += __shfl_xor_sync(0xffffffff, dot, 1);
            dot += __shfl_xor_sync(0xffffffff, dot, 2);
            float e = __expf(dot * pf);
            float4 vv = *reinterpret_cast<const float4*>(&vrb[(size_t)s * CDIM + lane * 4]);
            es += e;
            a0 += e * vv.x; a1 += e * vv.y; a2 += e * vv.z; a3 += e * vv.w;
        }
        *reinterpret_cast<float4*>(&sacc[w][lane * 4]) = make_float4(a0, a1, a2, a3);
        if ((lane & 3) == 0) ses[w][h] = es;
        __syncthreads();
        if (tid < 64) {
            int col0 = 2 * tid;
            float s0 = 0.f, s1 = 0.f, e = 0.f;
#pragma unroll
            for (int ww = 0; ww < 8; ww++) {
                s0 += sacc[ww][col0];
                s1 += sacc[ww][col0 + 1];
                e  += ses[ww][tid >> 3];
            }
            float v0 = (e > 0.f) ? s0 / e : 0.0f;
            float v1 = (e > 0.f) ? s1 / e : 0.0f;
            v0 = geluf(v0); v1 = geluf(v1);
            uint32_t hh, ll;
            split_pair(v0, v1, hh, ll);
            g_gh[nodeoff * 64 + tid] = hh;
            g_gl[nodeoff * 64 + tid] = ll;
        }
    }
}

// ---------------- merged per-relation K/V transform ----------------
struct ReltAll {
    const float* A[4];
    const float* Mw[4];
};
__global__ __launch_bounds__(128) void relt_all(ReltAll ra)
{
    __shared__ float ks[32][128];
    __shared__ float vs[32][128];
    const int tid = threadIdx.x;
    const int bx = blockIdx.x;
    const int h = tid >> 4;
    const int e = tid & 15;

    int node0, nsrc, srcoff;
    const float *A0, *M0, *A1, *M1;
    float *kr0, *vr0, *kr1, *vr1;
    bool two;
    if (bx < RTP) {
        node0 = bx * 32; nsrc = NPAT; srcoff = 0; two = true;
        A0 = ra.A[0]; M0 = ra.Mw[0]; A1 = ra.A[2]; M1 = ra.Mw[2];
        kr0 = g_krP0; vr0 = g_vrP0; kr1 = g_krP1; vr1 = g_vrP1;
    } else if (bx < RTP + RTI) {
        node0 = (bx - RTP) * 32; nsrc = NICD; srcoff = NPAT; two = false;
        A0 = ra.A[1]; M0 = ra.Mw[1]; A1 = nullptr; M1 = nullptr;
        kr0 = g_krI; vr0 = g_vrI; kr1 = nullptr; vr1 = nullptr;
    } else {
        node0 = (bx - RTP - RTI) * 32; nsrc = NNDC; srcoff = NPAT + NICD; two = false;
        A0 = ra.A[3]; M0 = ra.Mw[3]; A1 = nullptr; M1 = nullptr;
        kr0 = g_krN; vr0 = g_vrN; kr1 = nullptr; vr1 = nullptr;
    }

    float areg0[16], mreg0[16], areg1[16], mreg1[16];
#pragma unroll
    for (int d = 0; d < 16; d++) {
        areg0[d] = A0[(h * 16 + d) * 16 + e];
        mreg0[d] = M0[(h * 16 + d) * 16 + e];
        if (two) {
            areg1[d] = A1[(h * 16 + d) * 16 + e];
            mreg1[d] = M1[(h * 16 + d) * 16 + e];
        }
    }

    const float* kbase = g_k + (size_t)srcoff * CDIM;
    const float* vbase = g_v + (size_t)srcoff * CDIM;
    for (int i = tid; i < 32 * 32; i += 128) {
        int r = i >> 5;
        int cidx = (i & 31) * 4;
        if (node0 + r < nsrc) {
            *reinterpret_cast<float4*>(&ks[r][cidx]) =
                *reinterpret_cast<const float4*>(&kbase[(size_t)(node0 + r) * CDIM + cidx]);
            *reinterpret_cast<float4*>(&vs[r][cidx]) =
                *reinterpret_cast<const float4*>(&vbase[(size_t)(node0 + r) * CDIM + cidx]);
        }
    }
    __syncthreads();

    int nmax = nsrc - node0; if (nmax > 32) nmax = 32;
    for (int n = 0; n < nmax; n++) {
        float acck0 = 0.f, accv0 = 0.f, acck1 = 0.f, accv1 = 0.f;
#pragma unroll
        for (int d4 = 0; d4 < 4; d4++) {
            float4 kq = *reinterpret_cast<const float4*>(&ks[n][h * 16 + d4 * 4]);
            float4 vq = *reinterpret_cast<const float4*>(&vs[n][h * 16 + d4 * 4]);
            float kk[4] = {kq.x, kq.y, kq.z, kq.w};
            float vv[4] = {vq.x, vq.y, vq.z, vq.w};
#pragma unroll
            for (int j = 0; j < 4; j++) {
                int d = d4 * 4 + j;
                acck0 = fmaf(kk[j], areg0[d], acck0);
                accv0 = fmaf(vv[j], mreg0[d], accv0);
                if (two) {
                    acck1 = fmaf(kk[j], areg1[d], acck1);
                    accv1 = fmaf(vv[j], mreg1[d], accv1);
                }
            }
        }
        size_t o = (size_t)(node0 + n) * CDIM + h * 16 + e;
        kr0[o] = acck0; vr0[o] = accv0;
        if (two) { kr1[o] = acck1; vr1[o] = accv1; }
    }
}

// ---------------- host ----------------
extern "C" void kernel_launch(void* const* d_in, const int* in_sizes, int n_in,
                              void* d_out, int out_size)
{
    const float* x_patient = (const float*)d_in[0];
    const float* w_in      = (const float*)d_in[1];
    const float* b_in      = (const float*)d_in[2];
    const float* emb_icd   = (const float*)d_in[3];
    const float* emb_ndc   = (const float*)d_in[4];
    const float* kw = (const float*)d_in[5];
    const float* kb = (const float*)d_in[6];
    const float* qw = (const float*)d_in[7];
    const float* qb = (const float*)d_in[8];
    const float* vw = (const float*)d_in[9];
    const float* vb = (const float*)d_in[10];
    const float* aw = (const float*)d_in[11];
    const float* ab = (const float*)d_in[12];
    const float* skip  = (const float*)d_in[13];
    const float* a_rel = (const float*)d_in[14];
    const float* m_rel = (const float*)d_in[15];
    const float* p_rel = (const float*)d_in[16];
    const float* w_out = (const float*)d_in[17];
    const float* b_out = (const float*)d_in[18];
    const int* x_icd = (const int*)d_in[19];
    const int* x_ndc = (const int*)d_in[20];
    const int* esrc[4] = {(const int*)d_in[21], (const int*)d_in[23],
                          (const int*)d_in[25], (const int*)d_in[27]};
    const int* edst[4] = {(const int*)d_in[22], (const int*)d_in[24],
                          (const int*)d_in[26], (const int*)d_in[28]};
    float* out = (float*)d_out;

    // 1: weight pre-split
    {
        WSplit ws;
        ws.src[0] = w_in; ws.nn[0] = CDIM;
        const float* wsrc[3] = {kw, qw, vw};
        for (int l = 0; l < 2; l++)
            for (int j = 0; j < 3; j++)
                for (int ty = 0; ty < 3; ty++) {
                    ws.src[1 + l * 9 + j * 3 + ty] = wsrc[j] + (size_t)(l * 3 + ty) * CDIM * CDIM;
                    ws.nn[1 + l * 9 + j * 3 + ty] = CDIM;
                }
        for (int l = 0; l < 2; l++)
            for (int ty = 0; ty < 3; ty++) {
                ws.src[19 + l * 3 + ty] = aw + (size_t)(l * 3 + ty) * CDIM * CDIM;
                ws.nn[19 + l * 3 + ty] = CDIM;
            }
        ws.src[25] = w_out; ws.nn[25] = OUTD;
        dim3 g(32, NWMAT);
        split_weights<<<g, 256>>>(ws);
    }
    // 2: input prep (split x_patient + embed relu + split)
    prep_inputs<<<(NTOTAL * 64 + 255) / 256, 256>>>(x_patient, emb_icd, x_icd, emb_ndc, x_ndc);
    // 3: input projection
    {
        dim3 g(NBP, 2);
        gemm_in<<<g, 256>>>(b_in);
    }

    for (int l = 0; l < 2; l++) {
        // 4 (layer 0): merged K/Q/V GEMM — profiled slot
        {
            dim3 grid(NBALL, 3, 2);
            gemm_kqv<<<grid, 256>>>(kb, qb, vb, l);
        }

        if (l == 0) {
            csr_clear<<<(NSOFT + 255) / 256, 256>>>();
            csr_hist_pat<<<(NEDGE / 4 + 255) / 256, 256>>>(edst[1], edst[3]);
            dim3 gh(48, 2);
            csr_hist_sm<<<gh, 256>>>(edst[0], edst[2]);
            csr_scan<<<1, 1024>>>();
            csr_scatter_pat<<<(NEDGE + 255) / 256, 256>>>(esrc[1], edst[1], esrc[3], edst[3]);
            dim3 gs(64, 2);
            csr_scatter_sm<<<gs, 256>>>(esrc[0], edst[0], esrc[2], edst[2]);
        }

        // merged relation K/V transforms
        {
            ReltAll ra;
            for (int r = 0; r < 4; r++) {
                ra.A[r]  = a_rel + (size_t)(l * 4 + r) * HH * DD * DD;
                ra.Mw[r] = m_rel + (size_t)(l * 4 + r) * HH * DD * DD;
            }
            relt_all<<<RTALL, 128>>>(ra);
        }

        // fused edge phase (emits split(gelu(agg)))
        edge_fused<<<EALL, 256>>>(p_rel + l * 32);

        // merged A-proj GEMM (skip blend; gelu already applied in edge_fused)
        {
            dim3 grid(NBALL, 2);
            gemm_ap<<<grid, 256>>>(ab, skip, l);
        }
    }

    // output projection + sigmoid
    {
        dim3 g(NBP, 2);
        gemm_o<<<g, 256>>>(b_out, out);
    }
}

// round 12
// speedup vs baseline: 1.9318x; 1.0138x over previous
#include <cuda_runtime.h>
#include <math.h>
#include <stdint.h>

#define NPAT 50000
#define NICD 591
#define NNDC 2042
#define NTOTAL 52633
#define NSOFT 102633
#define CDIM 128
#define HH 8
#define DD 16
#define NEDGE 250000
#define OUTD 90

#define SOFF0 0
#define SOFF1 NICD
#define SOFF2 (NICD + NPAT)
#define SOFF3 (NICD + NPAT + NNDC)

#define NBP 391
#define NBI 5
#define NBN 16
#define NBALL (NBP + NBI + NBN)

#define RTP 1563
#define RTI 19
#define RTN 64
#define RTALL (RTP + RTI + RTN)

#define EPB 6250
#define EBLK (NICD + NNDC)
#define EALL (EPB + EBLK)

#define NWMAT 26

// ---------------- scratch ----------------
__device__ float g_x[NTOTAL * CDIM];
__device__ float g_k[NTOTAL * CDIM];
__device__ float g_q[NTOTAL * CDIM];
__device__ float g_v[NTOTAL * CDIM];
__device__ float g_krP0[NPAT * CDIM];
__device__ float g_vrP0[NPAT * CDIM];
__device__ float g_krP1[NPAT * CDIM];
__device__ float g_vrP1[NPAT * CDIM];
__device__ float g_krI[NICD * CDIM];
__device__ float g_vrI[NICD * CDIM];
__device__ float g_krN[NNDC * CDIM];
__device__ float g_vrN[NNDC * CDIM];
__device__ uint32_t g_xh[NTOTAL * 64];
__device__ uint32_t g_xl[NTOTAL * 64];
__device__ uint32_t g_gh[NTOTAL * 64];
__device__ uint32_t g_gl[NTOTAL * 64];
__device__ uint32_t g_wh[NWMAT * 8192];
__device__ uint32_t g_wl[NWMAT * 8192];
__device__ int g_cnt[NSOFT];
__device__ int g_off[NSOFT];
__device__ int g_cur[NSOFT];
__device__ int g_csr[4 * NEDGE];

__device__ __forceinline__ float geluf(float x) {
    float t = tanhf(0.7978845608028654f * (x + 0.044715f * x * x * x));
    return 0.5f * x * (1.0f + t);
}

__device__ __forceinline__ void split_pair(float v0, float v1, uint32_t& h, uint32_t& l) {
    uint32_t hh;
    asm("cvt.rn.bf16x2.f32 %0, %1, %2;" : "=r"(hh) : "f"(v1), "f"(v0));
    float h0 = __uint_as_float(hh << 16);
    float h1 = __uint_as_float(hh & 0xffff0000u);
    float l0 = v0 - h0;
    float l1 = v1 - h1;
    uint32_t ll;
    asm("cvt.rn.bf16x2.f32 %0, %1, %2;" : "=r"(ll) : "f"(l1), "f"(l0));
    h = hh; l = ll;
}

__device__ __forceinline__ void mma_bf16(float* c, const uint32_t* a, const uint32_t* b) {
    asm volatile("mma.sync.aligned.m16n8k16.row.col.f32.bf16.bf16.f32 "
                 "{%0,%1,%2,%3}, {%4,%5,%6,%7}, {%8,%9}, {%0,%1,%2,%3};"
                 : "+f"(c[0]), "+f"(c[1]), "+f"(c[2]), "+f"(c[3])
                 : "r"(a[0]), "r"(a[1]), "r"(a[2]), "r"(a[3]),
                   "r"(b[0]), "r"(b[1]));
}

// ---------------- pre-split weights ----------------
struct WSplit { const float* src[NWMAT]; int nn[NWMAT]; };
__global__ void split_weights(WSplit ws) {
    int m = blockIdx.y;
    int idx = blockIdx.x * 256 + threadIdx.x;
    int kp = idx >> 7, n = idx & 127;
    const float* s = ws.src[m];
    int N = ws.nn[m];
    float v0 = (n < N) ? s[(size_t)(2 * kp) * N + n] : 0.0f;
    float v1 = (n < N) ? s[(size_t)(2 * kp + 1) * N + n] : 0.0f;
    uint32_t h, l;
    split_pair(v0, v1, h, l);
    g_wh[m * 8192 + idx] = h;
    g_wl[m * 8192 + idx] = l;
}

// ---------------- input prep ----------------
__global__ void prep_inputs(const float* __restrict__ xp,
                            const float* __restrict__ ei, const int* __restrict__ xi,
                            const float* __restrict__ en, const int* __restrict__ xn) {
    int idx = blockIdx.x * 256 + threadIdx.x;
    const int n1 = NPAT * 64;
    const int n2 = n1 + NICD * 64;
    const int n3 = n2 + NNDC * 64;
    if (idx < n1) {
        int node = idx >> 6, kp = idx & 63;
        float2 v = *reinterpret_cast<const float2*>(&xp[(size_t)node * CDIM + 2 * kp]);
        uint32_t h, l;
        split_pair(v.x, v.y, h, l);
        g_gh[idx] = h; g_gl[idx] = l;
    } else if (idx < n3) {
        int j, node;
        const float* emb;
        const int* map;
        if (idx < n2) { j = idx - n1; emb = ei; map = xi; node = NPAT + (j >> 6); }
        else          { j = idx - n2; emb = en; map = xn; node = NPAT + NICD + (j >> 6); }
        int r = j >> 6, kp = j & 63;
        float2 v = *reinterpret_cast<const float2*>(&emb[(size_t)map[r] * CDIM + 2 * kp]);
        v.x = fmaxf(v.x, 0.0f);
        v.y = fmaxf(v.y, 0.0f);
        g_x[(size_t)node * CDIM + 2 * kp] = v.x;
        g_x[(size_t)node * CDIM + 2 * kp + 1] = v.y;
        uint32_t h, l;
        split_pair(v.x, v.y, h, l);
        g_xh[(size_t)node * 64 + kp] = h;
        g_xl[(size_t)node * 64 + kp] = l;
    }
}

// ---------------- GEMM body (pre-split operands) ----------------
// MODE: 0 plain fp32 (kqv), 1 relu+split (inproj), 2 blend+split (aproj), 3 sigmoid N=90
template<int MODE>
__device__ __forceinline__ void gemm_body(
    const uint32_t* __restrict__ XH, const uint32_t* __restrict__ XL,
    const uint32_t* __restrict__ WH, const uint32_t* __restrict__ WL,
    const float* __restrict__ bias,
    float* __restrict__ OutF, int ldo,
    uint32_t* __restrict__ OutH, uint32_t* __restrict__ OutL,
    const float* __restrict__ skipPtr, const float* __restrict__ xold,
    int M, int row0, int ncol0)
{
    __shared__ uint32_t Ah[128][20];
    __shared__ uint32_t Al[128][20];
    __shared__ uint32_t Bh[16][72];
    __shared__ uint32_t Bl[16][72];

    const int tid = threadIdx.x;
    const int lane = tid & 31;
    const int wid = tid >> 5;
    const int warp_m = wid >> 1;
    const int warp_n = wid & 1;
    const int gi = lane >> 2;
    const int tig = lane & 3;

    float c[2][4][4];
#pragma unroll
    for (int am = 0; am < 2; am++)
#pragma unroll
        for (int an = 0; an < 4; an++)
#pragma unroll
            for (int j = 0; j < 4; j++) c[am][an][j] = 0.0f;

    const int ar = tid >> 1;
    const int akh = tid & 1;
    const bool aok = (row0 + ar) < M;
    const int bkp = tid >> 4;
    const int nl0 = (tid & 15) * 4;

    for (int kc2 = 0; kc2 < 64; kc2 += 16) {
        uint4 ha = make_uint4(0, 0, 0, 0), hb = ha, la = ha, lb = ha;
        if (aok) {
            const uint32_t* ph = &XH[(size_t)(row0 + ar) * 64 + kc2 + akh * 8];
            const uint32_t* pl = &XL[(size_t)(row0 + ar) * 64 + kc2 + akh * 8];
            ha = *reinterpret_cast<const uint4*>(ph);
            hb = *reinterpret_cast<const uint4*>(ph + 4);
            la = *reinterpret_cast<const uint4*>(pl);
            lb = *reinterpret_cast<const uint4*>(pl + 4);
        }
        *reinterpret_cast<uint4*>(&Ah[ar][akh * 8]) = ha;
        *reinterpret_cast<uint4*>(&Ah[ar][akh * 8 + 4]) = hb;
        *reinterpret_cast<uint4*>(&Al[ar][akh * 8]) = la;
        *reinterpret_cast<uint4*>(&Al[ar][akh * 8 + 4]) = lb;
        *reinterpret_cast<uint4*>(&Bh[bkp][nl0]) =
            *reinterpret_cast<const uint4*>(&WH[(size_t)(kc2 + bkp) * 128 + ncol0 + nl0]);
        *reinterpret_cast<uint4*>(&Bl[bkp][nl0]) =
            *reinterpret_cast<const uint4*>(&WL[(size_t)(kc2 + bkp) * 128 + ncol0 + nl0]);
        __syncthreads();

#pragma unroll
        for (int ks = 0; ks < 2; ks++) {
            const int kb = ks * 8;
            uint32_t ah[2][4], al[2][4];
#pragma unroll
            for (int am = 0; am < 2; am++) {
                int rb = warp_m * 32 + am * 16 + gi;
                ah[am][0] = Ah[rb][kb + tig];
                ah[am][1] = Ah[rb + 8][kb + tig];
                ah[am][2] = Ah[rb][kb + 4 + tig];
                ah[am][3] = Ah[rb + 8][kb + 4 + tig];
                al[am][0] = Al[rb][kb + tig];
                al[am][1] = Al[rb + 8][kb + tig];
                al[am][2] = Al[rb][kb + 4 + tig];
                al[am][3] = Al[rb + 8][kb + 4 + tig];
            }
#pragma unroll
            for (int an = 0; an < 4; an++) {
                int nc = warp_n * 32 + an * 8 + gi;
                uint32_t bh[2], bl[2];
                bh[0] = Bh[kb + tig][nc];
                bh[1] = Bh[kb + 4 + tig][nc];
                bl[0] = Bl[kb + tig][nc];
                bl[1] = Bl[kb + 4 + tig][nc];
#pragma unroll
                for (int am = 0; am < 2; am++) {
                    mma_bf16(c[am][an], ah[am], bh);
                    mma_bf16(c[am][an], al[am], bh);
                    mma_bf16(c[am][an], ah[am], bl);
                }
            }
        }
        __syncthreads();
    }

    float sa = 0.f, sb = 0.f;
    if (MODE == 2) {
        float s = 1.0f / (1.0f + __expf(-*skipPtr));
        sa = s; sb = 1.0f - s;
    }
#pragma unroll
    for (int am = 0; am < 2; am++) {
#pragma unroll
        for (int an = 0; an < 4; an++) {
            int col = ncol0 + warp_n * 32 + an * 8 + tig * 2;
#pragma unroll
            for (int half = 0; half < 2; half++) {
                int row = row0 + warp_m * 32 + am * 16 + gi + half * 8;
                if (row >= M) continue;
                float b0 = (MODE == 3) ? ((col < OUTD) ? bias[col] : 0.0f) : bias[col];
                float b1 = (MODE == 3) ? ((col + 1 < OUTD) ? bias[col + 1] : 0.0f) : bias[col + 1];
                float v0 = c[am][an][half * 2 + 0] + b0;
                float v1 = c[am][an][half * 2 + 1] + b1;
                if (MODE == 1) { v0 = fmaxf(v0, 0.0f); v1 = fmaxf(v1, 0.0f); }
                else if (MODE == 2) {
                    v0 = sa * v0 + sb * xold[(size_t)row * CDIM + col];
                    v1 = sa * v1 + sb * xold[(size_t)row * CDIM + col + 1];
                } else if (MODE == 3) {
                    v0 = 1.0f / (1.0f + __expf(-v0));
                    v1 = 1.0f / (1.0f + __expf(-v1));
                }
                if (MODE == 3) {
                    if (col < OUTD)     OutF[(size_t)row * ldo + col] = v0;
                    if (col + 1 < OUTD) OutF[(size_t)row * ldo + col + 1] = v1;
                } else {
                    OutF[(size_t)row * CDIM + col] = v0;
                    OutF[(size_t)row * CDIM + col + 1] = v1;
                    if (MODE == 1 || MODE == 2) {
                        uint32_t h, l;
                        split_pair(v0, v1, h, l);
                        OutH[(size_t)row * 64 + (col >> 1)] = h;
                        OutL[(size_t)row * 64 + (col >> 1)] = l;
                    }
                }
            }
        }
    }
}

// ---------------- GEMM wrappers ----------------
__global__ __launch_bounds__(256, 4) void gemm_in(const float* __restrict__ bias)
{
    gemm_body<1>(g_gh, g_gl, g_wh, g_wl, bias,
                 g_x, CDIM, g_xh, g_xl, nullptr, nullptr,
                 NPAT, blockIdx.x * 128, blockIdx.y * 64);
}

// jmode 0: blockIdx.y -> {K, V}; jmode 1: Q only
__global__ __launch_bounds__(256, 4) void gemm_kqv(
    const float* __restrict__ kb, const float* __restrict__ qb,
    const float* __restrict__ vb, int l, int jmode)
{
    const int bx = blockIdx.x;
    int ty, bl;
    if (bx < NBP)            { ty = 0; bl = bx; }
    else if (bx < NBP + NBI) { ty = 1; bl = bx - NBP; }
    else                     { ty = 2; bl = bx - NBP - NBI; }
    const int M = (ty == 0) ? NPAT : (ty == 1) ? NICD : NNDC;
    const int toff = (ty == 0) ? 0 : (ty == 1) ? NPAT : NPAT + NICD;
    const int j = (jmode == 0) ? (blockIdx.y == 0 ? 0 : 2) : 1;
    const int widx = 1 + l * 9 + j * 3 + ty;
    const float* bias = ((j == 0) ? kb : (j == 1) ? qb : vb) + (size_t)(l * 3 + ty) * CDIM;
    float* outp = ((j == 0) ? g_k : (j == 1) ? g_q : g_v) + (size_t)toff * CDIM;
    gemm_body<0>(g_xh + (size_t)toff * 64, g_xl + (size_t)toff * 64,
                 g_wh + (size_t)widx * 8192, g_wl + (size_t)widx * 8192, bias,
                 outp, CDIM, nullptr, nullptr, nullptr, nullptr,
                 M, bl * 128, blockIdx.z * 64);
}

__global__ __launch_bounds__(256, 4) void gemm_ap(
    const float* __restrict__ ab, const float* __restrict__ skip, int l)
{
    const int bx = blockIdx.x;
    int ty, bl;
    if (bx < NBP)            { ty = 0; bl = bx; }
    else if (bx < NBP + NBI) { ty = 1; bl = bx - NBP; }
    else                     { ty = 2; bl = bx - NBP - NBI; }
    const int M = (ty == 0) ? NPAT : (ty == 1) ? NICD : NNDC;
    const int toff = (ty == 0) ? 0 : (ty == 1) ? NPAT : NPAT + NICD;
    const int widx = 19 + l * 3 + ty;
    gemm_body<2>(g_gh + (size_t)toff * 64, g_gl + (size_t)toff * 64,
                 g_wh + (size_t)widx * 8192, g_wl + (size_t)widx * 8192,
                 ab + (size_t)(l * 3 + ty) * CDIM,
                 g_x + (size_t)toff * CDIM, CDIM,
                 g_xh + (size_t)toff * 64, g_xl + (size_t)toff * 64,
                 skip + (l * 3 + ty), g_x + (size_t)toff * CDIM,
                 M, bl * 128, blockIdx.y * 64);
}

__global__ __launch_bounds__(256, 4) void gemm_o(
    const float* __restrict__ bias, float* __restrict__ out)
{
    gemm_body<3>(g_xh, g_xl, g_wh + (size_t)25 * 8192, g_wl + (size_t)25 * 8192, bias,
                 out, OUTD, nullptr, nullptr, nullptr, nullptr,
                 NPAT, blockIdx.x * 128, blockIdx.y * 64);
}

// ---------------- CSR build ----------------
__global__ void csr_clear() {
    int i = blockIdx.x * blockDim.x + threadIdx.x;
    if (i < NSOFT) { g_cnt[i] = 0; g_cur[i] = 0; }
}

__global__ void csr_hist_pat(const int* __restrict__ d1, const int* __restrict__ d3) {
    int i = blockIdx.x * blockDim.x + threadIdx.x;
    if (i < NEDGE / 4) {
        int4 a = reinterpret_cast<const int4*>(d1)[i];
        atomicAdd(&g_cnt[SOFF1 + a.x], 1);
        atomicAdd(&g_cnt[SOFF1 + a.y], 1);
        atomicAdd(&g_cnt[SOFF1 + a.z], 1);
        atomicAdd(&g_cnt[SOFF1 + a.w], 1);
        int4 b = reinterpret_cast<const int4*>(d3)[i];
        atomicAdd(&g_cnt[SOFF3 + b.x], 1);
        atomicAdd(&g_cnt[SOFF3 + b.y], 1);
        atomicAdd(&g_cnt[SOFF3 + b.z], 1);
        atomicAdd(&g_cnt[SOFF3 + b.w], 1);
    }
}

__global__ __launch_bounds__(256) void csr_hist_sm(const int* __restrict__ dst0,
                                                   const int* __restrict__ dst2) {
    __shared__ int h[NNDC];
    const int r = blockIdx.y;
    const int ndst = r ? NNDC : NICD;
    const int so = r ? SOFF2 : SOFF0;
    const int* __restrict__ dst = r ? dst2 : dst0;
    for (int i = threadIdx.x; i < ndst; i += 256) h[i] = 0;
    __syncthreads();
    const int tot = NEDGE / 4;
    for (int i = blockIdx.x * 256 + threadIdx.x; i < tot; i += gridDim.x * 256) {
        int4 a = reinterpret_cast<const int4*>(dst)[i];
        atomicAdd(&h[a.x], 1); atomicAdd(&h[a.y], 1);
        atomicAdd(&h[a.z], 1); atomicAdd(&h[a.w], 1);
    }
    __syncthreads();
    for (int i = threadIdx.x; i < ndst; i += 256)
        if (h[i]) atomicAdd(&g_cnt[so + i], h[i]);
}

__global__ __launch_bounds__(1024) void csr_scan() {
    __shared__ int partial[1024];
    const int CH = (NSOFT + 1023) / 1024;
    int t = threadIdx.x;
    int s0 = t * CH;
    int s1 = s0 + CH; if (s1 > NSOFT) s1 = NSOFT;
    int sum = 0;
    for (int i = s0; i < s1; i++) sum += g_cnt[i];
    partial[t] = sum;
    __syncthreads();
    for (int d = 1; d < 1024; d <<= 1) {
        int v = (t >= d) ? partial[t - d] : 0;
        __syncthreads();
        partial[t] += v;
        __syncthreads();
    }
    int pre = (t == 0) ? 0 : partial[t - 1];
    for (int i = s0; i < s1; i++) { g_off[i] = pre; pre += g_cnt[i]; }
}

__global__ void csr_scatter_pat(const int* __restrict__ s1, const int* __restrict__ d1,
                                const int* __restrict__ s3, const int* __restrict__ d3) {
    int i = blockIdx.x * blockDim.x + threadIdx.x;
    if (i < NEDGE) {
        int b1 = SOFF1 + d1[i];
        g_csr[g_off[b1] + atomicAdd(&g_cur[b1], 1)] = s1[i];
        int b3 = SOFF3 + d3[i];
        g_csr[g_off[b3] + atomicAdd(&g_cur[b3], 1)] = s3[i];
    }
}

__global__ __launch_bounds__(256) void csr_scatter_sm(
    const int* __restrict__ src0, const int* __restrict__ dst0,
    const int* __restrict__ src2, const int* __restrict__ dst2) {
    __shared__ int h[NNDC];
    __shared__ int base[NNDC];
    const int r = blockIdx.y;
    const int ndst = r ? NNDC : NICD;
    const int so = r ? SOFF2 : SOFF0;
    const int* __restrict__ dst = r ? dst2 : dst0;
    const int* __restrict__ src = r ? src2 : src0;
    const int chunk = (NEDGE + gridDim.x - 1) / gridDim.x;
    const int e0 = blockIdx.x * chunk;
    int e1 = e0 + chunk; if (e1 > NEDGE) e1 = NEDGE;

    for (int i = threadIdx.x; i < ndst; i += 256) h[i] = 0;
    __syncthreads();
    for (int e = e0 + threadIdx.x; e < e1; e += 256) atomicAdd(&h[dst[e]], 1);
    __syncthreads();
    for (int i = threadIdx.x; i < ndst; i += 256) {
        int cc = h[i];
        base[i] = cc ? atomicAdd(&g_cur[so + i], cc) : 0;
    }
    __syncthreads();
    for (int i = threadIdx.x; i < ndst; i += 256) h[i] = 0;
    __syncthreads();
    for (int e = e0 + threadIdx.x; e < e1; e += 256) {
        int d = dst[e];
        int loc = atomicAdd(&h[d], 1);
        g_csr[g_off[so + d] + base[d] + loc] = src[e];
    }
}

// ---------------- fused edge kernel ----------------
__global__ __launch_bounds__(256) void edge_fused(const float* __restrict__ prel)
{
    __shared__ float sacc[8][128];
    __shared__ float ses[8][8];
    const int b = blockIdx.x;
    const int tid = threadIdx.x;
    const int w = tid >> 5;
    const int lane = tid & 31;
    const int h = lane >> 2;

    if (b < EPB) {
        int d = b * 8 + w;
        float4 qv = *reinterpret_cast<const float4*>(&g_q[(size_t)d * CDIM + lane * 4]);
        float ax = 0.f, ay = 0.f, az = 0.f, aw2 = 0.f;
#pragma unroll
        for (int rr = 0; rr < 2; rr++) {
            const int rel = rr ? 3 : 1;
            const float* krb = rr ? g_krN : g_krI;
            const float* vrb = rr ? g_vrN : g_vrI;
            int base = (rr ? SOFF3 : SOFF1) + d;
            int st = g_off[base], n = g_cnt[base];
            float pf = prel[rel * 8 + h] * 0.25f;
            float es = 0.f, a0 = 0.f, a1 = 0.f, a2 = 0.f, a3 = 0.f;
            for (int i = 0; i < n; i++) {
                int s = g_csr[st + i];
                float4 kv = *reinterpret_cast<const float4*>(&krb[(size_t)s * CDIM + lane * 4]);
                float dot = qv.x * kv.x + qv.y * kv.y + qv.z * kv.z + qv.w * kv.w;
                dot += __shfl_xor_sync(0xffffffff, dot, 1);
                dot += __shfl_xor_sync(0xffffffff, dot, 2);
                float e = __expf(dot * pf);
                float4 vv = *reinterpret_cast<const float4*>(&vrb[(size_t)s * CDIM + lane * 4]);
                es += e;
                a0 += e * vv.x; a1 += e * vv.y; a2 += e * vv.z; a3 += e * vv.w;
            }
            if (n > 0) {
                float inv = 1.0f / es;
                ax += a0 * inv; ay += a1 * inv; az += a2 * inv; aw2 += a3 * inv;
            }
        }
        float v0 = geluf(ax), v1 = geluf(ay), v2 = geluf(az), v3 = geluf(aw2);
        uint32_t h0, l0, h1, l1;
        split_pair(v0, v1, h0, l0);
        split_pair(v2, v3, h1, l1);
        *reinterpret_cast<uint2*>(&g_gh[(size_t)d * 64 + lane * 2]) = make_uint2(h0, h1);
        *reinterpret_cast<uint2*>(&g_gl[(size_t)d * 64 + lane * 2]) = make_uint2(l0, l1);
    } else {
        int bb = b - EPB;
        int base;
        size_t nodeoff;
        const float *krb, *vrb;
        float pf;
        if (bb < NICD) {
            base = SOFF0 + bb;
            nodeoff = (size_t)(NPAT + bb);
            krb = g_krP0; vrb = g_vrP0;
            pf = prel[0 * 8 + h] * 0.25f;
        } else {
            int d = bb - NICD;
            base = SOFF2 + d;
            nodeoff = (size_t)(NPAT + NICD + d);
            krb = g_krP1; vrb = g_vrP1;
            pf = prel[2 * 8 + h] * 0.25f;
        }
        float4 qv = *reinterpret_cast<const float4*>(&g_q[nodeoff * CDIM + lane * 4]);
        int st = g_off[base], n = g_cnt[base];
        float es = 0.f, a0 = 0.f, a1 = 0.f, a2 = 0.f, a3 = 0.f;
        for (int i = w; i < n; i += 8) {
            int s = g_csr[st + i];
            float4 kv = *reinterpret_cast<const float4*>(&krb[(size_t)s * CDIM + lane * 4]);
            float dot = qv.x * kv.x + qv.y * kv.y + qv.z * kv.z + qv.w * kv.w;
            dot += __shfl_xor_sync(0xffffffff, dot, 1);
            dot += __shfl_xor_sync(0xffffffff, dot, 2);
            float e = __expf(dot * pf);
            float4 vv = *reinterpret_cast<const float4*>(&vrb[(size_t)s * CDIM + lane * 4]);
            es += e;
            a0 += e * vv.x; a1 += e * vv.y; a2 += e * vv.z; a3 += e * vv.w;
        }
        *reinterpret_cast<float4*>(&sacc[w][lane * 4]) = make_float4(a0, a1, a2, a3);
        if ((lane & 3) == 0) ses[w][h] = es;
        __syncthreads();
        if (tid < 64) {
            int col0 = 2 * tid;
            float s0 = 0.f, s1 = 0.f, e = 0.f;
#pragma unroll
            for (int ww = 0; ww < 8; ww++) {
                s0 += sacc[ww][col0];
                s1 += sacc[ww][col0 + 1];
                e  += ses[ww][tid >> 3];
            }
            float v0 = (e > 0.f) ? s0 / e : 0.0f;
            float v1 = (e > 0.f) ? s1 / e : 0.0f;
            v0 = geluf(v0); v1 = geluf(v1);
            uint32_t hh, ll;
            split_pair(v0, v1, hh, ll);
            g_gh[nodeoff * 64 + tid] = hh;
            g_gl[nodeoff * 64 + tid] = ll;
        }
    }
}

// ---------------- merged per-relation K/V transform ----------------
struct ReltAll {
    const float* A[4];
    const float* Mw[4];
};
__global__ __launch_bounds__(128) void relt_all(ReltAll ra)
{
    __shared__ float ks[32][128];
    __shared__ float vs[32][128];
    const int tid = threadIdx.x;
    const int bx = blockIdx.x;
    const int h = tid >> 4;
    const int e = tid & 15;

    int node0, nsrc, srcoff;
    const float *A0, *M0, *A1, *M1;
    float *kr0, *vr0, *kr1, *vr1;
    bool two;
    if (bx < RTP) {
        node0 = bx * 32; nsrc = NPAT; srcoff = 0; two = true;
        A0 = ra.A[0]; M0 = ra.Mw[0]; A1 = ra.A[2]; M1 = ra.Mw[2];
        kr0 = g_krP0; vr0 = g_vrP0; kr1 = g_krP1; vr1 = g_vrP1;
    } else if (bx < RTP + RTI) {
        node0 = (bx - RTP) * 32; nsrc = NICD; srcoff = NPAT; two = false;
        A0 = ra.A[1]; M0 = ra.Mw[1]; A1 = nullptr; M1 = nullptr;
        kr0 = g_krI; vr0 = g_vrI; kr1 = nullptr; vr1 = nullptr;
    } else {
        node0 = (bx - RTP - RTI) * 32; nsrc = NNDC; srcoff = NPAT + NICD; two = false;
        A0 = ra.A[3]; M0 = ra.Mw[3]; A1 = nullptr; M1 = nullptr;
        kr0 = g_krN; vr0 = g_vrN; kr1 = nullptr; vr1 = nullptr;
    }

    float areg0[16], mreg0[16], areg1[16], mreg1[16];
#pragma unroll
    for (int d = 0; d < 16; d++) {
        areg0[d] = A0[(h * 16 + d) * 16 + e];
        mreg0[d] = M0[(h * 16 + d) * 16 + e];
        if (two) {
            areg1[d] = A1[(h * 16 + d) * 16 + e];
            mreg1[d] = M1[(h * 16 + d) * 16 + e];
        }
    }

    const float* kbase = g_k + (size_t)srcoff * CDIM;
    const float* vbase = g_v + (size_t)srcoff * CDIM;
    for (int i = tid; i < 32 * 32; i += 128) {
        int r = i >> 5;
        int cidx = (i & 31) * 4;
        if (node0 + r < nsrc) {
            *reinterpret_cast<float4*>(&ks[r][cidx]) =
                *reinterpret_cast<const float4*>(&kbase[(size_t)(node0 + r) * CDIM + cidx]);
            *reinterpret_cast<float4*>(&vs[r][cidx]) =
                *reinterpret_cast<const float4*>(&vbase[(size_t)(node0 + r) * CDIM + cidx]);
        }
    }
    __syncthreads();

    int nmax = nsrc - node0; if (nmax > 32) nmax = 32;
    for (int n = 0; n < nmax; n++) {
        float acck0 = 0.f, accv0 = 0.f, acck1 = 0.f, accv1 = 0.f;
#pragma unroll
        for (int d4 = 0; d4 < 4; d4++) {
            float4 kq = *reinterpret_cast<const float4*>(&ks[n][h * 16 + d4 * 4]);
            float4 vq = *reinterpret_cast<const float4*>(&vs[n][h * 16 + d4 * 4]);
            float kk[4] = {kq.x, kq.y, kq.z, kq.w};
            float vv[4] = {vq.x, vq.y, vq.z, vq.w};
#pragma unroll
            for (int j = 0; j < 4; j++) {
                int d = d4 * 4 + j;
                acck0 = fmaf(kk[j], areg0[d], acck0);
                accv0 = fmaf(vv[j], mreg0[d], accv0);
                if (two) {
                    acck1 = fmaf(kk[j], areg1[d], acck1);
                    accv1 = fmaf(vv[j], mreg1[d], accv1);
                }
            }
        }
        size_t o = (size_t)(node0 + n) * CDIM + h * 16 + e;
        kr0[o] = acck0; vr0[o] = accv0;
        if (two) { kr1[o] = acck1; vr1[o] = accv1; }
    }
}

// ---------------- host ----------------
extern "C" void kernel_launch(void* const* d_in, const int* in_sizes, int n_in,
                              void* d_out, int out_size)
{
    const float* x_patient = (const float*)d_in[0];
    const float* w_in      = (const float*)d_in[1];
    const float* b_in      = (const float*)d_in[2];
    const float* emb_icd   = (const float*)d_in[3];
    const float* emb_ndc   = (const float*)d_in[4];
    const float* kw = (const float*)d_in[5];
    const float* kb = (const float*)d_in[6];
    const float* qw = (const float*)d_in[7];
    const float* qb = (const float*)d_in[8];
    const float* vw = (const float*)d_in[9];
    const float* vb = (const float*)d_in[10];
    const float* aw = (const float*)d_in[11];
    const float* ab = (const float*)d_in[12];
    const float* skip  = (const float*)d_in[13];
    const float* a_rel = (const float*)d_in[14];
    const float* m_rel = (const float*)d_in[15];
    const float* p_rel = (const float*)d_in[16];
    const float* w_out = (const float*)d_in[17];
    const float* b_out = (const float*)d_in[18];
    const int* x_icd = (const int*)d_in[19];
    const int* x_ndc = (const int*)d_in[20];
    const int* esrc[4] = {(const int*)d_in[21], (const int*)d_in[23],
                          (const int*)d_in[25], (const int*)d_in[27]};
    const int* edst[4] = {(const int*)d_in[22], (const int*)d_in[24],
                          (const int*)d_in[26], (const int*)d_in[28]};
    float* out = (float*)d_out;

    // second stream + events for fork/join (host-side objects; capture-legal pattern)
    cudaStream_t s2;
    cudaStreamCreate(&s2);
    cudaEvent_t evFork, evCsr, evX0, evX1, evQ0, evQ1;
    cudaEventCreateWithFlags(&evFork, cudaEventDisableTiming);
    cudaEventCreateWithFlags(&evCsr,  cudaEventDisableTiming);
    cudaEventCreateWithFlags(&evX0,   cudaEventDisableTiming);
    cudaEventCreateWithFlags(&evX1,   cudaEventDisableTiming);
    cudaEventCreateWithFlags(&evQ0,   cudaEventDisableTiming);
    cudaEventCreateWithFlags(&evQ1,   cudaEventDisableTiming);
    cudaEvent_t evX[2] = {evX0, evX1};
    cudaEvent_t evQ[2] = {evQ0, evQ1};

    // ---- fork CSR build onto s2 (independent of all weights/activations) ----
    cudaEventRecord(evFork, 0);
    cudaStreamWaitEvent(s2, evFork, 0);
    csr_clear<<<(NSOFT + 255) / 256, 256, 0, s2>>>();
    csr_hist_pat<<<(NEDGE / 4 + 255) / 256, 256, 0, s2>>>(edst[1], edst[3]);
    {
        dim3 gh(48, 2);
        csr_hist_sm<<<gh, 256, 0, s2>>>(edst[0], edst[2]);
    }
    csr_scan<<<1, 1024, 0, s2>>>();
    csr_scatter_pat<<<(NEDGE + 255) / 256, 256, 0, s2>>>(esrc[1], edst[1], esrc[3], edst[3]);
    {
        dim3 gs(64, 2);
        csr_scatter_sm<<<gs, 256, 0, s2>>>(esrc[0], edst[0], esrc[2], edst[2]);
    }
    cudaEventRecord(evCsr, s2);

    // ---- main stream: weights / inputs / in-proj ----
    {
        WSplit ws;
        ws.src[0] = w_in; ws.nn[0] = CDIM;
        const float* wsrc[3] = {kw, qw, vw};
        for (int l = 0; l < 2; l++)
            for (int j = 0; j < 3; j++)
                for (int ty = 0; ty < 3; ty++) {
                    ws.src[1 + l * 9 + j * 3 + ty] = wsrc[j] + (size_t)(l * 3 + ty) * CDIM * CDIM;
                    ws.nn[1 + l * 9 + j * 3 + ty] = CDIM;
                }
        for (int l = 0; l < 2; l++)
            for (int ty = 0; ty < 3; ty++) {
                ws.src[19 + l * 3 + ty] = aw + (size_t)(l * 3 + ty) * CDIM * CDIM;
                ws.nn[19 + l * 3 + ty] = CDIM;
            }
        ws.src[25] = w_out; ws.nn[25] = OUTD;
        dim3 g(32, NWMAT);
        split_weights<<<g, 256>>>(ws);
    }
    prep_inputs<<<(NTOTAL * 64 + 255) / 256, 256>>>(x_patient, emb_icd, x_icd, emb_ndc, x_ndc);
    {
        dim3 g(NBP, 2);
        gemm_in<<<g, 256>>>(b_in);
    }

    for (int l = 0; l < 2; l++) {
        // x (and split-x) ready on main stream here -> fork Q GEMM onto s2
        cudaEventRecord(evX[l], 0);
        cudaStreamWaitEvent(s2, evX[l], 0);
        {
            dim3 gq(NBALL, 1, 2);
            gemm_kqv<<<gq, 256, 0, s2>>>(kb, qb, vb, l, 1);   // Q
        }
        cudaEventRecord(evQ[l], s2);

        // main: K and V, then relation transforms (overlaps Q)
        {
            dim3 gkv(NBALL, 2, 2);
            gemm_kqv<<<gkv, 256>>>(kb, qb, vb, l, 0);         // K, V
        }
        {
            ReltAll ra;
            for (int r = 0; r < 4; r++) {
                ra.A[r]  = a_rel + (size_t)(l * 4 + r) * HH * DD * DD;
                ra.Mw[r] = m_rel + (size_t)(l * 4 + r) * HH * DD * DD;
            }
            relt_all<<<RTALL, 128>>>(ra);
        }

        // join: edge needs Q (s2) and, on layer 0, the CSR build (s2)
        cudaStreamWaitEvent(0, evQ[l], 0);
        if (l == 0) cudaStreamWaitEvent(0, evCsr, 0);

        edge_fused<<<EALL, 256>>>(p_rel + l * 32);

        {
            dim3 grid(NBALL, 2);
            gemm_ap<<<grid, 256>>>(ab, skip, l);
        }
    }

    // output projection + sigmoid
    {
        dim3 g(NBP, 2);
        gemm_o<<<g, 256>>>(b_out, out);
    }

    cudaEventDestroy(evFork);
    cudaEventDestroy(evCsr);
    cudaEventDestroy(evX0);
    cudaEventDestroy(evX1);
    cudaEventDestroy(evQ0);
    cudaEventDestroy(evQ1);
    cudaStreamDestroy(s2);
}

// round 13
// speedup vs baseline: 2.2313x; 1.1550x over previous
#include <cuda_runtime.h>
#include <math.h>
#include <stdint.h>

#define NPAT 50000
#define NICD 591
#define NNDC 2042
#define NTOTAL 52633
#define NSOFT 102633
#define CDIM 128
#define HH 8
#define DD 16
#define NEDGE 250000
#define OUTD 90

#define SOFF0 0
#define SOFF1 NICD
#define SOFF2 (NICD + NPAT)
#define SOFF3 (NICD + NPAT + NNDC)

#define NBP 391
#define NBI 5
#define NBN 16
#define NBALL (NBP + NBI + NBN)

#define RTP 1563
#define RTI 19
#define RTN 64
#define RTALL (RTP + RTI + RTN)

#define EPB 6250
#define EBLK (NICD + NNDC)
#define EALL (EPB + EBLK)

#define NWMAT 26

#define SCAN_TILE 1024
#define NSCB ((NSOFT + SCAN_TILE - 1) / SCAN_TILE)   /* 101 */

// ---------------- scratch ----------------
__device__ float g_x[NTOTAL * CDIM];
__device__ float g_k[NTOTAL * CDIM];
__device__ float g_q[NTOTAL * CDIM];
__device__ float g_v[NTOTAL * CDIM];
__device__ float g_krP0[NPAT * CDIM];
__device__ float g_vrP0[NPAT * CDIM];
__device__ float g_krP1[NPAT * CDIM];
__device__ float g_vrP1[NPAT * CDIM];
__device__ float g_krI[NICD * CDIM];
__device__ float g_vrI[NICD * CDIM];
__device__ float g_krN[NNDC * CDIM];
__device__ float g_vrN[NNDC * CDIM];
__device__ uint32_t g_xh[NTOTAL * 64];
__device__ uint32_t g_xl[NTOTAL * 64];
__device__ uint32_t g_gh[NTOTAL * 64];
__device__ uint32_t g_gl[NTOTAL * 64];
__device__ uint32_t g_wh[NWMAT * 8192];
__device__ uint32_t g_wl[NWMAT * 8192];
__device__ int g_cnt[NSOFT];
__device__ int g_off[NSOFT];
__device__ int g_cur[NSOFT];
__device__ int g_csr[4 * NEDGE];
__device__ int g_bsum[NSCB];
__device__ int g_bbase[NSCB];

__device__ __forceinline__ float geluf(float x) {
    float t = tanhf(0.7978845608028654f * (x + 0.044715f * x * x * x));
    return 0.5f * x * (1.0f + t);
}

__device__ __forceinline__ void split_pair(float v0, float v1, uint32_t& h, uint32_t& l) {
    uint32_t hh;
    asm("cvt.rn.bf16x2.f32 %0, %1, %2;" : "=r"(hh) : "f"(v1), "f"(v0));
    float h0 = __uint_as_float(hh << 16);
    float h1 = __uint_as_float(hh & 0xffff0000u);
    float l0 = v0 - h0;
    float l1 = v1 - h1;
    uint32_t ll;
    asm("cvt.rn.bf16x2.f32 %0, %1, %2;" : "=r"(ll) : "f"(l1), "f"(l0));
    h = hh; l = ll;
}

__device__ __forceinline__ void mma_bf16(float* c, const uint32_t* a, const uint32_t* b) {
    asm volatile("mma.sync.aligned.m16n8k16.row.col.f32.bf16.bf16.f32 "
                 "{%0,%1,%2,%3}, {%4,%5,%6,%7}, {%8,%9}, {%0,%1,%2,%3};"
                 : "+f"(c[0]), "+f"(c[1]), "+f"(c[2]), "+f"(c[3])
                 : "r"(a[0]), "r"(a[1]), "r"(a[2]), "r"(a[3]),
                   "r"(b[0]), "r"(b[1]));
}

// ---------------- pre-split weights ----------------
struct WSplit { const float* src[NWMAT]; int nn[NWMAT]; };
__global__ void split_weights(WSplit ws) {
    int m = blockIdx.y;
    int idx = blockIdx.x * 256 + threadIdx.x;
    int kp = idx >> 7, n = idx & 127;
    const float* s = ws.src[m];
    int N = ws.nn[m];
    float v0 = (n < N) ? s[(size_t)(2 * kp) * N + n] : 0.0f;
    float v1 = (n < N) ? s[(size_t)(2 * kp + 1) * N + n] : 0.0f;
    uint32_t h, l;
    split_pair(v0, v1, h, l);
    g_wh[m * 8192 + idx] = h;
    g_wl[m * 8192 + idx] = l;
}

// ---------------- input prep ----------------
__global__ void prep_inputs(const float* __restrict__ xp,
                            const float* __restrict__ ei, const int* __restrict__ xi,
                            const float* __restrict__ en, const int* __restrict__ xn) {
    int idx = blockIdx.x * 256 + threadIdx.x;
    const int n1 = NPAT * 64;
    const int n2 = n1 + NICD * 64;
    const int n3 = n2 + NNDC * 64;
    if (idx < n1) {
        int node = idx >> 6, kp = idx & 63;
        float2 v = *reinterpret_cast<const float2*>(&xp[(size_t)node * CDIM + 2 * kp]);
        uint32_t h, l;
        split_pair(v.x, v.y, h, l);
        g_gh[idx] = h; g_gl[idx] = l;
    } else if (idx < n3) {
        int j, node;
        const float* emb;
        const int* map;
        if (idx < n2) { j = idx - n1; emb = ei; map = xi; node = NPAT + (j >> 6); }
        else          { j = idx - n2; emb = en; map = xn; node = NPAT + NICD + (j >> 6); }
        int r = j >> 6, kp = j & 63;
        float2 v = *reinterpret_cast<const float2*>(&emb[(size_t)map[r] * CDIM + 2 * kp]);
        v.x = fmaxf(v.x, 0.0f);
        v.y = fmaxf(v.y, 0.0f);
        g_x[(size_t)node * CDIM + 2 * kp] = v.x;
        g_x[(size_t)node * CDIM + 2 * kp + 1] = v.y;
        uint32_t h, l;
        split_pair(v.x, v.y, h, l);
        g_xh[(size_t)node * 64 + kp] = h;
        g_xl[(size_t)node * 64 + kp] = l;
    }
}

// ---------------- GEMM body (pre-split operands) ----------------
// MODE: 0 plain fp32 (kqv), 1 relu+split (inproj), 2 blend+split (aproj), 3 sigmoid N=90
template<int MODE>
__device__ __forceinline__ void gemm_body(
    const uint32_t* __restrict__ XH, const uint32_t* __restrict__ XL,
    const uint32_t* __restrict__ WH, const uint32_t* __restrict__ WL,
    const float* __restrict__ bias,
    float* __restrict__ OutF, int ldo,
    uint32_t* __restrict__ OutH, uint32_t* __restrict__ OutL,
    const float* __restrict__ skipPtr, const float* __restrict__ xold,
    int M, int row0, int ncol0)
{
    __shared__ uint32_t Ah[128][20];
    __shared__ uint32_t Al[128][20];
    __shared__ uint32_t Bh[16][72];
    __shared__ uint32_t Bl[16][72];

    const int tid = threadIdx.x;
    const int lane = tid & 31;
    const int wid = tid >> 5;
    const int warp_m = wid >> 1;
    const int warp_n = wid & 1;
    const int gi = lane >> 2;
    const int tig = lane & 3;

    float c[2][4][4];
#pragma unroll
    for (int am = 0; am < 2; am++)
#pragma unroll
        for (int an = 0; an < 4; an++)
#pragma unroll
            for (int j = 0; j < 4; j++) c[am][an][j] = 0.0f;

    const int ar = tid >> 1;
    const int akh = tid & 1;
    const bool aok = (row0 + ar) < M;
    const int bkp = tid >> 4;
    const int nl0 = (tid & 15) * 4;

    for (int kc2 = 0; kc2 < 64; kc2 += 16) {
        uint4 ha = make_uint4(0, 0, 0, 0), hb = ha, la = ha, lb = ha;
        if (aok) {
            const uint32_t* ph = &XH[(size_t)(row0 + ar) * 64 + kc2 + akh * 8];
            const uint32_t* pl = &XL[(size_t)(row0 + ar) * 64 + kc2 + akh * 8];
            ha = *reinterpret_cast<const uint4*>(ph);
            hb = *reinterpret_cast<const uint4*>(ph + 4);
            la = *reinterpret_cast<const uint4*>(pl);
            lb = *reinterpret_cast<const uint4*>(pl + 4);
        }
        *reinterpret_cast<uint4*>(&Ah[ar][akh * 8]) = ha;
        *reinterpret_cast<uint4*>(&Ah[ar][akh * 8 + 4]) = hb;
        *reinterpret_cast<uint4*>(&Al[ar][akh * 8]) = la;
        *reinterpret_cast<uint4*>(&Al[ar][akh * 8 + 4]) = lb;
        *reinterpret_cast<uint4*>(&Bh[bkp][nl0]) =
            *reinterpret_cast<const uint4*>(&WH[(size_t)(kc2 + bkp) * 128 + ncol0 + nl0]);
        *reinterpret_cast<uint4*>(&Bl[bkp][nl0]) =
            *reinterpret_cast<const uint4*>(&WL[(size_t)(kc2 + bkp) * 128 + ncol0 + nl0]);
        __syncthreads();

#pragma unroll
        for (int ks = 0; ks < 2; ks++) {
            const int kb = ks * 8;
            uint32_t ah[2][4], al[2][4];
#pragma unroll
            for (int am = 0; am < 2; am++) {
                int rb = warp_m * 32 + am * 16 + gi;
                ah[am][0] = Ah[rb][kb + tig];
                ah[am][1] = Ah[rb + 8][kb + tig];
                ah[am][2] = Ah[rb][kb + 4 + tig];
                ah[am][3] = Ah[rb + 8][kb + 4 + tig];
                al[am][0] = Al[rb][kb + tig];
                al[am][1] = Al[rb + 8][kb + tig];
                al[am][2] = Al[rb][kb + 4 + tig];
                al[am][3] = Al[rb + 8][kb + 4 + tig];
            }
#pragma unroll
            for (int an = 0; an < 4; an++) {
                int nc = warp_n * 32 + an * 8 + gi;
                uint32_t bh[2], bl[2];
                bh[0] = Bh[kb + tig][nc];
                bh[1] = Bh[kb + 4 + tig][nc];
                bl[0] = Bl[kb + tig][nc];
                bl[1] = Bl[kb + 4 + tig][nc];
#pragma unroll
                for (int am = 0; am < 2; am++) {
                    mma_bf16(c[am][an], ah[am], bh);
                    mma_bf16(c[am][an], al[am], bh);
                    mma_bf16(c[am][an], ah[am], bl);
                }
            }
        }
        __syncthreads();
    }

    float sa = 0.f, sb = 0.f;
    if (MODE == 2) {
        float s = 1.0f / (1.0f + __expf(-*skipPtr));
        sa = s; sb = 1.0f - s;
    }
#pragma unroll
    for (int am = 0; am < 2; am++) {
#pragma unroll
        for (int an = 0; an < 4; an++) {
            int col = ncol0 + warp_n * 32 + an * 8 + tig * 2;
#pragma unroll
            for (int half = 0; half < 2; half++) {
                int row = row0 + warp_m * 32 + am * 16 + gi + half * 8;
                if (row >= M) continue;
                float b0 = (MODE == 3) ? ((col < OUTD) ? bias[col] : 0.0f) : bias[col];
                float b1 = (MODE == 3) ? ((col + 1 < OUTD) ? bias[col + 1] : 0.0f) : bias[col + 1];
                float v0 = c[am][an][half * 2 + 0] + b0;
                float v1 = c[am][an][half * 2 + 1] + b1;
                if (MODE == 1) { v0 = fmaxf(v0, 0.0f); v1 = fmaxf(v1, 0.0f); }
                else if (MODE == 2) {
                    v0 = sa * v0 + sb * xold[(size_t)row * CDIM + col];
                    v1 = sa * v1 + sb * xold[(size_t)row * CDIM + col + 1];
                } else if (MODE == 3) {
                    v0 = 1.0f / (1.0f + __expf(-v0));
                    v1 = 1.0f / (1.0f + __expf(-v1));
                }
                if (MODE == 3) {
                    if (col < OUTD)     OutF[(size_t)row * ldo + col] = v0;
                    if (col + 1 < OUTD) OutF[(size_t)row * ldo + col + 1] = v1;
                } else {
                    OutF[(size_t)row * CDIM + col] = v0;
                    OutF[(size_t)row * CDIM + col + 1] = v1;
                    if (MODE == 1 || MODE == 2) {
                        uint32_t h, l;
                        split_pair(v0, v1, h, l);
                        OutH[(size_t)row * 64 + (col >> 1)] = h;
                        OutL[(size_t)row * 64 + (col >> 1)] = l;
                    }
                }
            }
        }
    }
}

// ---------------- GEMM wrappers ----------------
__global__ __launch_bounds__(256, 4) void gemm_in(const float* __restrict__ bias)
{
    gemm_body<1>(g_gh, g_gl, g_wh, g_wl, bias,
                 g_x, CDIM, g_xh, g_xl, nullptr, nullptr,
                 NPAT, blockIdx.x * 128, blockIdx.y * 64);
}

// jmode 0: blockIdx.y -> {K, V}; jmode 1: Q only
__global__ __launch_bounds__(256, 4) void gemm_kqv(
    const float* __restrict__ kb, const float* __restrict__ qb,
    const float* __restrict__ vb, int l, int jmode)
{
    const int bx = blockIdx.x;
    int ty, bl;
    if (bx < NBP)            { ty = 0; bl = bx; }
    else if (bx < NBP + NBI) { ty = 1; bl = bx - NBP; }
    else                     { ty = 2; bl = bx - NBP - NBI; }
    const int M = (ty == 0) ? NPAT : (ty == 1) ? NICD : NNDC;
    const int toff = (ty == 0) ? 0 : (ty == 1) ? NPAT : NPAT + NICD;
    const int j = (jmode == 0) ? (blockIdx.y == 0 ? 0 : 2) : 1;
    const int widx = 1 + l * 9 + j * 3 + ty;
    const float* bias = ((j == 0) ? kb : (j == 1) ? qb : vb) + (size_t)(l * 3 + ty) * CDIM;
    float* outp = ((j == 0) ? g_k : (j == 1) ? g_q : g_v) + (size_t)toff * CDIM;
    gemm_body<0>(g_xh + (size_t)toff * 64, g_xl + (size_t)toff * 64,
                 g_wh + (size_t)widx * 8192, g_wl + (size_t)widx * 8192, bias,
                 outp, CDIM, nullptr, nullptr, nullptr, nullptr,
                 M, bl * 128, blockIdx.z * 64);
}

__global__ __launch_bounds__(256, 4) void gemm_ap(
    const float* __restrict__ ab, const float* __restrict__ skip, int l)
{
    const int bx = blockIdx.x;
    int ty, bl;
    if (bx < NBP)            { ty = 0; bl = bx; }
    else if (bx < NBP + NBI) { ty = 1; bl = bx - NBP; }
    else                     { ty = 2; bl = bx - NBP - NBI; }
    const int M = (ty == 0) ? NPAT : (ty == 1) ? NICD : NNDC;
    const int toff = (ty == 0) ? 0 : (ty == 1) ? NPAT : NPAT + NICD;
    const int widx = 19 + l * 3 + ty;
    gemm_body<2>(g_gh + (size_t)toff * 64, g_gl + (size_t)toff * 64,
                 g_wh + (size_t)widx * 8192, g_wl + (size_t)widx * 8192,
                 ab + (size_t)(l * 3 + ty) * CDIM,
                 g_x + (size_t)toff * CDIM, CDIM,
                 g_xh + (size_t)toff * 64, g_xl + (size_t)toff * 64,
                 skip + (l * 3 + ty), g_x + (size_t)toff * CDIM,
                 M, bl * 128, blockIdx.y * 64);
}

__global__ __launch_bounds__(256, 4) void gemm_o(
    const float* __restrict__ bias, float* __restrict__ out)
{
    gemm_body<3>(g_xh, g_xl, g_wh + (size_t)25 * 8192, g_wl + (size_t)25 * 8192, bias,
                 out, OUTD, nullptr, nullptr, nullptr, nullptr,
                 NPAT, blockIdx.x * 128, blockIdx.y * 64);
}

// ---------------- CSR build ----------------
__global__ void csr_clear() {
    int i = blockIdx.x * blockDim.x + threadIdx.x;
    if (i < NSOFT) { g_cnt[i] = 0; g_cur[i] = 0; }
}

__global__ void csr_hist_pat(const int* __restrict__ d1, const int* __restrict__ d3) {
    int i = blockIdx.x * blockDim.x + threadIdx.x;
    if (i < NEDGE / 4) {
        int4 a = reinterpret_cast<const int4*>(d1)[i];
        atomicAdd(&g_cnt[SOFF1 + a.x], 1);
        atomicAdd(&g_cnt[SOFF1 + a.y], 1);
        atomicAdd(&g_cnt[SOFF1 + a.z], 1);
        atomicAdd(&g_cnt[SOFF1 + a.w], 1);
        int4 b = reinterpret_cast<const int4*>(d3)[i];
        atomicAdd(&g_cnt[SOFF3 + b.x], 1);
        atomicAdd(&g_cnt[SOFF3 + b.y], 1);
        atomicAdd(&g_cnt[SOFF3 + b.z], 1);
        atomicAdd(&g_cnt[SOFF3 + b.w], 1);
    }
}

__global__ __launch_bounds__(256) void csr_hist_sm(const int* __restrict__ dst0,
                                                   const int* __restrict__ dst2) {
    __shared__ int h[NNDC];
    const int r = blockIdx.y;
    const int ndst = r ? NNDC : NICD;
    const int so = r ? SOFF2 : SOFF0;
    const int* __restrict__ dst = r ? dst2 : dst0;
    for (int i = threadIdx.x; i < ndst; i += 256) h[i] = 0;
    __syncthreads();
    const int tot = NEDGE / 4;
    for (int i = blockIdx.x * 256 + threadIdx.x; i < tot; i += gridDim.x * 256) {
        int4 a = reinterpret_cast<const int4*>(dst)[i];
        atomicAdd(&h[a.x], 1); atomicAdd(&h[a.y], 1);
        atomicAdd(&h[a.z], 1); atomicAdd(&h[a.w], 1);
    }
    __syncthreads();
    for (int i = threadIdx.x; i < ndst; i += 256)
        if (h[i]) atomicAdd(&g_cnt[so + i], h[i]);
}

// ---- 3-phase coalesced scan (replaces single-block strided scan) ----
__global__ __launch_bounds__(256) void scan_partial() {
    __shared__ int red[256];
    const int base = blockIdx.x * SCAN_TILE;
    int sum = 0;
#pragma unroll
    for (int j = 0; j < 4; j++) {
        int idx = base + j * 256 + threadIdx.x;
        sum += (idx < NSOFT) ? g_cnt[idx] : 0;
    }
    red[threadIdx.x] = sum;
    __syncthreads();
    for (int d = 128; d > 0; d >>= 1) {
        if (threadIdx.x < d) red[threadIdx.x] += red[threadIdx.x + d];
        __syncthreads();
    }
    if (threadIdx.x == 0) g_bsum[blockIdx.x] = red[0];
}

__global__ __launch_bounds__(128) void scan_base() {
    __shared__ int tmp[NSCB];
    int t = threadIdx.x;
    if (t < NSCB) tmp[t] = g_bsum[t];
    __syncthreads();
    if (t == 0) {
        int acc = 0;
        for (int i = 0; i < NSCB; i++) { int v = tmp[i]; tmp[i] = acc; acc += v; }
    }
    __syncthreads();
    if (t < NSCB) g_bbase[t] = tmp[t];
}

__global__ __launch_bounds__(256) void scan_write() {
    __shared__ int wsum[8];
    const int base = blockIdx.x * SCAN_TILE;
    const int t = threadIdx.x;
    const int lane = t & 31;
    const int w = t >> 5;
    int v[4];
    const int idx0 = base + t * 4;
#pragma unroll
    for (int j = 0; j < 4; j++) {
        int idx = idx0 + j;
        v[j] = (idx < NSOFT) ? g_cnt[idx] : 0;
    }
    int s1 = v[0] + v[1];
    int s2 = s1 + v[2];
    int tot = s2 + v[3];
    // warp inclusive scan of per-thread totals
    int x = tot;
#pragma unroll
    for (int d = 1; d < 32; d <<= 1) {
        int y = __shfl_up_sync(0xffffffff, x, d);
        if (lane >= d) x += y;
    }
    if (lane == 31) wsum[w] = x;
    __syncthreads();
    if (w == 0 && lane < 8) {
        int orig = wsum[lane];
        int ws = orig;
#pragma unroll
        for (int d = 1; d < 8; d <<= 1) {
            int y = __shfl_up_sync(0xff, ws, d);
            if (lane >= d) ws += y;
        }
        wsum[lane] = ws - orig;   // exclusive warp base
    }
    __syncthreads();
    int ebase = g_bbase[blockIdx.x] + wsum[w] + (x - tot);
    int offs[4] = {0, v[0], s1, s2};
#pragma unroll
    for (int j = 0; j < 4; j++) {
        int idx = idx0 + j;
        if (idx < NSOFT) g_off[idx] = ebase + offs[j];
    }
}

__global__ void csr_scatter_pat(const int* __restrict__ s1, const int* __restrict__ d1,
                                const int* __restrict__ s3, const int* __restrict__ d3) {
    int i = blockIdx.x * blockDim.x + threadIdx.x;
    if (i < NEDGE) {
        int b1 = SOFF1 + d1[i];
        g_csr[g_off[b1] + atomicAdd(&g_cur[b1], 1)] = s1[i];
        int b3 = SOFF3 + d3[i];
        g_csr[g_off[b3] + atomicAdd(&g_cur[b3], 1)] = s3[i];
    }
}

__global__ __launch_bounds__(256) void csr_scatter_sm(
    const int* __restrict__ src0, const int* __restrict__ dst0,
    const int* __restrict__ src2, const int* __restrict__ dst2) {
    __shared__ int h[NNDC];
    __shared__ int base[NNDC];
    const int r = blockIdx.y;
    const int ndst = r ? NNDC : NICD;
    const int so = r ? SOFF2 : SOFF0;
    const int* __restrict__ dst = r ? dst2 : dst0;
    const int* __restrict__ src = r ? src2 : src0;
    const int chunk = (NEDGE + gridDim.x - 1) / gridDim.x;
    const int e0 = blockIdx.x * chunk;
    int e1 = e0 + chunk; if (e1 > NEDGE) e1 = NEDGE;

    for (int i = threadIdx.x; i < ndst; i += 256) h[i] = 0;
    __syncthreads();
    for (int e = e0 + threadIdx.x; e < e1; e += 256) atomicAdd(&h[dst[e]], 1);
    __syncthreads();
    for (int i = threadIdx.x; i < ndst; i += 256) {
        int cc = h[i];
        base[i] = cc ? atomicAdd(&g_cur[so + i], cc) : 0;
    }
    __syncthreads();
    for (int i = threadIdx.x; i < ndst; i += 256) h[i] = 0;
    __syncthreads();
    for (int e = e0 + threadIdx.x; e < e1; e += 256) {
        int d = dst[e];
        int loc = atomicAdd(&h[d], 1);
        g_csr[g_off[so + d] + base[d] + loc] = src[e];
    }
}

// ---------------- fused edge kernel ----------------
__global__ __launch_bounds__(256) void edge_fused(const float* __restrict__ prel)
{
    __shared__ float sacc[8][128];
    __shared__ float ses[8][8];
    const int b = blockIdx.x;
    const int tid = threadIdx.x;
    const int w = tid >> 5;
    const int lane = tid & 31;
    const int h = lane >> 2;

    if (b < EPB) {
        int d = b * 8 + w;
        float4 qv = *reinterpret_cast<const float4*>(&g_q[(size_t)d * CDIM + lane * 4]);
        float ax = 0.f, ay = 0.f, az = 0.f, aw2 = 0.f;
#pragma unroll
        for (int rr = 0; rr < 2; rr++) {
            const int rel = rr ? 3 : 1;
            const float* krb = rr ? g_krN : g_krI;
            const float* vrb = rr ? g_vrN : g_vrI;
            int base = (rr ? SOFF3 : SOFF1) + d;
            int st = g_off[base], n = g_cnt[base];
            float pf = prel[rel * 8 + h] * 0.25f;
            float es = 0.f, a0 = 0.f, a1 = 0.f, a2 = 0.f, a3 = 0.f;
            for (int i = 0; i < n; i++) {
                int s = g_csr[st + i];
                float4 kv = *reinterpret_cast<const float4*>(&krb[(size_t)s * CDIM + lane * 4]);
                float dot = qv.x * kv.x + qv.y * kv.y + qv.z * kv.z + qv.w * kv.w;
                dot += __shfl_xor_sync(0xffffffff, dot, 1);
                dot += __shfl_xor_sync(0xffffffff, dot, 2);
                float e = __expf(dot * pf);
                float4 vv = *reinterpret_cast<const float4*>(&vrb[(size_t)s * CDIM + lane * 4]);
                es += e;
                a0 += e * vv.x; a1 += e * vv.y; a2 += e * vv.z; a3 += e * vv.w;
            }
            if (n > 0) {
                float inv = 1.0f / es;
                ax += a0 * inv; ay += a1 * inv; az += a2 * inv; aw2 += a3 * inv;
            }
        }
        float v0 = geluf(ax), v1 = geluf(ay), v2 = geluf(az), v3 = geluf(aw2);
        uint32_t h0, l0, h1, l1;
        split_pair(v0, v1, h0, l0);
        split_pair(v2, v3, h1, l1);
        *reinterpret_cast<uint2*>(&g_gh[(size_t)d * 64 + lane * 2]) = make_uint2(h0, h1);
        *reinterpret_cast<uint2*>(&g_gl[(size_t)d * 64 + lane * 2]) = make_uint2(l0, l1);
    } else {
        int bb = b - EPB;
        int base;
        size_t nodeoff;
        const float *krb, *vrb;
        float pf;
        if (bb < NICD) {
            base = SOFF0 + bb;
            nodeoff = (size_t)(NPAT + bb);
            krb = g_krP0; vrb = g_vrP0;
            pf = prel[0 * 8 + h] * 0.25f;
        } else {
            int d = bb - NICD;
            base = SOFF2 + d;
            nodeoff = (size_t)(NPAT + NICD + d);
            krb = g_krP1; vrb = g_vrP1;
            pf = prel[2 * 8 + h] * 0.25f;
        }
        float4 qv = *reinterpret_cast<const float4*>(&g_q[nodeoff * CDIM + lane * 4]);
        int st = g_off[base], n = g_cnt[base];
        float es = 0.f, a0 = 0.f, a1 = 0.f, a2 = 0.f, a3 = 0.f;
        for (int i = w; i < n; i += 8) {
            int s = g_csr[st + i];
            float4 kv = *reinterpret_cast<const float4*>(&krb[(size_t)s * CDIM + lane * 4]);
            float dot = qv.x * kv.x + qv.y * kv.y + qv.z * kv.z + qv.w * kv.w;
            dot += __shfl_xor_sync(0xffffffff, dot, 1);
            dot += __shfl_xor_sync(0xffffffff, dot, 2);
            float e = __expf(dot * pf);
            float4 vv = *reinterpret_cast<const float4*>(&vrb[(size_t)s * CDIM + lane * 4]);
            es += e;
            a0 += e * vv.x; a1 += e * vv.y; a2 += e * vv.z; a3 += e * vv.w;
        }
        *reinterpret_cast<float4*>(&sacc[w][lane * 4]) = make_float4(a0, a1, a2, a3);
        if ((lane & 3) == 0) ses[w][h] = es;
        __syncthreads();
        if (tid < 64) {
            int col0 = 2 * tid;
            float s0 = 0.f, s1 = 0.f, e = 0.f;
#pragma unroll
            for (int ww = 0; ww < 8; ww++) {
                s0 += sacc[ww][col0];
                s1 += sacc[ww][col0 + 1];
                e  += ses[ww][tid >> 3];
            }
            float v0 = (e > 0.f) ? s0 / e : 0.0f;
            float v1 = (e > 0.f) ? s1 / e : 0.0f;
            v0 = geluf(v0); v1 = geluf(v1);
            uint32_t hh, ll;
            split_pair(v0, v1, hh, ll);
            g_gh[nodeoff * 64 + tid] = hh;
            g_gl[nodeoff * 64 + tid] = ll;
        }
    }
}

// ---------------- merged per-relation K/V transform ----------------
struct ReltAll {
    const float* A[4];
    const float* Mw[4];
};
__global__ __launch_bounds__(128) void relt_all(ReltAll ra)
{
    __shared__ float ks[32][128];
    __shared__ float vs[32][128];
    const int tid = threadIdx.x;
    const int bx = blockIdx.x;
    const int h = tid >> 4;
    const int e = tid & 15;

    int node0, nsrc, srcoff;
    const float *A0, *M0, *A1, *M1;
    float *kr0, *vr0, *kr1, *vr1;
    bool two;
    if (bx < RTP) {
        node0 = bx * 32; nsrc = NPAT; srcoff = 0; two = true;
        A0 = ra.A[0]; M0 = ra.Mw[0]; A1 = ra.A[2]; M1 = ra.Mw[2];
        kr0 = g_krP0; vr0 = g_vrP0; kr1 = g_krP1; vr1 = g_vrP1;
    } else if (bx < RTP + RTI) {
        node0 = (bx - RTP) * 32; nsrc = NICD; srcoff = NPAT; two = false;
        A0 = ra.A[1]; M0 = ra.Mw[1]; A1 = nullptr; M1 = nullptr;
        kr0 = g_krI; vr0 = g_vrI; kr1 = nullptr; vr1 = nullptr;
    } else {
        node0 = (bx - RTP - RTI) * 32; nsrc = NNDC; srcoff = NPAT + NICD; two = false;
        A0 = ra.A[3]; M0 = ra.Mw[3]; A1 = nullptr; M1 = nullptr;
        kr0 = g_krN; vr0 = g_vrN; kr1 = nullptr; vr1 = nullptr;
    }

    float areg0[16], mreg0[16], areg1[16], mreg1[16];
#pragma unroll
    for (int d = 0; d < 16; d++) {
        areg0[d] = A0[(h * 16 + d) * 16 + e];
        mreg0[d] = M0[(h * 16 + d) * 16 + e];
        if (two) {
            areg1[d] = A1[(h * 16 + d) * 16 + e];
            mreg1[d] = M1[(h * 16 + d) * 16 + e];
        }
    }

    const float* kbase = g_k + (size_t)srcoff * CDIM;
    const float* vbase = g_v + (size_t)srcoff * CDIM;
    for (int i = tid; i < 32 * 32; i += 128) {
        int r = i >> 5;
        int cidx = (i & 31) * 4;
        if (node0 + r < nsrc) {
            *reinterpret_cast<float4*>(&ks[r][cidx]) =
                *reinterpret_cast<const float4*>(&kbase[(size_t)(node0 + r) * CDIM + cidx]);
            *reinterpret_cast<float4*>(&vs[r][cidx]) =
                *reinterpret_cast<const float4*>(&vbase[(size_t)(node0 + r) * CDIM + cidx]);
        }
    }
    __syncthreads();

    int nmax = nsrc - node0; if (nmax > 32) nmax = 32;
    for (int n = 0; n < nmax; n++) {
        float acck0 = 0.f, accv0 = 0.f, acck1 = 0.f, accv1 = 0.f;
#pragma unroll
        for (int d4 = 0; d4 < 4; d4++) {
            float4 kq = *reinterpret_cast<const float4*>(&ks[n][h * 16 + d4 * 4]);
            float4 vq = *reinterpret_cast<const float4*>(&vs[n][h * 16 + d4 * 4]);
            float kk[4] = {kq.x, kq.y, kq.z, kq.w};
            float vv[4] = {vq.x, vq.y, vq.z, vq.w};
#pragma unroll
            for (int j = 0; j < 4; j++) {
                int d = d4 * 4 + j;
                acck0 = fmaf(kk[j], areg0[d], acck0);
                accv0 = fmaf(vv[j], mreg0[d], accv0);
                if (two) {
                    acck1 = fmaf(kk[j], areg1[d], acck1);
                    accv1 = fmaf(vv[j], mreg1[d], accv1);
                }
            }
        }
        size_t o = (size_t)(node0 + n) * CDIM + h * 16 + e;
        kr0[o] = acck0; vr0[o] = accv0;
        if (two) { kr1[o] = acck1; vr1[o] = accv1; }
    }
}

// ---------------- host ----------------
extern "C" void kernel_launch(void* const* d_in, const int* in_sizes, int n_in,
                              void* d_out, int out_size)
{
    const float* x_patient = (const float*)d_in[0];
    const float* w_in      = (const float*)d_in[1];
    const float* b_in      = (const float*)d_in[2];
    const float* emb_icd   = (const float*)d_in[3];
    const float* emb_ndc   = (const float*)d_in[4];
    const float* kw = (const float*)d_in[5];
    const float* kb = (const float*)d_in[6];
    const float* qw = (const float*)d_in[7];
    const float* qb = (const float*)d_in[8];
    const float* vw = (const float*)d_in[9];
    const float* vb = (const float*)d_in[10];
    const float* aw = (const float*)d_in[11];
    const float* ab = (const float*)d_in[12];
    const float* skip  = (const float*)d_in[13];
    const float* a_rel = (const float*)d_in[14];
    const float* m_rel = (const float*)d_in[15];
    const float* p_rel = (const float*)d_in[16];
    const float* w_out = (const float*)d_in[17];
    const float* b_out = (const float*)d_in[18];
    const int* x_icd = (const int*)d_in[19];
    const int* x_ndc = (const int*)d_in[20];
    const int* esrc[4] = {(const int*)d_in[21], (const int*)d_in[23],
                          (const int*)d_in[25], (const int*)d_in[27]};
    const int* edst[4] = {(const int*)d_in[22], (const int*)d_in[24],
                          (const int*)d_in[26], (const int*)d_in[28]};
    float* out = (float*)d_out;

    // non-blocking second stream (blocking streams serialize against the legacy
    // NULL stream — this was suppressing all overlap in the previous revision)
    cudaStream_t s2;
    cudaStreamCreateWithFlags(&s2, cudaStreamNonBlocking);
    cudaEvent_t evFork, evCsr, evX0, evX1, evQ0, evQ1;
    cudaEventCreateWithFlags(&evFork, cudaEventDisableTiming);
    cudaEventCreateWithFlags(&evCsr,  cudaEventDisableTiming);
    cudaEventCreateWithFlags(&evX0,   cudaEventDisableTiming);
    cudaEventCreateWithFlags(&evX1,   cudaEventDisableTiming);
    cudaEventCreateWithFlags(&evQ0,   cudaEventDisableTiming);
    cudaEventCreateWithFlags(&evQ1,   cudaEventDisableTiming);
    cudaEvent_t evX[2] = {evX0, evX1};
    cudaEvent_t evQ[2] = {evQ0, evQ1};

    // ---- fork CSR build onto s2 ----
    cudaEventRecord(evFork, 0);
    cudaStreamWaitEvent(s2, evFork, 0);
    csr_clear<<<(NSOFT + 255) / 256, 256, 0, s2>>>();
    csr_hist_pat<<<(NEDGE / 4 + 255) / 256, 256, 0, s2>>>(edst[1], edst[3]);
    {
        dim3 gh(48, 2);
        csr_hist_sm<<<gh, 256, 0, s2>>>(edst[0], edst[2]);
    }
    scan_partial<<<NSCB, 256, 0, s2>>>();
    scan_base<<<1, 128, 0, s2>>>();
    scan_write<<<NSCB, 256, 0, s2>>>();
    csr_scatter_pat<<<(NEDGE + 255) / 256, 256, 0, s2>>>(esrc[1], edst[1], esrc[3], edst[3]);
    {
        dim3 gs(64, 2);
        csr_scatter_sm<<<gs, 256, 0, s2>>>(esrc[0], edst[0], esrc[2], edst[2]);
    }
    cudaEventRecord(evCsr, s2);

    // ---- main stream: weights / inputs / in-proj ----
    {
        WSplit ws;
        ws.src[0] = w_in; ws.nn[0] = CDIM;
        const float* wsrc[3] = {kw, qw, vw};
        for (int l = 0; l < 2; l++)
            for (int j = 0; j < 3; j++)
                for (int ty = 0; ty < 3; ty++) {
                    ws.src[1 + l * 9 + j * 3 + ty] = wsrc[j] + (size_t)(l * 3 + ty) * CDIM * CDIM;
                    ws.nn[1 + l * 9 + j * 3 + ty] = CDIM;
                }
        for (int l = 0; l < 2; l++)
            for (int ty = 0; ty < 3; ty++) {
                ws.src[19 + l * 3 + ty] = aw + (size_t)(l * 3 + ty) * CDIM * CDIM;
                ws.nn[19 + l * 3 + ty] = CDIM;
            }
        ws.src[25] = w_out; ws.nn[25] = OUTD;
        dim3 g(32, NWMAT);
        split_weights<<<g, 256>>>(ws);
    }
    prep_inputs<<<(NTOTAL * 64 + 255) / 256, 256>>>(x_patient, emb_icd, x_icd, emb_ndc, x_ndc);
    {
        dim3 g(NBP, 2);
        gemm_in<<<g, 256>>>(b_in);
    }

    for (int l = 0; l < 2; l++) {
        // x ready -> fork Q GEMM onto s2
        cudaEventRecord(evX[l], 0);
        cudaStreamWaitEvent(s2, evX[l], 0);
        {
            dim3 gq(NBALL, 1, 2);
            gemm_kqv<<<gq, 256, 0, s2>>>(kb, qb, vb, l, 1);   // Q
        }
        cudaEventRecord(evQ[l], s2);

        // main: K and V, then relation transforms (overlaps Q)
        {
            dim3 gkv(NBALL, 2, 2);
            gemm_kqv<<<gkv, 256>>>(kb, qb, vb, l, 0);         // K, V
        }
        {
            ReltAll ra;
            for (int r = 0; r < 4; r++) {
                ra.A[r]  = a_rel + (size_t)(l * 4 + r) * HH * DD * DD;
                ra.Mw[r] = m_rel + (size_t)(l * 4 + r) * HH * DD * DD;
            }
            relt_all<<<RTALL, 128>>>(ra);
        }

        // join: edge needs Q (s2) and, on layer 0, the CSR build (s2)
        cudaStreamWaitEvent(0, evQ[l], 0);
        if (l == 0) cudaStreamWaitEvent(0, evCsr, 0);

        edge_fused<<<EALL, 256>>>(p_rel + l * 32);

        {
            dim3 grid(NBALL, 2);
            gemm_ap<<<grid, 256>>>(ab, skip, l);
        }
    }

    // output projection + sigmoid
    {
        dim3 g(NBP, 2);
        gemm_o<<<g, 256>>>(b_out, out);
    }

    cudaEventDestroy(evFork);
    cudaEventDestroy(evCsr);
    cudaEventDestroy(evX0);
    cudaEventDestroy(evX1);
    cudaEventDestroy(evQ0);
    cudaEventDestroy(evQ1);
    cudaStreamDestroy(s2);
}

// round 14
// speedup vs baseline: 2.4381x; 1.0927x over previous
#include <cuda_runtime.h>
#include <cuda_fp16.h>
#include <math.h>
#include <stdint.h>

#define NPAT 50000
#define NICD 591
#define NNDC 2042
#define NTOTAL 52633
#define NSOFT 102633
#define CDIM 128
#define HH 8
#define DD 16
#define NEDGE 250000
#define OUTD 90

#define SOFF0 0
#define SOFF1 NICD
#define SOFF2 (NICD + NPAT)
#define SOFF3 (NICD + NPAT + NNDC)

#define NBP 391
#define NBI 5
#define NBN 16
#define NBALL (NBP + NBI + NBN)

#define RTP 1563
#define RTI 19
#define RTN 64
#define RTALL (RTP + RTI + RTN)

#define EPB 6250
#define EBLK (NICD + NNDC)
#define EALL (EPB + EBLK)

#define NWMAT 26

#define SCAN_TILE 1024
#define NSCB ((NSOFT + SCAN_TILE - 1) / SCAN_TILE)

// ---------------- scratch ----------------
__device__ float g_x[NTOTAL * CDIM];
__device__ float g_k[NTOTAL * CDIM];
__device__ float g_q[NTOTAL * CDIM];
__device__ float g_v[NTOTAL * CDIM];
// fp16 relation-transformed K/V (halves edge gather traffic; edge phase was LTS-bound)
__device__ __half g_krP0[NPAT * CDIM];
__device__ __half g_vrP0[NPAT * CDIM];
__device__ __half g_krP1[NPAT * CDIM];
__device__ __half g_vrP1[NPAT * CDIM];
__device__ __half g_krI[NICD * CDIM];
__device__ __half g_vrI[NICD * CDIM];
__device__ __half g_krN[NNDC * CDIM];
__device__ __half g_vrN[NNDC * CDIM];
__device__ uint32_t g_xh[NTOTAL * 64];
__device__ uint32_t g_xl[NTOTAL * 64];
__device__ uint32_t g_gh[NTOTAL * 64];
__device__ uint32_t g_gl[NTOTAL * 64];
__device__ uint32_t g_wh[NWMAT * 8192];
__device__ uint32_t g_wl[NWMAT * 8192];
__device__ int g_cnt[NSOFT];
__device__ int g_off[NSOFT];
__device__ int g_cur[NSOFT];
__device__ int g_csr[4 * NEDGE];
__device__ int g_bsum[NSCB];
__device__ int g_bbase[NSCB];

__device__ __forceinline__ float geluf(float x) {
    float t = tanhf(0.7978845608028654f * (x + 0.044715f * x * x * x));
    return 0.5f * x * (1.0f + t);
}

__device__ __forceinline__ void split_pair(float v0, float v1, uint32_t& h, uint32_t& l) {
    uint32_t hh;
    asm("cvt.rn.bf16x2.f32 %0, %1, %2;" : "=r"(hh) : "f"(v1), "f"(v0));
    float h0 = __uint_as_float(hh << 16);
    float h1 = __uint_as_float(hh & 0xffff0000u);
    float l0 = v0 - h0;
    float l1 = v1 - h1;
    uint32_t ll;
    asm("cvt.rn.bf16x2.f32 %0, %1, %2;" : "=r"(ll) : "f"(l1), "f"(l0));
    h = hh; l = ll;
}

__device__ __forceinline__ void mma_bf16(float* c, const uint32_t* a, const uint32_t* b) {
    asm volatile("mma.sync.aligned.m16n8k16.row.col.f32.bf16.bf16.f32 "
                 "{%0,%1,%2,%3}, {%4,%5,%6,%7}, {%8,%9}, {%0,%1,%2,%3};"
                 : "+f"(c[0]), "+f"(c[1]), "+f"(c[2]), "+f"(c[3])
                 : "r"(a[0]), "r"(a[1]), "r"(a[2]), "r"(a[3]),
                   "r"(b[0]), "r"(b[1]));
}

// ---------------- pre-split weights ----------------
struct WSplit { const float* src[NWMAT]; int nn[NWMAT]; };
__global__ void split_weights(WSplit ws) {
    int m = blockIdx.y;
    int idx = blockIdx.x * 256 + threadIdx.x;
    int kp = idx >> 7, n = idx & 127;
    const float* s = ws.src[m];
    int N = ws.nn[m];
    float v0 = (n < N) ? s[(size_t)(2 * kp) * N + n] : 0.0f;
    float v1 = (n < N) ? s[(size_t)(2 * kp + 1) * N + n] : 0.0f;
    uint32_t h, l;
    split_pair(v0, v1, h, l);
    g_wh[m * 8192 + idx] = h;
    g_wl[m * 8192 + idx] = l;
}

// ---------------- input prep ----------------
__global__ void prep_inputs(const float* __restrict__ xp,
                            const float* __restrict__ ei, const int* __restrict__ xi,
                            const float* __restrict__ en, const int* __restrict__ xn) {
    int idx = blockIdx.x * 256 + threadIdx.x;
    const int n1 = NPAT * 64;
    const int n2 = n1 + NICD * 64;
    const int n3 = n2 + NNDC * 64;
    if (idx < n1) {
        int node = idx >> 6, kp = idx & 63;
        float2 v = *reinterpret_cast<const float2*>(&xp[(size_t)node * CDIM + 2 * kp]);
        uint32_t h, l;
        split_pair(v.x, v.y, h, l);
        g_gh[idx] = h; g_gl[idx] = l;
    } else if (idx < n3) {
        int j, node;
        const float* emb;
        const int* map;
        if (idx < n2) { j = idx - n1; emb = ei; map = xi; node = NPAT + (j >> 6); }
        else          { j = idx - n2; emb = en; map = xn; node = NPAT + NICD + (j >> 6); }
        int r = j >> 6, kp = j & 63;
        float2 v = *reinterpret_cast<const float2*>(&emb[(size_t)map[r] * CDIM + 2 * kp]);
        v.x = fmaxf(v.x, 0.0f);
        v.y = fmaxf(v.y, 0.0f);
        g_x[(size_t)node * CDIM + 2 * kp] = v.x;
        g_x[(size_t)node * CDIM + 2 * kp + 1] = v.y;
        uint32_t h, l;
        split_pair(v.x, v.y, h, l);
        g_xh[(size_t)node * 64 + kp] = h;
        g_xl[(size_t)node * 64 + kp] = l;
    }
}

// ---------------- GEMM body (pre-split operands) ----------------
template<int MODE>
__device__ __forceinline__ void gemm_body(
    const uint32_t* __restrict__ XH, const uint32_t* __restrict__ XL,
    const uint32_t* __restrict__ WH, const uint32_t* __restrict__ WL,
    const float* __restrict__ bias,
    float* __restrict__ OutF, int ldo,
    uint32_t* __restrict__ OutH, uint32_t* __restrict__ OutL,
    const float* __restrict__ skipPtr, const float* __restrict__ xold,
    int M, int row0, int ncol0)
{
    __shared__ uint32_t Ah[128][20];
    __shared__ uint32_t Al[128][20];
    __shared__ uint32_t Bh[16][72];
    __shared__ uint32_t Bl[16][72];

    const int tid = threadIdx.x;
    const int lane = tid & 31;
    const int wid = tid >> 5;
    const int warp_m = wid >> 1;
    const int warp_n = wid & 1;
    const int gi = lane >> 2;
    const int tig = lane & 3;

    float c[2][4][4];
#pragma unroll
    for (int am = 0; am < 2; am++)
#pragma unroll
        for (int an = 0; an < 4; an++)
#pragma unroll
            for (int j = 0; j < 4; j++) c[am][an][j] = 0.0f;

    const int ar = tid >> 1;
    const int akh = tid & 1;
    const bool aok = (row0 + ar) < M;
    const int bkp = tid >> 4;
    const int nl0 = (tid & 15) * 4;

    for (int kc2 = 0; kc2 < 64; kc2 += 16) {
        uint4 ha = make_uint4(0, 0, 0, 0), hb = ha, la = ha, lb = ha;
        if (aok) {
            const uint32_t* ph = &XH[(size_t)(row0 + ar) * 64 + kc2 + akh * 8];
            const uint32_t* pl = &XL[(size_t)(row0 + ar) * 64 + kc2 + akh * 8];
            ha = *reinterpret_cast<const uint4*>(ph);
            hb = *reinterpret_cast<const uint4*>(ph + 4);
            la = *reinterpret_cast<const uint4*>(pl);
            lb = *reinterpret_cast<const uint4*>(pl + 4);
        }
        *reinterpret_cast<uint4*>(&Ah[ar][akh * 8]) = ha;
        *reinterpret_cast<uint4*>(&Ah[ar][akh * 8 + 4]) = hb;
        *reinterpret_cast<uint4*>(&Al[ar][akh * 8]) = la;
        *reinterpret_cast<uint4*>(&Al[ar][akh * 8 + 4]) = lb;
        *reinterpret_cast<uint4*>(&Bh[bkp][nl0]) =
            *reinterpret_cast<const uint4*>(&WH[(size_t)(kc2 + bkp) * 128 + ncol0 + nl0]);
        *reinterpret_cast<uint4*>(&Bl[bkp][nl0]) =
            *reinterpret_cast<const uint4*>(&WL[(size_t)(kc2 + bkp) * 128 + ncol0 + nl0]);
        __syncthreads();

#pragma unroll
        for (int ks = 0; ks < 2; ks++) {
            const int kb = ks * 8;
            uint32_t ah[2][4], al[2][4];
#pragma unroll
            for (int am = 0; am < 2; am++) {
                int rb = warp_m * 32 + am * 16 + gi;
                ah[am][0] = Ah[rb][kb + tig];
                ah[am][1] = Ah[rb + 8][kb + tig];
                ah[am][2] = Ah[rb][kb + 4 + tig];
                ah[am][3] = Ah[rb + 8][kb + 4 + tig];
                al[am][0] = Al[rb][kb + tig];
                al[am][1] = Al[rb + 8][kb + tig];
                al[am][2] = Al[rb][kb + 4 + tig];
                al[am][3] = Al[rb + 8][kb + 4 + tig];
            }
#pragma unroll
            for (int an = 0; an < 4; an++) {
                int nc = warp_n * 32 + an * 8 + gi;
                uint32_t bh[2], bl[2];
                bh[0] = Bh[kb + tig][nc];
                bh[1] = Bh[kb + 4 + tig][nc];
                bl[0] = Bl[kb + tig][nc];
                bl[1] = Bl[kb + 4 + tig][nc];
#pragma unroll
                for (int am = 0; am < 2; am++) {
                    mma_bf16(c[am][an], ah[am], bh);
                    mma_bf16(c[am][an], al[am], bh);
                    mma_bf16(c[am][an], ah[am], bl);
                }
            }
        }
        __syncthreads();
    }

    float sa = 0.f, sb = 0.f;
    if (MODE == 2) {
        float s = 1.0f / (1.0f + __expf(-*skipPtr));
        sa = s; sb = 1.0f - s;
    }
#pragma unroll
    for (int am = 0; am < 2; am++) {
#pragma unroll
        for (int an = 0; an < 4; an++) {
            int col = ncol0 + warp_n * 32 + an * 8 + tig * 2;
#pragma unroll
            for (int half = 0; half < 2; half++) {
                int row = row0 + warp_m * 32 + am * 16 + gi + half * 8;
                if (row >= M) continue;
                float b0 = (MODE == 3) ? ((col < OUTD) ? bias[col] : 0.0f) : bias[col];
                float b1 = (MODE == 3) ? ((col + 1 < OUTD) ? bias[col + 1] : 0.0f) : bias[col + 1];
                float v0 = c[am][an][half * 2 + 0] + b0;
                float v1 = c[am][an][half * 2 + 1] + b1;
                if (MODE == 1) { v0 = fmaxf(v0, 0.0f); v1 = fmaxf(v1, 0.0f); }
                else if (MODE == 2) {
                    v0 = sa * v0 + sb * xold[(size_t)row * CDIM + col];
                    v1 = sa * v1 + sb * xold[(size_t)row * CDIM + col + 1];
                } else if (MODE == 3) {
                    v0 = 1.0f / (1.0f + __expf(-v0));
                    v1 = 1.0f / (1.0f + __expf(-v1));
                }
                if (MODE == 3) {
                    if (col < OUTD)     OutF[(size_t)row * ldo + col] = v0;
                    if (col + 1 < OUTD) OutF[(size_t)row * ldo + col + 1] = v1;
                } else {
                    OutF[(size_t)row * CDIM + col] = v0;
                    OutF[(size_t)row * CDIM + col + 1] = v1;
                    if (MODE == 1 || MODE == 2) {
                        uint32_t h, l;
                        split_pair(v0, v1, h, l);
                        OutH[(size_t)row * 64 + (col >> 1)] = h;
                        OutL[(size_t)row * 64 + (col >> 1)] = l;
                    }
                }
            }
        }
    }
}

// ---------------- GEMM wrappers ----------------
__global__ __launch_bounds__(256, 4) void gemm_in(const float* __restrict__ bias)
{
    gemm_body<1>(g_gh, g_gl, g_wh, g_wl, bias,
                 g_x, CDIM, g_xh, g_xl, nullptr, nullptr,
                 NPAT, blockIdx.x * 128, blockIdx.y * 64);
}

__global__ __launch_bounds__(256, 4) void gemm_kqv(
    const float* __restrict__ kb, const float* __restrict__ qb,
    const float* __restrict__ vb, int l, int jmode)
{
    const int bx = blockIdx.x;
    int ty, bl;
    if (bx < NBP)            { ty = 0; bl = bx; }
    else if (bx < NBP + NBI) { ty = 1; bl = bx - NBP; }
    else                     { ty = 2; bl = bx - NBP - NBI; }
    const int M = (ty == 0) ? NPAT : (ty == 1) ? NICD : NNDC;
    const int toff = (ty == 0) ? 0 : (ty == 1) ? NPAT : NPAT + NICD;
    const int j = (jmode == 0) ? (blockIdx.y == 0 ? 0 : 2) : 1;
    const int widx = 1 + l * 9 + j * 3 + ty;
    const float* bias = ((j == 0) ? kb : (j == 1) ? qb : vb) + (size_t)(l * 3 + ty) * CDIM;
    float* outp = ((j == 0) ? g_k : (j == 1) ? g_q : g_v) + (size_t)toff * CDIM;
    gemm_body<0>(g_xh + (size_t)toff * 64, g_xl + (size_t)toff * 64,
                 g_wh + (size_t)widx * 8192, g_wl + (size_t)widx * 8192, bias,
                 outp, CDIM, nullptr, nullptr, nullptr, nullptr,
                 M, bl * 128, blockIdx.z * 64);
}

__global__ __launch_bounds__(256, 4) void gemm_ap(
    const float* __restrict__ ab, const float* __restrict__ skip, int l)
{
    const int bx = blockIdx.x;
    int ty, bl;
    if (bx < NBP)            { ty = 0; bl = bx; }
    else if (bx < NBP + NBI) { ty = 1; bl = bx - NBP; }
    else                     { ty = 2; bl = bx - NBP - NBI; }
    const int M = (ty == 0) ? NPAT : (ty == 1) ? NICD : NNDC;
    const int toff = (ty == 0) ? 0 : (ty == 1) ? NPAT : NPAT + NICD;
    const int widx = 19 + l * 3 + ty;
    gemm_body<2>(g_gh + (size_t)toff * 64, g_gl + (size_t)toff * 64,
                 g_wh + (size_t)widx * 8192, g_wl + (size_t)widx * 8192,
                 ab + (size_t)(l * 3 + ty) * CDIM,
                 g_x + (size_t)toff * CDIM, CDIM,
                 g_xh + (size_t)toff * 64, g_xl + (size_t)toff * 64,
                 skip + (l * 3 + ty), g_x + (size_t)toff * CDIM,
                 M, bl * 128, blockIdx.y * 64);
}

__global__ __launch_bounds__(256, 4) void gemm_o(
    const float* __restrict__ bias, float* __restrict__ out)
{
    gemm_body<3>(g_xh, g_xl, g_wh + (size_t)25 * 8192, g_wl + (size_t)25 * 8192, bias,
                 out, OUTD, nullptr, nullptr, nullptr, nullptr,
                 NPAT, blockIdx.x * 128, blockIdx.y * 64);
}

// ---------------- CSR build ----------------
__global__ void csr_clear() {
    int i = blockIdx.x * blockDim.x + threadIdx.x;
    if (i < NSOFT) { g_cnt[i] = 0; g_cur[i] = 0; }
}

__global__ void csr_hist_pat(const int* __restrict__ d1, const int* __restrict__ d3) {
    int i = blockIdx.x * blockDim.x + threadIdx.x;
    if (i < NEDGE / 4) {
        int4 a = reinterpret_cast<const int4*>(d1)[i];
        atomicAdd(&g_cnt[SOFF1 + a.x], 1);
        atomicAdd(&g_cnt[SOFF1 + a.y], 1);
        atomicAdd(&g_cnt[SOFF1 + a.z], 1);
        atomicAdd(&g_cnt[SOFF1 + a.w], 1);
        int4 b = reinterpret_cast<const int4*>(d3)[i];
        atomicAdd(&g_cnt[SOFF3 + b.x], 1);
        atomicAdd(&g_cnt[SOFF3 + b.y], 1);
        atomicAdd(&g_cnt[SOFF3 + b.z], 1);
        atomicAdd(&g_cnt[SOFF3 + b.w], 1);
    }
}

__global__ __launch_bounds__(256) void csr_hist_sm(const int* __restrict__ dst0,
                                                   const int* __restrict__ dst2) {
    __shared__ int h[NNDC];
    const int r = blockIdx.y;
    const int ndst = r ? NNDC : NICD;
    const int so = r ? SOFF2 : SOFF0;
    const int* __restrict__ dst = r ? dst2 : dst0;
    for (int i = threadIdx.x; i < ndst; i += 256) h[i] = 0;
    __syncthreads();
    const int tot = NEDGE / 4;
    for (int i = blockIdx.x * 256 + threadIdx.x; i < tot; i += gridDim.x * 256) {
        int4 a = reinterpret_cast<const int4*>(dst)[i];
        atomicAdd(&h[a.x], 1); atomicAdd(&h[a.y], 1);
        atomicAdd(&h[a.z], 1); atomicAdd(&h[a.w], 1);
    }
    __syncthreads();
    for (int i = threadIdx.x; i < ndst; i += 256)
        if (h[i]) atomicAdd(&g_cnt[so + i], h[i]);
}

__global__ __launch_bounds__(256) void scan_partial() {
    __shared__ int red[256];
    const int base = blockIdx.x * SCAN_TILE;
    int sum = 0;
#pragma unroll
    for (int j = 0; j < 4; j++) {
        int idx = base + j * 256 + threadIdx.x;
        sum += (idx < NSOFT) ? g_cnt[idx] : 0;
    }
    red[threadIdx.x] = sum;
    __syncthreads();
    for (int d = 128; d > 0; d >>= 1) {
        if (threadIdx.x < d) red[threadIdx.x] += red[threadIdx.x + d];
        __syncthreads();
    }
    if (threadIdx.x == 0) g_bsum[blockIdx.x] = red[0];
}

__global__ __launch_bounds__(128) void scan_base() {
    __shared__ int tmp[NSCB];
    int t = threadIdx.x;
    if (t < NSCB) tmp[t] = g_bsum[t];
    __syncthreads();
    if (t == 0) {
        int acc = 0;
        for (int i = 0; i < NSCB; i++) { int v = tmp[i]; tmp[i] = acc; acc += v; }
    }
    __syncthreads();
    if (t < NSCB) g_bbase[t] = tmp[t];
}

__global__ __launch_bounds__(256) void scan_write() {
    __shared__ int wsum[8];
    const int base = blockIdx.x * SCAN_TILE;
    const int t = threadIdx.x;
    const int lane = t & 31;
    const int w = t >> 5;
    int v[4];
    const int idx0 = base + t * 4;
#pragma unroll
    for (int j = 0; j < 4; j++) {
        int idx = idx0 + j;
        v[j] = (idx < NSOFT) ? g_cnt[idx] : 0;
    }
    int s1 = v[0] + v[1];
    int s2 = s1 + v[2];
    int tot = s2 + v[3];
    int x = tot;
#pragma unroll
    for (int d = 1; d < 32; d <<= 1) {
        int y = __shfl_up_sync(0xffffffff, x, d);
        if (lane >= d) x += y;
    }
    if (lane == 31) wsum[w] = x;
    __syncthreads();
    if (w == 0 && lane < 8) {
        int orig = wsum[lane];
        int ws = orig;
#pragma unroll
        for (int d = 1; d < 8; d <<= 1) {
            int y = __shfl_up_sync(0xff, ws, d);
            if (lane >= d) ws += y;
        }
        wsum[lane] = ws - orig;
    }
    __syncthreads();
    int ebase = g_bbase[blockIdx.x] + wsum[w] + (x - tot);
    int offs[4] = {0, v[0], s1, s2};
#pragma unroll
    for (int j = 0; j < 4; j++) {
        int idx = idx0 + j;
        if (idx < NSOFT) g_off[idx] = ebase + offs[j];
    }
}

__global__ void csr_scatter_pat(const int* __restrict__ s1, const int* __restrict__ d1,
                                const int* __restrict__ s3, const int* __restrict__ d3) {
    int i = blockIdx.x * blockDim.x + threadIdx.x;
    if (i < NEDGE) {
        int b1 = SOFF1 + d1[i];
        g_csr[g_off[b1] + atomicAdd(&g_cur[b1], 1)] = s1[i];
        int b3 = SOFF3 + d3[i];
        g_csr[g_off[b3] + atomicAdd(&g_cur[b3], 1)] = s3[i];
    }
}

__global__ __launch_bounds__(256) void csr_scatter_sm(
    const int* __restrict__ src0, const int* __restrict__ dst0,
    const int* __restrict__ src2, const int* __restrict__ dst2) {
    __shared__ int h[NNDC];
    __shared__ int base[NNDC];
    const int r = blockIdx.y;
    const int ndst = r ? NNDC : NICD;
    const int so = r ? SOFF2 : SOFF0;
    const int* __restrict__ dst = r ? dst2 : dst0;
    const int* __restrict__ src = r ? src2 : src0;
    const int chunk = (NEDGE + gridDim.x - 1) / gridDim.x;
    const int e0 = blockIdx.x * chunk;
    int e1 = e0 + chunk; if (e1 > NEDGE) e1 = NEDGE;

    for (int i = threadIdx.x; i < ndst; i += 256) h[i] = 0;
    __syncthreads();
    for (int e = e0 + threadIdx.x; e < e1; e += 256) atomicAdd(&h[dst[e]], 1);
    __syncthreads();
    for (int i = threadIdx.x; i < ndst; i += 256) {
        int cc = h[i];
        base[i] = cc ? atomicAdd(&g_cur[so + i], cc) : 0;
    }
    __syncthreads();
    for (int i = threadIdx.x; i < ndst; i += 256) h[i] = 0;
    __syncthreads();
    for (int e = e0 + threadIdx.x; e < e1; e += 256) {
        int d = dst[e];
        int loc = atomicAdd(&h[d], 1);
        g_csr[g_off[so + d] + base[d] + loc] = src[e];
    }
}

// ---------------- fused edge kernel (fp16 kr/vr gathers) ----------------
__device__ __forceinline__ void ld_half4(const __half* p, float& f0, float& f1,
                                         float& f2, float& f3) {
    uint2 raw = *reinterpret_cast<const uint2*>(p);
    float2 a = __half22float2(*reinterpret_cast<const __half2*>(&raw.x));
    float2 b = __half22float2(*reinterpret_cast<const __half2*>(&raw.y));
    f0 = a.x; f1 = a.y; f2 = b.x; f3 = b.y;
}

__global__ __launch_bounds__(256) void edge_fused(const float* __restrict__ prel)
{
    __shared__ float sacc[8][128];
    __shared__ float ses[8][8];
    const int b = blockIdx.x;
    const int tid = threadIdx.x;
    const int w = tid >> 5;
    const int lane = tid & 31;
    const int h = lane >> 2;

    if (b < EPB) {
        int d = b * 8 + w;
        float4 qv = *reinterpret_cast<const float4*>(&g_q[(size_t)d * CDIM + lane * 4]);
        float ax = 0.f, ay = 0.f, az = 0.f, aw2 = 0.f;
#pragma unroll
        for (int rr = 0; rr < 2; rr++) {
            const int rel = rr ? 3 : 1;
            const __half* krb = rr ? g_krN : g_krI;
            const __half* vrb = rr ? g_vrN : g_vrI;
            int base = (rr ? SOFF3 : SOFF1) + d;
            int st = g_off[base], n = g_cnt[base];
            float pf = prel[rel * 8 + h] * 0.25f;
            float es = 0.f, a0 = 0.f, a1 = 0.f, a2 = 0.f, a3 = 0.f;
            for (int i = 0; i < n; i++) {
                int s = g_csr[st + i];
                float k0, k1, k2, k3;
                ld_half4(&krb[(size_t)s * CDIM + lane * 4], k0, k1, k2, k3);
                float dot = qv.x * k0 + qv.y * k1 + qv.z * k2 + qv.w * k3;
                dot += __shfl_xor_sync(0xffffffff, dot, 1);
                dot += __shfl_xor_sync(0xffffffff, dot, 2);
                float e = __expf(dot * pf);
                float v0, v1, v2, v3;
                ld_half4(&vrb[(size_t)s * CDIM + lane * 4], v0, v1, v2, v3);
                es += e;
                a0 += e * v0; a1 += e * v1; a2 += e * v2; a3 += e * v3;
            }
            if (n > 0) {
                float inv = 1.0f / es;
                ax += a0 * inv; ay += a1 * inv; az += a2 * inv; aw2 += a3 * inv;
            }
        }
        float v0 = geluf(ax), v1 = geluf(ay), v2 = geluf(az), v3 = geluf(aw2);
        uint32_t h0, l0, h1, l1;
        split_pair(v0, v1, h0, l0);
        split_pair(v2, v3, h1, l1);
        *reinterpret_cast<uint2*>(&g_gh[(size_t)d * 64 + lane * 2]) = make_uint2(h0, h1);
        *reinterpret_cast<uint2*>(&g_gl[(size_t)d * 64 + lane * 2]) = make_uint2(l0, l1);
    } else {
        int bb = b - EPB;
        int base;
        size_t nodeoff;
        const __half *krb, *vrb;
        float pf;
        if (bb < NICD) {
            base = SOFF0 + bb;
            nodeoff = (size_t)(NPAT + bb);
            krb = g_krP0; vrb = g_vrP0;
            pf = prel[0 * 8 + h] * 0.25f;
        } else {
            int d = bb - NICD;
            base = SOFF2 + d;
            nodeoff = (size_t)(NPAT + NICD + d);
            krb = g_krP1; vrb = g_vrP1;
            pf = prel[2 * 8 + h] * 0.25f;
        }
        float4 qv = *reinterpret_cast<const float4*>(&g_q[nodeoff * CDIM + lane * 4]);
        int st = g_off[base], n = g_cnt[base];
        float es = 0.f, a0 = 0.f, a1 = 0.f, a2 = 0.f, a3 = 0.f;
        for (int i = w; i < n; i += 8) {
            int s = g_csr[st + i];
            float k0, k1, k2, k3;
            ld_half4(&krb[(size_t)s * CDIM + lane * 4], k0, k1, k2, k3);
            float dot = qv.x * k0 + qv.y * k1 + qv.z * k2 + qv.w * k3;
            dot += __shfl_xor_sync(0xffffffff, dot, 1);
            dot += __shfl_xor_sync(0xffffffff, dot, 2);
            float e = __expf(dot * pf);
            float v0, v1, v2, v3;
            ld_half4(&vrb[(size_t)s * CDIM + lane * 4], v0, v1, v2, v3);
            es += e;
            a0 += e * v0; a1 += e * v1; a2 += e * v2; a3 += e * v3;
        }
        *reinterpret_cast<float4*>(&sacc[w][lane * 4]) = make_float4(a0, a1, a2, a3);
        if ((lane & 3) == 0) ses[w][h] = es;
        __syncthreads();
        if (tid < 64) {
            int col0 = 2 * tid;
            float s0 = 0.f, s1 = 0.f, e = 0.f;
#pragma unroll
            for (int ww = 0; ww < 8; ww++) {
                s0 += sacc[ww][col0];
                s1 += sacc[ww][col0 + 1];
                e  += ses[ww][tid >> 3];
            }
            float v0 = (e > 0.f) ? s0 / e : 0.0f;
            float v1 = (e > 0.f) ? s1 / e : 0.0f;
            v0 = geluf(v0); v1 = geluf(v1);
            uint32_t hh, ll;
            split_pair(v0, v1, hh, ll);
            g_gh[nodeoff * 64 + tid] = hh;
            g_gl[nodeoff * 64 + tid] = ll;
        }
    }
}

// ---------------- merged per-relation K/V transform (fp16 outputs) ----------------
struct ReltAll {
    const float* A[4];
    const float* Mw[4];
};
__global__ __launch_bounds__(128) void relt_all(ReltAll ra)
{
    __shared__ float ks[32][128];
    __shared__ float vs[32][128];
    const int tid = threadIdx.x;
    const int bx = blockIdx.x;
    const int h = tid >> 4;
    const int e = tid & 15;

    int node0, nsrc, srcoff;
    const float *A0, *M0, *A1, *M1;
    __half *kr0, *vr0, *kr1, *vr1;
    bool two;
    if (bx < RTP) {
        node0 = bx * 32; nsrc = NPAT; srcoff = 0; two = true;
        A0 = ra.A[0]; M0 = ra.Mw[0]; A1 = ra.A[2]; M1 = ra.Mw[2];
        kr0 = g_krP0; vr0 = g_vrP0; kr1 = g_krP1; vr1 = g_vrP1;
    } else if (bx < RTP + RTI) {
        node0 = (bx - RTP) * 32; nsrc = NICD; srcoff = NPAT; two = false;
        A0 = ra.A[1]; M0 = ra.Mw[1]; A1 = nullptr; M1 = nullptr;
        kr0 = g_krI; vr0 = g_vrI; kr1 = nullptr; vr1 = nullptr;
    } else {
        node0 = (bx - RTP - RTI) * 32; nsrc = NNDC; srcoff = NPAT + NICD; two = false;
        A0 = ra.A[3]; M0 = ra.Mw[3]; A1 = nullptr; M1 = nullptr;
        kr0 = g_krN; vr0 = g_vrN; kr1 = nullptr; vr1 = nullptr;
    }

    float areg0[16], mreg0[16], areg1[16], mreg1[16];
#pragma unroll
    for (int d = 0; d < 16; d++) {
        areg0[d] = A0[(h * 16 + d) * 16 + e];
        mreg0[d] = M0[(h * 16 + d) * 16 + e];
        if (two) {
            areg1[d] = A1[(h * 16 + d) * 16 + e];
            mreg1[d] = M1[(h * 16 + d) * 16 + e];
        }
    }

    const float* kbase = g_k + (size_t)srcoff * CDIM;
    const float* vbase = g_v + (size_t)srcoff * CDIM;
    for (int i = tid; i < 32 * 32; i += 128) {
        int r = i >> 5;
        int cidx = (i & 31) * 4;
        if (node0 + r < nsrc) {
            *reinterpret_cast<float4*>(&ks[r][cidx]) =
                *reinterpret_cast<const float4*>(&kbase[(size_t)(node0 + r) * CDIM + cidx]);
            *reinterpret_cast<float4*>(&vs[r][cidx]) =
                *reinterpret_cast<const float4*>(&vbase[(size_t)(node0 + r) * CDIM + cidx]);
        }
    }
    __syncthreads();

    int nmax = nsrc - node0; if (nmax > 32) nmax = 32;
    for (int n = 0; n < nmax; n++) {
        float acck0 = 0.f, accv0 = 0.f, acck1 = 0.f, accv1 = 0.f;
#pragma unroll
        for (int d4 = 0; d4 < 4; d4++) {
            float4 kq = *reinterpret_cast<const float4*>(&ks[n][h * 16 + d4 * 4]);
            float4 vq = *reinterpret_cast<const float4*>(&vs[n][h * 16 + d4 * 4]);
            float kk[4] = {kq.x, kq.y, kq.z, kq.w};
            float vv[4] = {vq.x, vq.y, vq.z, vq.w};
#pragma unroll
            for (int j = 0; j < 4; j++) {
                int d = d4 * 4 + j;
                acck0 = fmaf(kk[j], areg0[d], acck0);
                accv0 = fmaf(vv[j], mreg0[d], accv0);
                if (two) {
                    acck1 = fmaf(kk[j], areg1[d], acck1);
                    accv1 = fmaf(vv[j], mreg1[d], accv1);
                }
            }
        }
        size_t o = (size_t)(node0 + n) * CDIM + h * 16 + e;
        kr0[o] = __float2half(acck0); vr0[o] = __float2half(accv0);
        if (two) { kr1[o] = __float2half(acck1); vr1[o] = __float2half(accv1); }
    }
}

// ---------------- host ----------------
extern "C" void kernel_launch(void* const* d_in, const int* in_sizes, int n_in,
                              void* d_out, int out_size)
{
    const float* x_patient = (const float*)d_in[0];
    const float* w_in      = (const float*)d_in[1];
    const float* b_in      = (const float*)d_in[2];
    const float* emb_icd   = (const float*)d_in[3];
    const float* emb_ndc   = (const float*)d_in[4];
    const float* kw = (const float*)d_in[5];
    const float* kb = (const float*)d_in[6];
    const float* qw = (const float*)d_in[7];
    const float* qb = (const float*)d_in[8];
    const float* vw = (const float*)d_in[9];
    const float* vb = (const float*)d_in[10];
    const float* aw = (const float*)d_in[11];
    const float* ab = (const float*)d_in[12];
    const float* skip  = (const float*)d_in[13];
    const float* a_rel = (const float*)d_in[14];
    const float* m_rel = (const float*)d_in[15];
    const float* p_rel = (const float*)d_in[16];
    const float* w_out = (const float*)d_in[17];
    const float* b_out = (const float*)d_in[18];
    const int* x_icd = (const int*)d_in[19];
    const int* x_ndc = (const int*)d_in[20];
    const int* esrc[4] = {(const int*)d_in[21], (const int*)d_in[23],
                          (const int*)d_in[25], (const int*)d_in[27]};
    const int* edst[4] = {(const int*)d_in[22], (const int*)d_in[24],
                          (const int*)d_in[26], (const int*)d_in[28]};
    float* out = (float*)d_out;

    cudaStream_t s2;
    cudaStreamCreateWithFlags(&s2, cudaStreamNonBlocking);
    cudaEvent_t evFork, evCsr, evX0, evX1, evQ0, evQ1;
    cudaEventCreateWithFlags(&evFork, cudaEventDisableTiming);
    cudaEventCreateWithFlags(&evCsr,  cudaEventDisableTiming);
    cudaEventCreateWithFlags(&evX0,   cudaEventDisableTiming);
    cudaEventCreateWithFlags(&evX1,   cudaEventDisableTiming);
    cudaEventCreateWithFlags(&evQ0,   cudaEventDisableTiming);
    cudaEventCreateWithFlags(&evQ1,   cudaEventDisableTiming);
    cudaEvent_t evX[2] = {evX0, evX1};
    cudaEvent_t evQ[2] = {evQ0, evQ1};

    // ---- fork CSR build onto s2 ----
    cudaEventRecord(evFork, 0);
    cudaStreamWaitEvent(s2, evFork, 0);
    csr_clear<<<(NSOFT + 255) / 256, 256, 0, s2>>>();
    csr_hist_pat<<<(NEDGE / 4 + 255) / 256, 256, 0, s2>>>(edst[1], edst[3]);
    {
        dim3 gh(48, 2);
        csr_hist_sm<<<gh, 256, 0, s2>>>(edst[0], edst[2]);
    }
    scan_partial<<<NSCB, 256, 0, s2>>>();
    scan_base<<<1, 128, 0, s2>>>();
    scan_write<<<NSCB, 256, 0, s2>>>();
    csr_scatter_pat<<<(NEDGE + 255) / 256, 256, 0, s2>>>(esrc[1], edst[1], esrc[3], edst[3]);
    {
        dim3 gs(64, 2);
        csr_scatter_sm<<<gs, 256, 0, s2>>>(esrc[0], edst[0], esrc[2], edst[2]);
    }
    cudaEventRecord(evCsr, s2);

    // ---- main stream ----
    {
        WSplit ws;
        ws.src[0] = w_in; ws.nn[0] = CDIM;
        const float* wsrc[3] = {kw, qw, vw};
        for (int l = 0; l < 2; l++)
            for (int j = 0; j < 3; j++)
                for (int ty = 0; ty < 3; ty++) {
                    ws.src[1 + l * 9 + j * 3 + ty] = wsrc[j] + (size_t)(l * 3 + ty) * CDIM * CDIM;
                    ws.nn[1 + l * 9 + j * 3 + ty] = CDIM;
                }
        for (int l = 0; l < 2; l++)
            for (int ty = 0; ty < 3; ty++) {
                ws.src[19 + l * 3 + ty] = aw + (size_t)(l * 3 + ty) * CDIM * CDIM;
                ws.nn[19 + l * 3 + ty] = CDIM;
            }
        ws.src[25] = w_out; ws.nn[25] = OUTD;
        dim3 g(32, NWMAT);
        split_weights<<<g, 256>>>(ws);
    }
    prep_inputs<<<(NTOTAL * 64 + 255) / 256, 256>>>(x_patient, emb_icd, x_icd, emb_ndc, x_ndc);
    {
        dim3 g(NBP, 2);
        gemm_in<<<g, 256>>>(b_in);
    }

    for (int l = 0; l < 2; l++) {
        cudaEventRecord(evX[l], 0);
        cudaStreamWaitEvent(s2, evX[l], 0);
        {
            dim3 gq(NBALL, 1, 2);
            gemm_kqv<<<gq, 256, 0, s2>>>(kb, qb, vb, l, 1);   // Q
        }
        cudaEventRecord(evQ[l], s2);

        {
            dim3 gkv(NBALL, 2, 2);
            gemm_kqv<<<gkv, 256>>>(kb, qb, vb, l, 0);         // K, V
        }
        {
            ReltAll ra;
            for (int r = 0; r < 4; r++) {
                ra.A[r]  = a_rel + (size_t)(l * 4 + r) * HH * DD * DD;
                ra.Mw[r] = m_rel + (size_t)(l * 4 + r) * HH * DD * DD;
            }
            relt_all<<<RTALL, 128>>>(ra);
        }

        cudaStreamWaitEvent(0, evQ[l], 0);
        if (l == 0) cudaStreamWaitEvent(0, evCsr, 0);

        edge_fused<<<EALL, 256>>>(p_rel + l * 32);

        {
            dim3 grid(NBALL, 2);
            gemm_ap<<<grid, 256>>>(ab, skip, l);
        }
    }

    {
        dim3 g(NBP, 2);
        gemm_o<<<g, 256>>>(b_out, out);
    }

    cudaEventDestroy(evFork);
    cudaEventDestroy(evCsr);
    cudaEventDestroy(evX0);
    cudaEventDestroy(evX1);
    cudaEventDestroy(evQ0);
    cudaEventDestroy(evQ1);
    cudaStreamDestroy(s2);
}

// round 15
// speedup vs baseline: 2.4617x; 1.0097x over previous
#include <cuda_runtime.h>
#include <cuda_fp16.h>
#include <math.h>
#include <stdint.h>

#define NPAT 50000
#define NICD 591
#define NNDC 2042
#define NTOTAL 52633
#define NSOFT 102633
#define CDIM 128
#define HH 8
#define DD 16
#define NEDGE 250000
#define OUTD 90

#define SOFF0 0
#define SOFF1 NICD
#define SOFF2 (NICD + NPAT)
#define SOFF3 (NICD + NPAT + NNDC)

#define NBP 391
#define NBI 5
#define NBN 16
#define NBALL (NBP + NBI + NBN)

#define RTP 1563
#define RTI 19
#define RTN 64
#define RTALL (RTP + RTI + RTN)

#define EPB 6250
#define EBLK (NICD + NNDC)

#define NWMAT 26

#define SCAN_TILE 1024
#define NSCB ((NSOFT + SCAN_TILE - 1) / SCAN_TILE)

// ---------------- scratch ----------------
__device__ float g_x[NTOTAL * CDIM];
__device__ float g_k[NTOTAL * CDIM];
__device__ float g_q[NTOTAL * CDIM];
__device__ float g_v[NTOTAL * CDIM];
__device__ __half g_krP0[NPAT * CDIM];
__device__ __half g_vrP0[NPAT * CDIM];
__device__ __half g_krP1[NPAT * CDIM];
__device__ __half g_vrP1[NPAT * CDIM];
__device__ __half g_krI[NICD * CDIM];
__device__ __half g_vrI[NICD * CDIM];
__device__ __half g_krN[NNDC * CDIM];
__device__ __half g_vrN[NNDC * CDIM];
__device__ uint32_t g_xh[NTOTAL * 64];
__device__ uint32_t g_xl[NTOTAL * 64];
__device__ uint32_t g_gh[NTOTAL * 64];
__device__ uint32_t g_gl[NTOTAL * 64];
__device__ uint32_t g_wh[NWMAT * 8192];
__device__ uint32_t g_wl[NWMAT * 8192];
__device__ int g_cnt[NSOFT];
__device__ int g_off[NSOFT];
__device__ int g_cur[NSOFT];
__device__ int g_csr[4 * NEDGE];
__device__ int g_bsum[NSCB];
__device__ int g_bbase[NSCB];

__device__ __forceinline__ float geluf(float x) {
    float t = tanhf(0.7978845608028654f * (x + 0.044715f * x * x * x));
    return 0.5f * x * (1.0f + t);
}

__device__ __forceinline__ void split_pair(float v0, float v1, uint32_t& h, uint32_t& l) {
    uint32_t hh;
    asm("cvt.rn.bf16x2.f32 %0, %1, %2;" : "=r"(hh) : "f"(v1), "f"(v0));
    float h0 = __uint_as_float(hh << 16);
    float h1 = __uint_as_float(hh & 0xffff0000u);
    float l0 = v0 - h0;
    float l1 = v1 - h1;
    uint32_t ll;
    asm("cvt.rn.bf16x2.f32 %0, %1, %2;" : "=r"(ll) : "f"(l1), "f"(l0));
    h = hh; l = ll;
}

__device__ __forceinline__ void mma_bf16(float* c, const uint32_t* a, const uint32_t* b) {
    asm volatile("mma.sync.aligned.m16n8k16.row.col.f32.bf16.bf16.f32 "
                 "{%0,%1,%2,%3}, {%4,%5,%6,%7}, {%8,%9}, {%0,%1,%2,%3};"
                 : "+f"(c[0]), "+f"(c[1]), "+f"(c[2]), "+f"(c[3])
                 : "r"(a[0]), "r"(a[1]), "r"(a[2]), "r"(a[3]),
                   "r"(b[0]), "r"(b[1]));
}

// ---------------- pre-split weights ----------------
struct WSplit { const float* src[NWMAT]; int nn[NWMAT]; };
__global__ void split_weights(WSplit ws) {
    int m = blockIdx.y;
    int idx = blockIdx.x * 256 + threadIdx.x;
    int kp = idx >> 7, n = idx & 127;
    const float* s = ws.src[m];
    int N = ws.nn[m];
    float v0 = (n < N) ? s[(size_t)(2 * kp) * N + n] : 0.0f;
    float v1 = (n < N) ? s[(size_t)(2 * kp + 1) * N + n] : 0.0f;
    uint32_t h, l;
    split_pair(v0, v1, h, l);
    g_wh[m * 8192 + idx] = h;
    g_wl[m * 8192 + idx] = l;
}

// ---------------- input prep ----------------
__global__ void prep_inputs(const float* __restrict__ xp,
                            const float* __restrict__ ei, const int* __restrict__ xi,
                            const float* __restrict__ en, const int* __restrict__ xn) {
    int idx = blockIdx.x * 256 + threadIdx.x;
    const int n1 = NPAT * 64;
    const int n2 = n1 + NICD * 64;
    const int n3 = n2 + NNDC * 64;
    if (idx < n1) {
        int node = idx >> 6, kp = idx & 63;
        float2 v = *reinterpret_cast<const float2*>(&xp[(size_t)node * CDIM + 2 * kp]);
        uint32_t h, l;
        split_pair(v.x, v.y, h, l);
        g_gh[idx] = h; g_gl[idx] = l;
    } else if (idx < n3) {
        int j, node;
        const float* emb;
        const int* map;
        if (idx < n2) { j = idx - n1; emb = ei; map = xi; node = NPAT + (j >> 6); }
        else          { j = idx - n2; emb = en; map = xn; node = NPAT + NICD + (j >> 6); }
        int r = j >> 6, kp = j & 63;
        float2 v = *reinterpret_cast<const float2*>(&emb[(size_t)map[r] * CDIM + 2 * kp]);
        v.x = fmaxf(v.x, 0.0f);
        v.y = fmaxf(v.y, 0.0f);
        g_x[(size_t)node * CDIM + 2 * kp] = v.x;
        g_x[(size_t)node * CDIM + 2 * kp + 1] = v.y;
        uint32_t h, l;
        split_pair(v.x, v.y, h, l);
        g_xh[(size_t)node * 64 + kp] = h;
        g_xl[(size_t)node * 64 + kp] = l;
    }
}

// ---------------- GEMM body (pre-split operands) ----------------
template<int MODE>
__device__ __forceinline__ void gemm_body(
    const uint32_t* __restrict__ XH, const uint32_t* __restrict__ XL,
    const uint32_t* __restrict__ WH, const uint32_t* __restrict__ WL,
    const float* __restrict__ bias,
    float* __restrict__ OutF, int ldo,
    uint32_t* __restrict__ OutH, uint32_t* __restrict__ OutL,
    const float* __restrict__ skipPtr, const float* __restrict__ xold,
    int M, int row0, int ncol0)
{
    __shared__ uint32_t Ah[128][20];
    __shared__ uint32_t Al[128][20];
    __shared__ uint32_t Bh[16][72];
    __shared__ uint32_t Bl[16][72];

    const int tid = threadIdx.x;
    const int lane = tid & 31;
    const int wid = tid >> 5;
    const int warp_m = wid >> 1;
    const int warp_n = wid & 1;
    const int gi = lane >> 2;
    const int tig = lane & 3;

    float c[2][4][4];
#pragma unroll
    for (int am = 0; am < 2; am++)
#pragma unroll
        for (int an = 0; an < 4; an++)
#pragma unroll
            for (int j = 0; j < 4; j++) c[am][an][j] = 0.0f;

    const int ar = tid >> 1;
    const int akh = tid & 1;
    const bool aok = (row0 + ar) < M;
    const int bkp = tid >> 4;
    const int nl0 = (tid & 15) * 4;

    for (int kc2 = 0; kc2 < 64; kc2 += 16) {
        uint4 ha = make_uint4(0, 0, 0, 0), hb = ha, la = ha, lb = ha;
        if (aok) {
            const uint32_t* ph = &XH[(size_t)(row0 + ar) * 64 + kc2 + akh * 8];
            const uint32_t* pl = &XL[(size_t)(row0 + ar) * 64 + kc2 + akh * 8];
            ha = *reinterpret_cast<const uint4*>(ph);
            hb = *reinterpret_cast<const uint4*>(ph + 4);
            la = *reinterpret_cast<const uint4*>(pl);
            lb = *reinterpret_cast<const uint4*>(pl + 4);
        }
        *reinterpret_cast<uint4*>(&Ah[ar][akh * 8]) = ha;
        *reinterpret_cast<uint4*>(&Ah[ar][akh * 8 + 4]) = hb;
        *reinterpret_cast<uint4*>(&Al[ar][akh * 8]) = la;
        *reinterpret_cast<uint4*>(&Al[ar][akh * 8 + 4]) = lb;
        *reinterpret_cast<uint4*>(&Bh[bkp][nl0]) =
            *reinterpret_cast<const uint4*>(&WH[(size_t)(kc2 + bkp) * 128 + ncol0 + nl0]);
        *reinterpret_cast<uint4*>(&Bl[bkp][nl0]) =
            *reinterpret_cast<const uint4*>(&WL[(size_t)(kc2 + bkp) * 128 + ncol0 + nl0]);
        __syncthreads();

#pragma unroll
        for (int ks = 0; ks < 2; ks++) {
            const int kb = ks * 8;
            uint32_t ah[2][4], al[2][4];
#pragma unroll
            for (int am = 0; am < 2; am++) {
                int rb = warp_m * 32 + am * 16 + gi;
                ah[am][0] = Ah[rb][kb + tig];
                ah[am][1] = Ah[rb + 8][kb + tig];
                ah[am][2] = Ah[rb][kb + 4 + tig];
                ah[am][3] = Ah[rb + 8][kb + 4 + tig];
                al[am][0] = Al[rb][kb + tig];
                al[am][1] = Al[rb + 8][kb + tig];
                al[am][2] = Al[rb][kb + 4 + tig];
                al[am][3] = Al[rb + 8][kb + 4 + tig];
            }
#pragma unroll
            for (int an = 0; an < 4; an++) {
                int nc = warp_n * 32 + an * 8 + gi;
                uint32_t bh[2], bl[2];
                bh[0] = Bh[kb + tig][nc];
                bh[1] = Bh[kb + 4 + tig][nc];
                bl[0] = Bl[kb + tig][nc];
                bl[1] = Bl[kb + 4 + tig][nc];
#pragma unroll
                for (int am = 0; am < 2; am++) {
                    mma_bf16(c[am][an], ah[am], bh);
                    mma_bf16(c[am][an], al[am], bh);
                    mma_bf16(c[am][an], ah[am], bl);
                }
            }
        }
        __syncthreads();
    }

    float sa = 0.f, sb = 0.f;
    if (MODE == 2) {
        float s = 1.0f / (1.0f + __expf(-*skipPtr));
        sa = s; sb = 1.0f - s;
    }
#pragma unroll
    for (int am = 0; am < 2; am++) {
#pragma unroll
        for (int an = 0; an < 4; an++) {
            int col = ncol0 + warp_n * 32 + an * 8 + tig * 2;
#pragma unroll
            for (int half = 0; half < 2; half++) {
                int row = row0 + warp_m * 32 + am * 16 + gi + half * 8;
                if (row >= M) continue;
                float b0 = (MODE == 3) ? ((col < OUTD) ? bias[col] : 0.0f) : bias[col];
                float b1 = (MODE == 3) ? ((col + 1 < OUTD) ? bias[col + 1] : 0.0f) : bias[col + 1];
                float v0 = c[am][an][half * 2 + 0] + b0;
                float v1 = c[am][an][half * 2 + 1] + b1;
                if (MODE == 1) { v0 = fmaxf(v0, 0.0f); v1 = fmaxf(v1, 0.0f); }
                else if (MODE == 2) {
                    v0 = sa * v0 + sb * xold[(size_t)row * CDIM + col];
                    v1 = sa * v1 + sb * xold[(size_t)row * CDIM + col + 1];
                } else if (MODE == 3) {
                    v0 = 1.0f / (1.0f + __expf(-v0));
                    v1 = 1.0f / (1.0f + __expf(-v1));
                }
                if (MODE == 3) {
                    if (col < OUTD)     OutF[(size_t)row * ldo + col] = v0;
                    if (col + 1 < OUTD) OutF[(size_t)row * ldo + col + 1] = v1;
                } else {
                    OutF[(size_t)row * CDIM + col] = v0;
                    OutF[(size_t)row * CDIM + col + 1] = v1;
                    if (MODE == 1 || MODE == 2) {
                        uint32_t h, l;
                        split_pair(v0, v1, h, l);
                        OutH[(size_t)row * 64 + (col >> 1)] = h;
                        OutL[(size_t)row * 64 + (col >> 1)] = l;
                    }
                }
            }
        }
    }
}

// ---------------- GEMM wrappers ----------------
__global__ __launch_bounds__(256, 4) void gemm_in(const float* __restrict__ bias)
{
    gemm_body<1>(g_gh, g_gl, g_wh, g_wl, bias,
                 g_x, CDIM, g_xh, g_xl, nullptr, nullptr,
                 NPAT, blockIdx.x * 128, blockIdx.y * 64);
}

__global__ __launch_bounds__(256, 4) void gemm_kqv(
    const float* __restrict__ kb, const float* __restrict__ qb,
    const float* __restrict__ vb, int l, int jmode)
{
    const int bx = blockIdx.x;
    int ty, bl;
    if (bx < NBP)            { ty = 0; bl = bx; }
    else if (bx < NBP + NBI) { ty = 1; bl = bx - NBP; }
    else                     { ty = 2; bl = bx - NBP - NBI; }
    const int M = (ty == 0) ? NPAT : (ty == 1) ? NICD : NNDC;
    const int toff = (ty == 0) ? 0 : (ty == 1) ? NPAT : NPAT + NICD;
    const int j = (jmode == 0) ? (blockIdx.y == 0 ? 0 : 2) : 1;
    const int widx = 1 + l * 9 + j * 3 + ty;
    const float* bias = ((j == 0) ? kb : (j == 1) ? qb : vb) + (size_t)(l * 3 + ty) * CDIM;
    float* outp = ((j == 0) ? g_k : (j == 1) ? g_q : g_v) + (size_t)toff * CDIM;
    gemm_body<0>(g_xh + (size_t)toff * 64, g_xl + (size_t)toff * 64,
                 g_wh + (size_t)widx * 8192, g_wl + (size_t)widx * 8192, bias,
                 outp, CDIM, nullptr, nullptr, nullptr, nullptr,
                 M, bl * 128, blockIdx.z * 64);
}

// A-proj for patients only: grid (NBP, 2)
__global__ __launch_bounds__(256, 4) void gemm_ap_pat(
    const float* __restrict__ ab, const float* __restrict__ skip, int l)
{
    const int widx = 19 + l * 3;
    gemm_body<2>(g_gh, g_gl,
                 g_wh + (size_t)widx * 8192, g_wl + (size_t)widx * 8192,
                 ab + (size_t)(l * 3) * CDIM,
                 g_x, CDIM, g_xh, g_xl,
                 skip + (l * 3), g_x,
                 NPAT, blockIdx.x * 128, blockIdx.y * 64);
}

// A-proj for icd + ndc: grid (NBI + NBN, 2)
__global__ __launch_bounds__(256, 4) void gemm_ap_ind(
    const float* __restrict__ ab, const float* __restrict__ skip, int l)
{
    const int bx = blockIdx.x;
    int ty, bl;
    if (bx < NBI) { ty = 1; bl = bx; }
    else          { ty = 2; bl = bx - NBI; }
    const int M = (ty == 1) ? NICD : NNDC;
    const int toff = (ty == 1) ? NPAT : NPAT + NICD;
    const int widx = 19 + l * 3 + ty;
    gemm_body<2>(g_gh + (size_t)toff * 64, g_gl + (size_t)toff * 64,
                 g_wh + (size_t)widx * 8192, g_wl + (size_t)widx * 8192,
                 ab + (size_t)(l * 3 + ty) * CDIM,
                 g_x + (size_t)toff * CDIM, CDIM,
                 g_xh + (size_t)toff * 64, g_xl + (size_t)toff * 64,
                 skip + (l * 3 + ty), g_x + (size_t)toff * CDIM,
                 M, bl * 128, blockIdx.y * 64);
}

__global__ __launch_bounds__(256, 4) void gemm_o(
    const float* __restrict__ bias, float* __restrict__ out)
{
    gemm_body<3>(g_xh, g_xl, g_wh + (size_t)25 * 8192, g_wl + (size_t)25 * 8192, bias,
                 out, OUTD, nullptr, nullptr, nullptr, nullptr,
                 NPAT, blockIdx.x * 128, blockIdx.y * 64);
}

// ---------------- CSR build ----------------
__global__ void csr_clear() {
    int i = blockIdx.x * blockDim.x + threadIdx.x;
    if (i < NSOFT) { g_cnt[i] = 0; g_cur[i] = 0; }
}

__global__ void csr_hist_pat(const int* __restrict__ d1, const int* __restrict__ d3) {
    int i = blockIdx.x * blockDim.x + threadIdx.x;
    if (i < NEDGE / 4) {
        int4 a = reinterpret_cast<const int4*>(d1)[i];
        atomicAdd(&g_cnt[SOFF1 + a.x], 1);
        atomicAdd(&g_cnt[SOFF1 + a.y], 1);
        atomicAdd(&g_cnt[SOFF1 + a.z], 1);
        atomicAdd(&g_cnt[SOFF1 + a.w], 1);
        int4 b = reinterpret_cast<const int4*>(d3)[i];
        atomicAdd(&g_cnt[SOFF3 + b.x], 1);
        atomicAdd(&g_cnt[SOFF3 + b.y], 1);
        atomicAdd(&g_cnt[SOFF3 + b.z], 1);
        atomicAdd(&g_cnt[SOFF3 + b.w], 1);
    }
}

__global__ __launch_bounds__(256) void csr_hist_sm(const int* __restrict__ dst0,
                                                   const int* __restrict__ dst2) {
    __shared__ int h[NNDC];
    const int r = blockIdx.y;
    const int ndst = r ? NNDC : NICD;
    const int so = r ? SOFF2 : SOFF0;
    const int* __restrict__ dst = r ? dst2 : dst0;
    for (int i = threadIdx.x; i < ndst; i += 256) h[i] = 0;
    __syncthreads();
    const int tot = NEDGE / 4;
    for (int i = blockIdx.x * 256 + threadIdx.x; i < tot; i += gridDim.x * 256) {
        int4 a = reinterpret_cast<const int4*>(dst)[i];
        atomicAdd(&h[a.x], 1); atomicAdd(&h[a.y], 1);
        atomicAdd(&h[a.z], 1); atomicAdd(&h[a.w], 1);
    }
    __syncthreads();
    for (int i = threadIdx.x; i < ndst; i += 256)
        if (h[i]) atomicAdd(&g_cnt[so + i], h[i]);
}

__global__ __launch_bounds__(256) void scan_partial() {
    __shared__ int red[256];
    const int base = blockIdx.x * SCAN_TILE;
    int sum = 0;
#pragma unroll
    for (int j = 0; j < 4; j++) {
        int idx = base + j * 256 + threadIdx.x;
        sum += (idx < NSOFT) ? g_cnt[idx] : 0;
    }
    red[threadIdx.x] = sum;
    __syncthreads();
    for (int d = 128; d > 0; d >>= 1) {
        if (threadIdx.x < d) red[threadIdx.x] += red[threadIdx.x + d];
        __syncthreads();
    }
    if (threadIdx.x == 0) g_bsum[blockIdx.x] = red[0];
}

__global__ __launch_bounds__(128) void scan_base() {
    __shared__ int tmp[NSCB];
    int t = threadIdx.x;
    if (t < NSCB) tmp[t] = g_bsum[t];
    __syncthreads();
    if (t == 0) {
        int acc = 0;
        for (int i = 0; i < NSCB; i++) { int v = tmp[i]; tmp[i] = acc; acc += v; }
    }
    __syncthreads();
    if (t < NSCB) g_bbase[t] = tmp[t];
}

__global__ __launch_bounds__(256) void scan_write() {
    __shared__ int wsum[8];
    const int base = blockIdx.x * SCAN_TILE;
    const int t = threadIdx.x;
    const int lane = t & 31;
    const int w = t >> 5;
    int v[4];
    const int idx0 = base + t * 4;
#pragma unroll
    for (int j = 0; j < 4; j++) {
        int idx = idx0 + j;
        v[j] = (idx < NSOFT) ? g_cnt[idx] : 0;
    }
    int s1 = v[0] + v[1];
    int s2 = s1 + v[2];
    int tot = s2 + v[3];
    int x = tot;
#pragma unroll
    for (int d = 1; d < 32; d <<= 1) {
        int y = __shfl_up_sync(0xffffffff, x, d);
        if (lane >= d) x += y;
    }
    if (lane == 31) wsum[w] = x;
    __syncthreads();
    if (w == 0 && lane < 8) {
        int orig = wsum[lane];
        int ws = orig;
#pragma unroll
        for (int d = 1; d < 8; d <<= 1) {
            int y = __shfl_up_sync(0xff, ws, d);
            if (lane >= d) ws += y;
        }
        wsum[lane] = ws - orig;
    }
    __syncthreads();
    int ebase = g_bbase[blockIdx.x] + wsum[w] + (x - tot);
    int offs[4] = {0, v[0], s1, s2};
#pragma unroll
    for (int j = 0; j < 4; j++) {
        int idx = idx0 + j;
        if (idx < NSOFT) g_off[idx] = ebase + offs[j];
    }
}

__global__ void csr_scatter_pat(const int* __restrict__ s1, const int* __restrict__ d1,
                                const int* __restrict__ s3, const int* __restrict__ d3) {
    int i = blockIdx.x * blockDim.x + threadIdx.x;
    if (i < NEDGE) {
        int b1 = SOFF1 + d1[i];
        g_csr[g_off[b1] + atomicAdd(&g_cur[b1], 1)] = s1[i];
        int b3 = SOFF3 + d3[i];
        g_csr[g_off[b3] + atomicAdd(&g_cur[b3], 1)] = s3[i];
    }
}

__global__ __launch_bounds__(256) void csr_scatter_sm(
    const int* __restrict__ src0, const int* __restrict__ dst0,
    const int* __restrict__ src2, const int* __restrict__ dst2) {
    __shared__ int h[NNDC];
    __shared__ int base[NNDC];
    const int r = blockIdx.y;
    const int ndst = r ? NNDC : NICD;
    const int so = r ? SOFF2 : SOFF0;
    const int* __restrict__ dst = r ? dst2 : dst0;
    const int* __restrict__ src = r ? src2 : src0;
    const int chunk = (NEDGE + gridDim.x - 1) / gridDim.x;
    const int e0 = blockIdx.x * chunk;
    int e1 = e0 + chunk; if (e1 > NEDGE) e1 = NEDGE;

    for (int i = threadIdx.x; i < ndst; i += 256) h[i] = 0;
    __syncthreads();
    for (int e = e0 + threadIdx.x; e < e1; e += 256) atomicAdd(&h[dst[e]], 1);
    __syncthreads();
    for (int i = threadIdx.x; i < ndst; i += 256) {
        int cc = h[i];
        base[i] = cc ? atomicAdd(&g_cur[so + i], cc) : 0;
    }
    __syncthreads();
    for (int i = threadIdx.x; i < ndst; i += 256) h[i] = 0;
    __syncthreads();
    for (int e = e0 + threadIdx.x; e < e1; e += 256) {
        int d = dst[e];
        int loc = atomicAdd(&h[d], 1);
        g_csr[g_off[so + d] + base[d] + loc] = src[e];
    }
}

// ---------------- edge kernels (fp16 kr/vr gathers), split by destination type ----------------
__device__ __forceinline__ void ld_half4(const __half* p, float& f0, float& f1,
                                         float& f2, float& f3) {
    uint2 raw = *reinterpret_cast<const uint2*>(p);
    float2 a = __half22float2(*reinterpret_cast<const __half2*>(&raw.x));
    float2 b = __half22float2(*reinterpret_cast<const __half2*>(&raw.y));
    f0 = a.x; f1 = a.y; f2 = b.x; f3 = b.y;
}

// patient destinations (relations 1, 3); sources icd/ndc (small L2-resident tables)
__global__ __launch_bounds__(256) void edge_pat(const float* __restrict__ prel)
{
    const int tid = threadIdx.x;
    const int w = tid >> 5;
    const int lane = tid & 31;
    const int h = lane >> 2;
    int d = blockIdx.x * 8 + w;

    float4 qv = *reinterpret_cast<const float4*>(&g_q[(size_t)d * CDIM + lane * 4]);
    float ax = 0.f, ay = 0.f, az = 0.f, aw2 = 0.f;
#pragma unroll
    for (int rr = 0; rr < 2; rr++) {
        const int rel = rr ? 3 : 1;
        const __half* krb = rr ? g_krN : g_krI;
        const __half* vrb = rr ? g_vrN : g_vrI;
        int base = (rr ? SOFF3 : SOFF1) + d;
        int st = g_off[base], n = g_cnt[base];
        float pf = prel[rel * 8 + h] * 0.25f;
        float es = 0.f, a0 = 0.f, a1 = 0.f, a2 = 0.f, a3 = 0.f;
        for (int i = 0; i < n; i++) {
            int s = g_csr[st + i];
            float k0, k1, k2, k3;
            ld_half4(&krb[(size_t)s * CDIM + lane * 4], k0, k1, k2, k3);
            float dot = qv.x * k0 + qv.y * k1 + qv.z * k2 + qv.w * k3;
            dot += __shfl_xor_sync(0xffffffff, dot, 1);
            dot += __shfl_xor_sync(0xffffffff, dot, 2);
            float e = __expf(dot * pf);
            float v0, v1, v2, v3;
            ld_half4(&vrb[(size_t)s * CDIM + lane * 4], v0, v1, v2, v3);
            es += e;
            a0 += e * v0; a1 += e * v1; a2 += e * v2; a3 += e * v3;
        }
        if (n > 0) {
            float inv = 1.0f / es;
            ax += a0 * inv; ay += a1 * inv; az += a2 * inv; aw2 += a3 * inv;
        }
    }
    float v0 = geluf(ax), v1 = geluf(ay), v2 = geluf(az), v3 = geluf(aw2);
    uint32_t h0, l0, h1, l1;
    split_pair(v0, v1, h0, l0);
    split_pair(v2, v3, h1, l1);
    *reinterpret_cast<uint2*>(&g_gh[(size_t)d * 64 + lane * 2]) = make_uint2(h0, h1);
    *reinterpret_cast<uint2*>(&g_gl[(size_t)d * 64 + lane * 2]) = make_uint2(l0, l1);
}

// icd/ndc destinations (relations 0, 2); sources patients (large tables)
__global__ __launch_bounds__(256) void edge_ind(const float* __restrict__ prel)
{
    __shared__ float sacc[8][128];
    __shared__ float ses[8][8];
    const int bb = blockIdx.x;
    const int tid = threadIdx.x;
    const int w = tid >> 5;
    const int lane = tid & 31;
    const int h = lane >> 2;

    int base;
    size_t nodeoff;
    const __half *krb, *vrb;
    float pf;
    if (bb < NICD) {
        base = SOFF0 + bb;
        nodeoff = (size_t)(NPAT + bb);
        krb = g_krP0; vrb = g_vrP0;
        pf = prel[0 * 8 + h] * 0.25f;
    } else {
        int d = bb - NICD;
        base = SOFF2 + d;
        nodeoff = (size_t)(NPAT + NICD + d);
        krb = g_krP1; vrb = g_vrP1;
        pf = prel[2 * 8 + h] * 0.25f;
    }
    float4 qv = *reinterpret_cast<const float4*>(&g_q[nodeoff * CDIM + lane * 4]);
    int st = g_off[base], n = g_cnt[base];
    float es = 0.f, a0 = 0.f, a1 = 0.f, a2 = 0.f, a3 = 0.f;
    for (int i = w; i < n; i += 8) {
        int s = g_csr[st + i];
        float k0, k1, k2, k3;
        ld_half4(&krb[(size_t)s * CDIM + lane * 4], k0, k1, k2, k3);
        float dot = qv.x * k0 + qv.y * k1 + qv.z * k2 + qv.w * k3;
        dot += __shfl_xor_sync(0xffffffff, dot, 1);
        dot += __shfl_xor_sync(0xffffffff, dot, 2);
        float e = __expf(dot * pf);
        float v0, v1, v2, v3;
        ld_half4(&vrb[(size_t)s * CDIM + lane * 4], v0, v1, v2, v3);
        es += e;
        a0 += e * v0; a1 += e * v1; a2 += e * v2; a3 += e * v3;
    }
    *reinterpret_cast<float4*>(&sacc[w][lane * 4]) = make_float4(a0, a1, a2, a3);
    if ((lane & 3) == 0) ses[w][h] = es;
    __syncthreads();
    if (tid < 64) {
        int col0 = 2 * tid;
        float s0 = 0.f, s1 = 0.f, e = 0.f;
#pragma unroll
        for (int ww = 0; ww < 8; ww++) {
            s0 += sacc[ww][col0];
            s1 += sacc[ww][col0 + 1];
            e  += ses[ww][tid >> 3];
        }
        float v0 = (e > 0.f) ? s0 / e : 0.0f;
        float v1 = (e > 0.f) ? s1 / e : 0.0f;
        v0 = geluf(v0); v1 = geluf(v1);
        uint32_t hh, ll;
        split_pair(v0, v1, hh, ll);
        g_gh[nodeoff * 64 + tid] = hh;
        g_gl[nodeoff * 64 + tid] = ll;
    }
}

// ---------------- merged per-relation K/V transform (fp16 outputs) ----------------
struct ReltAll {
    const float* A[4];
    const float* Mw[4];
};
__global__ __launch_bounds__(128) void relt_all(ReltAll ra)
{
    __shared__ float ks[32][128];
    __shared__ float vs[32][128];
    const int tid = threadIdx.x;
    const int bx = blockIdx.x;
    const int h = tid >> 4;
    const int e = tid & 15;

    int node0, nsrc, srcoff;
    const float *A0, *M0, *A1, *M1;
    __half *kr0, *vr0, *kr1, *vr1;
    bool two;
    if (bx < RTP) {
        node0 = bx * 32; nsrc = NPAT; srcoff = 0; two = true;
        A0 = ra.A[0]; M0 = ra.Mw[0]; A1 = ra.A[2]; M1 = ra.Mw[2];
        kr0 = g_krP0; vr0 = g_vrP0; kr1 = g_krP1; vr1 = g_vrP1;
    } else if (bx < RTP + RTI) {
        node0 = (bx - RTP) * 32; nsrc = NICD; srcoff = NPAT; two = false;
        A0 = ra.A[1]; M0 = ra.Mw[1]; A1 = nullptr; M1 = nullptr;
        kr0 = g_krI; vr0 = g_vrI; kr1 = nullptr; vr1 = nullptr;
    } else {
        node0 = (bx - RTP - RTI) * 32; nsrc = NNDC; srcoff = NPAT + NICD; two = false;
        A0 = ra.A[3]; M0 = ra.Mw[3]; A1 = nullptr; M1 = nullptr;
        kr0 = g_krN; vr0 = g_vrN; kr1 = nullptr; vr1 = nullptr;
    }

    float areg0[16], mreg0[16], areg1[16], mreg1[16];
#pragma unroll
    for (int d = 0; d < 16; d++) {
        areg0[d] = A0[(h * 16 + d) * 16 + e];
        mreg0[d] = M0[(h * 16 + d) * 16 + e];
        if (two) {
            areg1[d] = A1[(h * 16 + d) * 16 + e];
            mreg1[d] = M1[(h * 16 + d) * 16 + e];
        }
    }

    const float* kbase = g_k + (size_t)srcoff * CDIM;
    const float* vbase = g_v + (size_t)srcoff * CDIM;
    for (int i = tid; i < 32 * 32; i += 128) {
        int r = i >> 5;
        int cidx = (i & 31) * 4;
        if (node0 + r < nsrc) {
            *reinterpret_cast<float4*>(&ks[r][cidx]) =
                *reinterpret_cast<const float4*>(&kbase[(size_t)(node0 + r) * CDIM + cidx]);
            *reinterpret_cast<float4*>(&vs[r][cidx]) =
                *reinterpret_cast<const float4*>(&vbase[(size_t)(node0 + r) * CDIM + cidx]);
        }
    }
    __syncthreads();

    int nmax = nsrc - node0; if (nmax > 32) nmax = 32;
    for (int n = 0; n < nmax; n++) {
        float acck0 = 0.f, accv0 = 0.f, acck1 = 0.f, accv1 = 0.f;
#pragma unroll
        for (int d4 = 0; d4 < 4; d4++) {
            float4 kq = *reinterpret_cast<const float4*>(&ks[n][h * 16 + d4 * 4]);
            float4 vq = *reinterpret_cast<const float4*>(&vs[n][h * 16 + d4 * 4]);
            float kk[4] = {kq.x, kq.y, kq.z, kq.w};
            float vv[4] = {vq.x, vq.y, vq.z, vq.w};
#pragma unroll
            for (int j = 0; j < 4; j++) {
                int d = d4 * 4 + j;
                acck0 = fmaf(kk[j], areg0[d], acck0);
                accv0 = fmaf(vv[j], mreg0[d], accv0);
                if (two) {
                    acck1 = fmaf(kk[j], areg1[d], acck1);
                    accv1 = fmaf(vv[j], mreg1[d], accv1);
                }
            }
        }
        size_t o = (size_t)(node0 + n) * CDIM + h * 16 + e;
        kr0[o] = __float2half(acck0); vr0[o] = __float2half(accv0);
        if (two) { kr1[o] = __float2half(acck1); vr1[o] = __float2half(accv1); }
    }
}

// ---------------- host ----------------
extern "C" void kernel_launch(void* const* d_in, const int* in_sizes, int n_in,
                              void* d_out, int out_size)
{
    const float* x_patient = (const float*)d_in[0];
    const float* w_in      = (const float*)d_in[1];
    const float* b_in      = (const float*)d_in[2];
    const float* emb_icd   = (const float*)d_in[3];
    const float* emb_ndc   = (const float*)d_in[4];
    const float* kw = (const float*)d_in[5];
    const float* kb = (const float*)d_in[6];
    const float* qw = (const float*)d_in[7];
    const float* qb = (const float*)d_in[8];
    const float* vw = (const float*)d_in[9];
    const float* vb = (const float*)d_in[10];
    const float* aw = (const float*)d_in[11];
    const float* ab = (const float*)d_in[12];
    const float* skip  = (const float*)d_in[13];
    const float* a_rel = (const float*)d_in[14];
    const float* m_rel = (const float*)d_in[15];
    const float* p_rel = (const float*)d_in[16];
    const float* w_out = (const float*)d_in[17];
    const float* b_out = (const float*)d_in[18];
    const int* x_icd = (const int*)d_in[19];
    const int* x_ndc = (const int*)d_in[20];
    const int* esrc[4] = {(const int*)d_in[21], (const int*)d_in[23],
                          (const int*)d_in[25], (const int*)d_in[27]};
    const int* edst[4] = {(const int*)d_in[22], (const int*)d_in[24],
                          (const int*)d_in[26], (const int*)d_in[28]};
    float* out = (float*)d_out;

    cudaStream_t s2;
    cudaStreamCreateWithFlags(&s2, cudaStreamNonBlocking);
    cudaEvent_t evFork, evCsr, evX0, evX1, evQ0, evQ1, evR0, evR1, evS0, evS1;
    cudaEventCreateWithFlags(&evFork, cudaEventDisableTiming);
    cudaEventCreateWithFlags(&evCsr,  cudaEventDisableTiming);
    cudaEventCreateWithFlags(&evX0,   cudaEventDisableTiming);
    cudaEventCreateWithFlags(&evX1,   cudaEventDisableTiming);
    cudaEventCreateWithFlags(&evQ0,   cudaEventDisableTiming);
    cudaEventCreateWithFlags(&evQ1,   cudaEventDisableTiming);
    cudaEventCreateWithFlags(&evR0,   cudaEventDisableTiming);
    cudaEventCreateWithFlags(&evR1,   cudaEventDisableTiming);
    cudaEventCreateWithFlags(&evS0,   cudaEventDisableTiming);
    cudaEventCreateWithFlags(&evS1,   cudaEventDisableTiming);
    cudaEvent_t evX[2] = {evX0, evX1};
    cudaEvent_t evQ[2] = {evQ0, evQ1};
    cudaEvent_t evR[2] = {evR0, evR1};
    cudaEvent_t evS[2] = {evS0, evS1};

    // ---- fork CSR build onto s2 ----
    cudaEventRecord(evFork, 0);
    cudaStreamWaitEvent(s2, evFork, 0);
    csr_clear<<<(NSOFT + 255) / 256, 256, 0, s2>>>();
    csr_hist_pat<<<(NEDGE / 4 + 255) / 256, 256, 0, s2>>>(edst[1], edst[3]);
    {
        dim3 gh(48, 2);
        csr_hist_sm<<<gh, 256, 0, s2>>>(edst[0], edst[2]);
    }
    scan_partial<<<NSCB, 256, 0, s2>>>();
    scan_base<<<1, 128, 0, s2>>>();
    scan_write<<<NSCB, 256, 0, s2>>>();
    csr_scatter_pat<<<(NEDGE + 255) / 256, 256, 0, s2>>>(esrc[1], edst[1], esrc[3], edst[3]);
    {
        dim3 gs(64, 2);
        csr_scatter_sm<<<gs, 256, 0, s2>>>(esrc[0], edst[0], esrc[2], edst[2]);
    }
    cudaEventRecord(evCsr, s2);

    // ---- main: weights / inputs / in-proj ----
    {
        WSplit ws;
        ws.src[0] = w_in; ws.nn[0] = CDIM;
        const float* wsrc[3] = {kw, qw, vw};
        for (int l = 0; l < 2; l++)
            for (int j = 0; j < 3; j++)
                for (int ty = 0; ty < 3; ty++) {
                    ws.src[1 + l * 9 + j * 3 + ty] = wsrc[j] + (size_t)(l * 3 + ty) * CDIM * CDIM;
                    ws.nn[1 + l * 9 + j * 3 + ty] = CDIM;
                }
        for (int l = 0; l < 2; l++)
            for (int ty = 0; ty < 3; ty++) {
                ws.src[19 + l * 3 + ty] = aw + (size_t)(l * 3 + ty) * CDIM * CDIM;
                ws.nn[19 + l * 3 + ty] = CDIM;
            }
        ws.src[25] = w_out; ws.nn[25] = OUTD;
        dim3 g(32, NWMAT);
        split_weights<<<g, 256>>>(ws);
    }
    prep_inputs<<<(NTOTAL * 64 + 255) / 256, 256>>>(x_patient, emb_icd, x_icd, emb_ndc, x_ndc);
    {
        dim3 g(NBP, 2);
        gemm_in<<<g, 256>>>(b_in);
    }
    cudaEventRecord(evX[0], 0);

    for (int l = 0; l < 2; l++) {
        // s2: Q GEMM (needs x of all types)
        cudaStreamWaitEvent(s2, evX[l], 0);
        {
            dim3 gq(NBALL, 1, 2);
            gemm_kqv<<<gq, 256, 0, s2>>>(kb, qb, vb, l, 1);
        }
        cudaEventRecord(evQ[l], s2);

        // main: K and V GEMMs + relation transforms
        {
            dim3 gkv(NBALL, 2, 2);
            gemm_kqv<<<gkv, 256>>>(kb, qb, vb, l, 0);
        }
        {
            ReltAll ra;
            for (int r = 0; r < 4; r++) {
                ra.A[r]  = a_rel + (size_t)(l * 4 + r) * HH * DD * DD;
                ra.Mw[r] = m_rel + (size_t)(l * 4 + r) * HH * DD * DD;
            }
            relt_all<<<RTALL, 128>>>(ra);
        }
        cudaEventRecord(evR[l], 0);

        // s2 chain B: edge_ind (icd/ndc dst) -> aproj_ind
        // (s2 in-order already has Q and, for l=0, the CSR build)
        cudaStreamWaitEvent(s2, evR[l], 0);
        edge_ind<<<EBLK, 256, 0, s2>>>(p_rel + l * 32);
        {
            dim3 gi(NBI + NBN, 2);
            gemm_ap_ind<<<gi, 256, 0, s2>>>(ab, skip, l);
        }
        cudaEventRecord(evS[l], s2);

        // main chain A: edge_pat (patient dst) -> aproj_pat
        cudaStreamWaitEvent(0, evQ[l], 0);
        if (l == 0) cudaStreamWaitEvent(0, evCsr, 0);
        edge_pat<<<EPB, 256>>>(p_rel + l * 32);
        {
            dim3 gp(NBP, 2);
            gemm_ap_pat<<<gp, 256>>>(ab, skip, l);
        }

        // join: x (all types) complete
        cudaStreamWaitEvent(0, evS[l], 0);
        if (l == 0) cudaEventRecord(evX[1], 0);
    }

    // output projection + sigmoid (needs all of x; joined above)
    {
        dim3 g(NBP, 2);
        gemm_o<<<g, 256>>>(b_out, out);
    }

    cudaEventDestroy(evFork);
    cudaEventDestroy(evCsr);
    cudaEventDestroy(evX0);
    cudaEventDestroy(evX1);
    cudaEventDestroy(evQ0);
    cudaEventDestroy(evQ1);
    cudaEventDestroy(evR0);
    cudaEventDestroy(evR1);
    cudaEventDestroy(evS0);
    cudaEventDestroy(evS1);
    cudaStreamDestroy(s2);
}

// round 16
// speedup vs baseline: 2.9577x; 1.2015x over previous
#include <cuda_runtime.h>
#include <cuda_fp16.h>
#include <math.h>
#include <stdint.h>

#define NPAT 50000
#define NICD 591
#define NNDC 2042
#define NTOTAL 52633
#define NSOFT 102633
#define CDIM 128
#define HH 8
#define DD 16
#define NEDGE 250000
#define OUTD 90

#define SOFF0 0
#define SOFF1 NICD
#define SOFF2 (NICD + NPAT)
#define SOFF3 (NICD + NPAT + NNDC)

#define NBP 391
#define NBI 5
#define NBN 16
#define NBALL (NBP + NBI + NBN)

#define RTP 1563
#define RTI 19
#define RTN 64
#define RTALL (RTP + RTI + RTN)

#define EPB 6250
#define EBLK (NICD + NNDC)

#define NWMAT 26

#define SCAN_TILE 1024
#define NSCB ((NSOFT + SCAN_TILE - 1) / SCAN_TILE)

// ---------------- scratch ----------------
__device__ float g_x[NTOTAL * CDIM];
__device__ float g_q[NTOTAL * CDIM];
__device__ float g_k[NTOTAL * CDIM];
__device__ float g_v[NTOTAL * CDIM];
__device__ __half g_krP0[NPAT * CDIM];
__device__ __half g_vrP0[NPAT * CDIM];
__device__ __half g_krP1[NPAT * CDIM];
__device__ __half g_vrP1[NPAT * CDIM];
__device__ __half g_krI[NICD * CDIM];
__device__ __half g_vrI[NICD * CDIM];
__device__ __half g_krN[NNDC * CDIM];
__device__ __half g_vrN[NNDC * CDIM];
// bf16x2 activations (A-side of GEMMs; single-term — weights carry the hi/lo split)
__device__ uint32_t g_xh[NTOTAL * 64];
__device__ uint32_t g_gh[NTOTAL * 64];
__device__ uint32_t g_wh[NWMAT * 8192];
__device__ uint32_t g_wl[NWMAT * 8192];
__device__ int g_cnt[NSOFT];
__device__ int g_off[NSOFT];
__device__ int g_cur[NSOFT];
__device__ int g_csr[4 * NEDGE];
__device__ int g_bsum[NSCB];
__device__ int g_bbase[NSCB];

__device__ __forceinline__ float geluf(float x) {
    float t = tanhf(0.7978845608028654f * (x + 0.044715f * x * x * x));
    return 0.5f * x * (1.0f + t);
}

__device__ __forceinline__ uint32_t cvt_bf16x2(float v0, float v1) {
    uint32_t h;
    asm("cvt.rn.bf16x2.f32 %0, %1, %2;" : "=r"(h) : "f"(v1), "f"(v0));
    return h;
}

__device__ __forceinline__ void split_pair(float v0, float v1, uint32_t& h, uint32_t& l) {
    uint32_t hh = cvt_bf16x2(v0, v1);
    float h0 = __uint_as_float(hh << 16);
    float h1 = __uint_as_float(hh & 0xffff0000u);
    l = cvt_bf16x2(v0 - h0, v1 - h1);
    h = hh;
}

__device__ __forceinline__ void mma_bf16(float* c, const uint32_t* a, const uint32_t* b) {
    asm volatile("mma.sync.aligned.m16n8k16.row.col.f32.bf16.bf16.f32 "
                 "{%0,%1,%2,%3}, {%4,%5,%6,%7}, {%8,%9}, {%0,%1,%2,%3};"
                 : "+f"(c[0]), "+f"(c[1]), "+f"(c[2]), "+f"(c[3])
                 : "r"(a[0]), "r"(a[1]), "r"(a[2]), "r"(a[3]),
                   "r"(b[0]), "r"(b[1]));
}

// ---------------- pre-split weights ----------------
struct WSplit { const float* src[NWMAT]; int nn[NWMAT]; };
__global__ void split_weights(WSplit ws) {
    int m = blockIdx.y;
    int idx = blockIdx.x * 256 + threadIdx.x;
    int kp = idx >> 7, n = idx & 127;
    const float* s = ws.src[m];
    int N = ws.nn[m];
    float v0 = (n < N) ? s[(size_t)(2 * kp) * N + n] : 0.0f;
    float v1 = (n < N) ? s[(size_t)(2 * kp + 1) * N + n] : 0.0f;
    uint32_t h, l;
    split_pair(v0, v1, h, l);
    g_wh[m * 8192 + idx] = h;
    g_wl[m * 8192 + idx] = l;
}

// ---------------- input prep ----------------
__global__ void prep_inputs(const float* __restrict__ xp,
                            const float* __restrict__ ei, const int* __restrict__ xi,
                            const float* __restrict__ en, const int* __restrict__ xn) {
    int idx = blockIdx.x * 256 + threadIdx.x;
    const int n1 = NPAT * 64;
    const int n2 = n1 + NICD * 64;
    const int n3 = n2 + NNDC * 64;
    if (idx < n1) {
        float2 v = *reinterpret_cast<const float2*>(&xp[(size_t)(idx >> 6) * CDIM + 2 * (idx & 63)]);
        g_gh[idx] = cvt_bf16x2(v.x, v.y);
    } else if (idx < n3) {
        int j, node;
        const float* emb;
        const int* map;
        if (idx < n2) { j = idx - n1; emb = ei; map = xi; node = NPAT + (j >> 6); }
        else          { j = idx - n2; emb = en; map = xn; node = NPAT + NICD + (j >> 6); }
        int r = j >> 6, kp = j & 63;
        float2 v = *reinterpret_cast<const float2*>(&emb[(size_t)map[r] * CDIM + 2 * kp]);
        v.x = fmaxf(v.x, 0.0f);
        v.y = fmaxf(v.y, 0.0f);
        g_x[(size_t)node * CDIM + 2 * kp] = v.x;
        g_x[(size_t)node * CDIM + 2 * kp + 1] = v.y;
        g_xh[(size_t)node * 64 + kp] = cvt_bf16x2(v.x, v.y);
    }
}

// ---------------- GEMM body: A bf16 single-term, W 2-term hi/lo ----------------
// MODE: 0 plain fp32 (kqv), 1 relu+bf16 out (inproj), 2 blend+bf16 out (aproj), 3 sigmoid N=90
template<int MODE>
__device__ __forceinline__ void gemm_body(
    const uint32_t* __restrict__ XH,
    const uint32_t* __restrict__ WH, const uint32_t* __restrict__ WL,
    const float* __restrict__ bias,
    float* __restrict__ OutF, int ldo,
    uint32_t* __restrict__ OutH,
    const float* __restrict__ skipPtr, const float* __restrict__ xold,
    int M, int row0, int ncol0)
{
    __shared__ uint32_t Ah[128][20];
    __shared__ uint32_t Bh[16][72];
    __shared__ uint32_t Bl[16][72];

    const int tid = threadIdx.x;
    const int lane = tid & 31;
    const int wid = tid >> 5;
    const int warp_m = wid >> 1;
    const int warp_n = wid & 1;
    const int gi = lane >> 2;
    const int tig = lane & 3;

    float c[2][4][4];
#pragma unroll
    for (int am = 0; am < 2; am++)
#pragma unroll
        for (int an = 0; an < 4; an++)
#pragma unroll
            for (int j = 0; j < 4; j++) c[am][an][j] = 0.0f;

    const int ar = tid >> 1;
    const int akh = tid & 1;
    const bool aok = (row0 + ar) < M;
    const int bkp = tid >> 4;
    const int nl0 = (tid & 15) * 4;

    for (int kc2 = 0; kc2 < 64; kc2 += 16) {
        uint4 ha = make_uint4(0, 0, 0, 0), hb = ha;
        if (aok) {
            const uint32_t* ph = &XH[(size_t)(row0 + ar) * 64 + kc2 + akh * 8];
            ha = *reinterpret_cast<const uint4*>(ph);
            hb = *reinterpret_cast<const uint4*>(ph + 4);
        }
        *reinterpret_cast<uint4*>(&Ah[ar][akh * 8]) = ha;
        *reinterpret_cast<uint4*>(&Ah[ar][akh * 8 + 4]) = hb;
        *reinterpret_cast<uint4*>(&Bh[bkp][nl0]) =
            *reinterpret_cast<const uint4*>(&WH[(size_t)(kc2 + bkp) * 128 + ncol0 + nl0]);
        *reinterpret_cast<uint4*>(&Bl[bkp][nl0]) =
            *reinterpret_cast<const uint4*>(&WL[(size_t)(kc2 + bkp) * 128 + ncol0 + nl0]);
        __syncthreads();

#pragma unroll
        for (int ks = 0; ks < 2; ks++) {
            const int kb = ks * 8;
            uint32_t ah[2][4];
#pragma unroll
            for (int am = 0; am < 2; am++) {
                int rb = warp_m * 32 + am * 16 + gi;
                ah[am][0] = Ah[rb][kb + tig];
                ah[am][1] = Ah[rb + 8][kb + tig];
                ah[am][2] = Ah[rb][kb + 4 + tig];
                ah[am][3] = Ah[rb + 8][kb + 4 + tig];
            }
#pragma unroll
            for (int an = 0; an < 4; an++) {
                int nc = warp_n * 32 + an * 8 + gi;
                uint32_t bh[2], bl[2];
                bh[0] = Bh[kb + tig][nc];
                bh[1] = Bh[kb + 4 + tig][nc];
                bl[0] = Bl[kb + tig][nc];
                bl[1] = Bl[kb + 4 + tig][nc];
#pragma unroll
                for (int am = 0; am < 2; am++) {
                    mma_bf16(c[am][an], ah[am], bh);
                    mma_bf16(c[am][an], ah[am], bl);
                }
            }
        }
        __syncthreads();
    }

    float sa = 0.f, sb = 0.f;
    if (MODE == 2) {
        float s = 1.0f / (1.0f + __expf(-*skipPtr));
        sa = s; sb = 1.0f - s;
    }
#pragma unroll
    for (int am = 0; am < 2; am++) {
#pragma unroll
        for (int an = 0; an < 4; an++) {
            int col = ncol0 + warp_n * 32 + an * 8 + tig * 2;
#pragma unroll
            for (int half = 0; half < 2; half++) {
                int row = row0 + warp_m * 32 + am * 16 + gi + half * 8;
                if (row >= M) continue;
                float b0 = (MODE == 3) ? ((col < OUTD) ? bias[col] : 0.0f) : bias[col];
                float b1 = (MODE == 3) ? ((col + 1 < OUTD) ? bias[col + 1] : 0.0f) : bias[col + 1];
                float v0 = c[am][an][half * 2 + 0] + b0;
                float v1 = c[am][an][half * 2 + 1] + b1;
                if (MODE == 1) { v0 = fmaxf(v0, 0.0f); v1 = fmaxf(v1, 0.0f); }
                else if (MODE == 2) {
                    v0 = sa * v0 + sb * xold[(size_t)row * CDIM + col];
                    v1 = sa * v1 + sb * xold[(size_t)row * CDIM + col + 1];
                } else if (MODE == 3) {
                    v0 = 1.0f / (1.0f + __expf(-v0));
                    v1 = 1.0f / (1.0f + __expf(-v1));
                }
                if (MODE == 3) {
                    if (col < OUTD)     OutF[(size_t)row * ldo + col] = v0;
                    if (col + 1 < OUTD) OutF[(size_t)row * ldo + col + 1] = v1;
                } else {
                    OutF[(size_t)row * CDIM + col] = v0;
                    OutF[(size_t)row * CDIM + col + 1] = v1;
                    if (MODE == 1 || MODE == 2)
                        OutH[(size_t)row * 64 + (col >> 1)] = cvt_bf16x2(v0, v1);
                }
            }
        }
    }
}

// ---------------- GEMM wrappers ----------------
__global__ __launch_bounds__(256, 4) void gemm_in(const float* __restrict__ bias)
{
    gemm_body<1>(g_gh, g_wh, g_wl, bias,
                 g_x, CDIM, g_xh, nullptr, nullptr,
                 NPAT, blockIdx.x * 128, blockIdx.y * 64);
}

__global__ __launch_bounds__(256, 4) void gemm_kqv(
    const float* __restrict__ kb, const float* __restrict__ qb,
    const float* __restrict__ vb, int l, int jmode)
{
    const int bx = blockIdx.x;
    int ty, bl;
    if (bx < NBP)            { ty = 0; bl = bx; }
    else if (bx < NBP + NBI) { ty = 1; bl = bx - NBP; }
    else                     { ty = 2; bl = bx - NBP - NBI; }
    const int M = (ty == 0) ? NPAT : (ty == 1) ? NICD : NNDC;
    const int toff = (ty == 0) ? 0 : (ty == 1) ? NPAT : NPAT + NICD;
    const int j = (jmode == 0) ? (blockIdx.y == 0 ? 0 : 2) : 1;
    const int widx = 1 + l * 9 + j * 3 + ty;
    const float* bias = ((j == 0) ? kb : (j == 1) ? qb : vb) + (size_t)(l * 3 + ty) * CDIM;
    float* outp = ((j == 0) ? g_k : (j == 1) ? g_q : g_v) + (size_t)toff * CDIM;
    gemm_body<0>(g_xh + (size_t)toff * 64,
                 g_wh + (size_t)widx * 8192, g_wl + (size_t)widx * 8192, bias,
                 outp, CDIM, nullptr, nullptr, nullptr,
                 M, bl * 128, blockIdx.z * 64);
}

__global__ __launch_bounds__(256, 4) void gemm_ap_pat(
    const float* __restrict__ ab, const float* __restrict__ skip, int l)
{
    const int widx = 19 + l * 3;
    gemm_body<2>(g_gh,
                 g_wh + (size_t)widx * 8192, g_wl + (size_t)widx * 8192,
                 ab + (size_t)(l * 3) * CDIM,
                 g_x, CDIM, g_xh,
                 skip + (l * 3), g_x,
                 NPAT, blockIdx.x * 128, blockIdx.y * 64);
}

__global__ __launch_bounds__(256, 4) void gemm_ap_ind(
    const float* __restrict__ ab, const float* __restrict__ skip, int l)
{
    const int bx = blockIdx.x;
    int ty, bl;
    if (bx < NBI) { ty = 1; bl = bx; }
    else          { ty = 2; bl = bx - NBI; }
    const int M = (ty == 1) ? NICD : NNDC;
    const int toff = (ty == 1) ? NPAT : NPAT + NICD;
    const int widx = 19 + l * 3 + ty;
    gemm_body<2>(g_gh + (size_t)toff * 64,
                 g_wh + (size_t)widx * 8192, g_wl + (size_t)widx * 8192,
                 ab + (size_t)(l * 3 + ty) * CDIM,
                 g_x + (size_t)toff * CDIM, CDIM,
                 g_xh + (size_t)toff * 64,
                 skip + (l * 3 + ty), g_x + (size_t)toff * CDIM,
                 M, bl * 128, blockIdx.y * 64);
}

__global__ __launch_bounds__(256, 4) void gemm_o(
    const float* __restrict__ bias, float* __restrict__ out)
{
    gemm_body<3>(g_xh, g_wh + (size_t)25 * 8192, g_wl + (size_t)25 * 8192, bias,
                 out, OUTD, nullptr, nullptr, nullptr,
                 NPAT, blockIdx.x * 128, blockIdx.y * 64);
}

// ---------------- CSR build ----------------
__global__ void csr_clear() {
    int i = blockIdx.x * blockDim.x + threadIdx.x;
    if (i < NSOFT) { g_cnt[i] = 0; g_cur[i] = 0; }
}

__global__ void csr_hist_pat(const int* __restrict__ d1, const int* __restrict__ d3) {
    int i = blockIdx.x * blockDim.x + threadIdx.x;
    if (i < NEDGE / 4) {
        int4 a = reinterpret_cast<const int4*>(d1)[i];
        atomicAdd(&g_cnt[SOFF1 + a.x], 1);
        atomicAdd(&g_cnt[SOFF1 + a.y], 1);
        atomicAdd(&g_cnt[SOFF1 + a.z], 1);
        atomicAdd(&g_cnt[SOFF1 + a.w], 1);
        int4 b = reinterpret_cast<const int4*>(d3)[i];
        atomicAdd(&g_cnt[SOFF3 + b.x], 1);
        atomicAdd(&g_cnt[SOFF3 + b.y], 1);
        atomicAdd(&g_cnt[SOFF3 + b.z], 1);
        atomicAdd(&g_cnt[SOFF3 + b.w], 1);
    }
}

__global__ __launch_bounds__(256) void csr_hist_sm(const int* __restrict__ dst0,
                                                   const int* __restrict__ dst2) {
    __shared__ int h[NNDC];
    const int r = blockIdx.y;
    const int ndst = r ? NNDC : NICD;
    const int so = r ? SOFF2 : SOFF0;
    const int* __restrict__ dst = r ? dst2 : dst0;
    for (int i = threadIdx.x; i < ndst; i += 256) h[i] = 0;
    __syncthreads();
    const int tot = NEDGE / 4;
    for (int i = blockIdx.x * 256 + threadIdx.x; i < tot; i += gridDim.x * 256) {
        int4 a = reinterpret_cast<const int4*>(dst)[i];
        atomicAdd(&h[a.x], 1); atomicAdd(&h[a.y], 1);
        atomicAdd(&h[a.z], 1); atomicAdd(&h[a.w], 1);
    }
    __syncthreads();
    for (int i = threadIdx.x; i < ndst; i += 256)
        if (h[i]) atomicAdd(&g_cnt[so + i], h[i]);
}

__global__ __launch_bounds__(256) void scan_partial() {
    __shared__ int red[256];
    const int base = blockIdx.x * SCAN_TILE;
    int sum = 0;
#pragma unroll
    for (int j = 0; j < 4; j++) {
        int idx = base + j * 256 + threadIdx.x;
        sum += (idx < NSOFT) ? g_cnt[idx] : 0;
    }
    red[threadIdx.x] = sum;
    __syncthreads();
    for (int d = 128; d > 0; d >>= 1) {
        if (threadIdx.x < d) red[threadIdx.x] += red[threadIdx.x + d];
        __syncthreads();
    }
    if (threadIdx.x == 0) g_bsum[blockIdx.x] = red[0];
}

__global__ __launch_bounds__(128) void scan_base() {
    __shared__ int tmp[NSCB];
    int t = threadIdx.x;
    if (t < NSCB) tmp[t] = g_bsum[t];
    __syncthreads();
    if (t == 0) {
        int acc = 0;
        for (int i = 0; i < NSCB; i++) { int v = tmp[i]; tmp[i] = acc; acc += v; }
    }
    __syncthreads();
    if (t < NSCB) g_bbase[t] = tmp[t];
}

__global__ __launch_bounds__(256) void scan_write() {
    __shared__ int wsum[8];
    const int base = blockIdx.x * SCAN_TILE;
    const int t = threadIdx.x;
    const int lane = t & 31;
    const int w = t >> 5;
    int v[4];
    const int idx0 = base + t * 4;
#pragma unroll
    for (int j = 0; j < 4; j++) {
        int idx = idx0 + j;
        v[j] = (idx < NSOFT) ? g_cnt[idx] : 0;
    }
    int s1 = v[0] + v[1];
    int s2 = s1 + v[2];
    int tot = s2 + v[3];
    int x = tot;
#pragma unroll
    for (int d = 1; d < 32; d <<= 1) {
        int y = __shfl_up_sync(0xffffffff, x, d);
        if (lane >= d) x += y;
    }
    if (lane == 31) wsum[w] = x;
    __syncthreads();
    if (w == 0 && lane < 8) {
        int orig = wsum[lane];
        int ws = orig;
#pragma unroll
        for (int d = 1; d < 8; d <<= 1) {
            int y = __shfl_up_sync(0xff, ws, d);
            if (lane >= d) ws += y;
        }
        wsum[lane] = ws - orig;
    }
    __syncthreads();
    int ebase = g_bbase[blockIdx.x] + wsum[w] + (x - tot);
    int offs[4] = {0, v[0], s1, s2};
#pragma unroll
    for (int j = 0; j < 4; j++) {
        int idx = idx0 + j;
        if (idx < NSOFT) g_off[idx] = ebase + offs[j];
    }
}

__global__ void csr_scatter_pat(const int* __restrict__ s1, const int* __restrict__ d1,
                                const int* __restrict__ s3, const int* __restrict__ d3) {
    int i = blockIdx.x * blockDim.x + threadIdx.x;
    if (i < NEDGE) {
        int b1 = SOFF1 + d1[i];
        g_csr[g_off[b1] + atomicAdd(&g_cur[b1], 1)] = s1[i];
        int b3 = SOFF3 + d3[i];
        g_csr[g_off[b3] + atomicAdd(&g_cur[b3], 1)] = s3[i];
    }
}

__global__ __launch_bounds__(256) void csr_scatter_sm(
    const int* __restrict__ src0, const int* __restrict__ dst0,
    const int* __restrict__ src2, const int* __restrict__ dst2) {
    __shared__ int h[NNDC];
    __shared__ int base[NNDC];
    const int r = blockIdx.y;
    const int ndst = r ? NNDC : NICD;
    const int so = r ? SOFF2 : SOFF0;
    const int* __restrict__ dst = r ? dst2 : dst0;
    const int* __restrict__ src = r ? src2 : src0;
    const int chunk = (NEDGE + gridDim.x - 1) / gridDim.x;
    const int e0 = blockIdx.x * chunk;
    int e1 = e0 + chunk; if (e1 > NEDGE) e1 = NEDGE;

    for (int i = threadIdx.x; i < ndst; i += 256) h[i] = 0;
    __syncthreads();
    for (int e = e0 + threadIdx.x; e < e1; e += 256) atomicAdd(&h[dst[e]], 1);
    __syncthreads();
    for (int i = threadIdx.x; i < ndst; i += 256) {
        int cc = h[i];
        base[i] = cc ? atomicAdd(&g_cur[so + i], cc) : 0;
    }
    __syncthreads();
    for (int i = threadIdx.x; i < ndst; i += 256) h[i] = 0;
    __syncthreads();
    for (int e = e0 + threadIdx.x; e < e1; e += 256) {
        int d = dst[e];
        int loc = atomicAdd(&h[d], 1);
        g_csr[g_off[so + d] + base[d] + loc] = src[e];
    }
}

// ---------------- edge kernels (fp16 kr/vr gathers) ----------------
__device__ __forceinline__ void ld_half4(const __half* p, float& f0, float& f1,
                                         float& f2, float& f3) {
    uint2 raw = *reinterpret_cast<const uint2*>(p);
    float2 a = __half22float2(*reinterpret_cast<const __half2*>(&raw.x));
    float2 b = __half22float2(*reinterpret_cast<const __half2*>(&raw.y));
    f0 = a.x; f1 = a.y; f2 = b.x; f3 = b.y;
}

__global__ __launch_bounds__(256) void edge_pat(const float* __restrict__ prel)
{
    const int tid = threadIdx.x;
    const int w = tid >> 5;
    const int lane = tid & 31;
    const int h = lane >> 2;
    int d = blockIdx.x * 8 + w;

    float4 qv = *reinterpret_cast<const float4*>(&g_q[(size_t)d * CDIM + lane * 4]);
    float ax = 0.f, ay = 0.f, az = 0.f, aw2 = 0.f;
#pragma unroll
    for (int rr = 0; rr < 2; rr++) {
        const int rel = rr ? 3 : 1;
        const __half* krb = rr ? g_krN : g_krI;
        const __half* vrb = rr ? g_vrN : g_vrI;
        int base = (rr ? SOFF3 : SOFF1) + d;
        int st = g_off[base], n = g_cnt[base];
        float pf = prel[rel * 8 + h] * 0.25f;
        float es = 0.f, a0 = 0.f, a1 = 0.f, a2 = 0.f, a3 = 0.f;
        for (int i = 0; i < n; i++) {
            int s = g_csr[st + i];
            float k0, k1, k2, k3;
            ld_half4(&krb[(size_t)s * CDIM + lane * 4], k0, k1, k2, k3);
            float dot = qv.x * k0 + qv.y * k1 + qv.z * k2 + qv.w * k3;
            dot += __shfl_xor_sync(0xffffffff, dot, 1);
            dot += __shfl_xor_sync(0xffffffff, dot, 2);
            float e = __expf(dot * pf);
            float v0, v1, v2, v3;
            ld_half4(&vrb[(size_t)s * CDIM + lane * 4], v0, v1, v2, v3);
            es += e;
            a0 += e * v0; a1 += e * v1; a2 += e * v2; a3 += e * v3;
        }
        if (n > 0) {
            float inv = 1.0f / es;
            ax += a0 * inv; ay += a1 * inv; az += a2 * inv; aw2 += a3 * inv;
        }
    }
    float v0 = geluf(ax), v1 = geluf(ay), v2 = geluf(az), v3 = geluf(aw2);
    *reinterpret_cast<uint2*>(&g_gh[(size_t)d * 64 + lane * 2]) =
        make_uint2(cvt_bf16x2(v0, v1), cvt_bf16x2(v2, v3));
}

__global__ __launch_bounds__(256) void edge_ind(const float* __restrict__ prel)
{
    __shared__ float sacc[8][128];
    __shared__ float ses[8][8];
    const int bb = blockIdx.x;
    const int tid = threadIdx.x;
    const int w = tid >> 5;
    const int lane = tid & 31;
    const int h = lane >> 2;

    int base;
    size_t nodeoff;
    const __half *krb, *vrb;
    float pf;
    if (bb < NICD) {
        base = SOFF0 + bb;
        nodeoff = (size_t)(NPAT + bb);
        krb = g_krP0; vrb = g_vrP0;
        pf = prel[0 * 8 + h] * 0.25f;
    } else {
        int d = bb - NICD;
        base = SOFF2 + d;
        nodeoff = (size_t)(NPAT + NICD + d);
        krb = g_krP1; vrb = g_vrP1;
        pf = prel[2 * 8 + h] * 0.25f;
    }
    float4 qv = *reinterpret_cast<const float4*>(&g_q[nodeoff * CDIM + lane * 4]);
    int st = g_off[base], n = g_cnt[base];
    float es = 0.f, a0 = 0.f, a1 = 0.f, a2 = 0.f, a3 = 0.f;
    for (int i = w; i < n; i += 8) {
        int s = g_csr[st + i];
        float k0, k1, k2, k3;
        ld_half4(&krb[(size_t)s * CDIM + lane * 4], k0, k1, k2, k3);
        float dot = qv.x * k0 + qv.y * k1 + qv.z * k2 + qv.w * k3;
        dot += __shfl_xor_sync(0xffffffff, dot, 1);
        dot += __shfl_xor_sync(0xffffffff, dot, 2);
        float e = __expf(dot * pf);
        float v0, v1, v2, v3;
        ld_half4(&vrb[(size_t)s * CDIM + lane * 4], v0, v1, v2, v3);
        es += e;
        a0 += e * v0; a1 += e * v1; a2 += e * v2; a3 += e * v3;
    }
    *reinterpret_cast<float4*>(&sacc[w][lane * 4]) = make_float4(a0, a1, a2, a3);
    if ((lane & 3) == 0) ses[w][h] = es;
    __syncthreads();
    if (tid < 64) {
        int col0 = 2 * tid;
        float s0 = 0.f, s1 = 0.f, e = 0.f;
#pragma unroll
        for (int ww = 0; ww < 8; ww++) {
            s0 += sacc[ww][col0];
            s1 += sacc[ww][col0 + 1];
            e  += ses[ww][tid >> 3];
        }
        float v0 = (e > 0.f) ? s0 / e : 0.0f;
        float v1 = (e > 0.f) ? s1 / e : 0.0f;
        v0 = geluf(v0); v1 = geluf(v1);
        g_gh[nodeoff * 64 + tid] = cvt_bf16x2(v0, v1);
    }
}

// ---------------- merged per-relation K/V transform (fp16 outputs) ----------------
struct ReltAll {
    const float* A[4];
    const float* Mw[4];
};
__global__ __launch_bounds__(128) void relt_all(ReltAll ra)
{
    __shared__ float ks[32][128];
    __shared__ float vs[32][128];
    const int tid = threadIdx.x;
    const int bx = blockIdx.x;
    const int h = tid >> 4;
    const int e = tid & 15;

    int node0, nsrc, srcoff;
    const float *A0, *M0, *A1, *M1;
    __half *kr0, *vr0, *kr1, *vr1;
    bool two;
    if (bx < RTP) {
        node0 = bx * 32; nsrc = NPAT; srcoff = 0; two = true;
        A0 = ra.A[0]; M0 = ra.Mw[0]; A1 = ra.A[2]; M1 = ra.Mw[2];
        kr0 = g_krP0; vr0 = g_vrP0; kr1 = g_krP1; vr1 = g_vrP1;
    } else if (bx < RTP + RTI) {
        node0 = (bx - RTP) * 32; nsrc = NICD; srcoff = NPAT; two = false;
        A0 = ra.A[1]; M0 = ra.Mw[1]; A1 = nullptr; M1 = nullptr;
        kr0 = g_krI; vr0 = g_vrI; kr1 = nullptr; vr1 = nullptr;
    } else {
        node0 = (bx - RTP - RTI) * 32; nsrc = NNDC; srcoff = NPAT + NICD; two = false;
        A0 = ra.A[3]; M0 = ra.Mw[3]; A1 = nullptr; M1 = nullptr;
        kr0 = g_krN; vr0 = g_vrN; kr1 = nullptr; vr1 = nullptr;
    }

    float areg0[16], mreg0[16], areg1[16], mreg1[16];
#pragma unroll
    for (int d = 0; d < 16; d++) {
        areg0[d] = A0[(h * 16 + d) * 16 + e];
        mreg0[d] = M0[(h * 16 + d) * 16 + e];
        if (two) {
            areg1[d] = A1[(h * 16 + d) * 16 + e];
            mreg1[d] = M1[(h * 16 + d) * 16 + e];
        }
    }

    const float* kbase = g_k + (size_t)srcoff * CDIM;
    const float* vbase = g_v + (size_t)srcoff * CDIM;
    for (int i = tid; i < 32 * 32; i += 128) {
        int r = i >> 5;
        int cidx = (i & 31) * 4;
        if (node0 + r < nsrc) {
            *reinterpret_cast<float4*>(&ks[r][cidx]) =
                *reinterpret_cast<const float4*>(&kbase[(size_t)(node0 + r) * CDIM + cidx]);
            *reinterpret_cast<float4*>(&vs[r][cidx]) =
                *reinterpret_cast<const float4*>(&vbase[(size_t)(node0 + r) * CDIM + cidx]);
        }
    }
    __syncthreads();

    int nmax = nsrc - node0; if (nmax > 32) nmax = 32;
    for (int n = 0; n < nmax; n++) {
        float acck0 = 0.f, accv0 = 0.f, acck1 = 0.f, accv1 = 0.f;
#pragma unroll
        for (int d4 = 0; d4 < 4; d4++) {
            float4 kq = *reinterpret_cast<const float4*>(&ks[n][h * 16 + d4 * 4]);
            float4 vq = *reinterpret_cast<const float4*>(&vs[n][h * 16 + d4 * 4]);
            float kk[4] = {kq.x, kq.y, kq.z, kq.w};
            float vv[4] = {vq.x, vq.y, vq.z, vq.w};
#pragma unroll
            for (int j = 0; j < 4; j++) {
                int d = d4 * 4 + j;
                acck0 = fmaf(kk[j], areg0[d], acck0);
                accv0 = fmaf(vv[j], mreg0[d], accv0);
                if (two) {
                    acck1 = fmaf(kk[j], areg1[d], acck1);
                    accv1 = fmaf(vv[j], mreg1[d], accv1);
                }
            }
        }
        size_t o = (size_t)(node0 + n) * CDIM + h * 16 + e;
        kr0[o] = __float2half(acck0); vr0[o] = __float2half(accv0);
        if (two) { kr1[o] = __float2half(acck1); vr1[o] = __float2half(accv1); }
    }
}

// ---------------- host ----------------
extern "C" void kernel_launch(void* const* d_in, const int* in_sizes, int n_in,
                              void* d_out, int out_size)
{
    const float* x_patient = (const float*)d_in[0];
    const float* w_in      = (const float*)d_in[1];
    const float* b_in      = (const float*)d_in[2];
    const float* emb_icd   = (const float*)d_in[3];
    const float* emb_ndc   = (const float*)d_in[4];
    const float* kw = (const float*)d_in[5];
    const float* kb = (const float*)d_in[6];
    const float* qw = (const float*)d_in[7];
    const float* qb = (const float*)d_in[8];
    const float* vw = (const float*)d_in[9];
    const float* vb = (const float*)d_in[10];
    const float* aw = (const float*)d_in[11];
    const float* ab = (const float*)d_in[12];
    const float* skip  = (const float*)d_in[13];
    const float* a_rel = (const float*)d_in[14];
    const float* m_rel = (const float*)d_in[15];
    const float* p_rel = (const float*)d_in[16];
    const float* w_out = (const float*)d_in[17];
    const float* b_out = (const float*)d_in[18];
    const int* x_icd = (const int*)d_in[19];
    const int* x_ndc = (const int*)d_in[20];
    const int* esrc[4] = {(const int*)d_in[21], (const int*)d_in[23],
                          (const int*)d_in[25], (const int*)d_in[27]};
    const int* edst[4] = {(const int*)d_in[22], (const int*)d_in[24],
                          (const int*)d_in[26], (const int*)d_in[28]};
    float* out = (float*)d_out;

    cudaStream_t s2;
    cudaStreamCreateWithFlags(&s2, cudaStreamNonBlocking);
    cudaEvent_t evFork, evCsr, evX0, evX1, evQ0, evQ1, evR0, evR1, evS0, evS1;
    cudaEventCreateWithFlags(&evFork, cudaEventDisableTiming);
    cudaEventCreateWithFlags(&evCsr,  cudaEventDisableTiming);
    cudaEventCreateWithFlags(&evX0,   cudaEventDisableTiming);
    cudaEventCreateWithFlags(&evX1,   cudaEventDisableTiming);
    cudaEventCreateWithFlags(&evQ0,   cudaEventDisableTiming);
    cudaEventCreateWithFlags(&evQ1,   cudaEventDisableTiming);
    cudaEventCreateWithFlags(&evR0,   cudaEventDisableTiming);
    cudaEventCreateWithFlags(&evR1,   cudaEventDisableTiming);
    cudaEventCreateWithFlags(&evS0,   cudaEventDisableTiming);
    cudaEventCreateWithFlags(&evS1,   cudaEventDisableTiming);
    cudaEvent_t evX[2] = {evX0, evX1};
    cudaEvent_t evQ[2] = {evQ0, evQ1};
    cudaEvent_t evR[2] = {evR0, evR1};
    cudaEvent_t evS[2] = {evS0, evS1};

    // ---- fork CSR build onto s2 ----
    cudaEventRecord(evFork, 0);
    cudaStreamWaitEvent(s2, evFork, 0);
    csr_clear<<<(NSOFT + 255) / 256, 256, 0, s2>>>();
    csr_hist_pat<<<(NEDGE / 4 + 255) / 256, 256, 0, s2>>>(edst[1], edst[3]);
    {
        dim3 gh(48, 2);
        csr_hist_sm<<<gh, 256, 0, s2>>>(edst[0], edst[2]);
    }
    scan_partial<<<NSCB, 256, 0, s2>>>();
    scan_base<<<1, 128, 0, s2>>>();
    scan_write<<<NSCB, 256, 0, s2>>>();
    csr_scatter_pat<<<(NEDGE + 255) / 256, 256, 0, s2>>>(esrc[1], edst[1], esrc[3], edst[3]);
    {
        dim3 gs(64, 2);
        csr_scatter_sm<<<gs, 256, 0, s2>>>(esrc[0], edst[0], esrc[2], edst[2]);
    }
    cudaEventRecord(evCsr, s2);

    // ---- main: weights / inputs / in-proj ----
    {
        WSplit ws;
        ws.src[0] = w_in; ws.nn[0] = CDIM;
        const float* wsrc[3] = {kw, qw, vw};
        for (int l = 0; l < 2; l++)
            for (int j = 0; j < 3; j++)
                for (int ty = 0; ty < 3; ty++) {
                    ws.src[1 + l * 9 + j * 3 + ty] = wsrc[j] + (size_t)(l * 3 + ty) * CDIM * CDIM;
                    ws.nn[1 + l * 9 + j * 3 + ty] = CDIM;
                }
        for (int l = 0; l < 2; l++)
            for (int ty = 0; ty < 3; ty++) {
                ws.src[19 + l * 3 + ty] = aw + (size_t)(l * 3 + ty) * CDIM * CDIM;
                ws.nn[19 + l * 3 + ty] = CDIM;
            }
        ws.src[25] = w_out; ws.nn[25] = OUTD;
        dim3 g(32, NWMAT);
        split_weights<<<g, 256>>>(ws);
    }
    prep_inputs<<<(NTOTAL * 64 + 255) / 256, 256>>>(x_patient, emb_icd, x_icd, emb_ndc, x_ndc);
    {
        dim3 g(NBP, 2);
        gemm_in<<<g, 256>>>(b_in);
    }
    cudaEventRecord(evX[0], 0);

    for (int l = 0; l < 2; l++) {
        // s2: Q GEMM
        cudaStreamWaitEvent(s2, evX[l], 0);
        {
            dim3 gq(NBALL, 1, 2);
            gemm_kqv<<<gq, 256, 0, s2>>>(kb, qb, vb, l, 1);
        }
        cudaEventRecord(evQ[l], s2);

        // main: K and V GEMMs + relation transforms
        {
            dim3 gkv(NBALL, 2, 2);
            gemm_kqv<<<gkv, 256>>>(kb, qb, vb, l, 0);
        }
        {
            ReltAll ra;
            for (int r = 0; r < 4; r++) {
                ra.A[r]  = a_rel + (size_t)(l * 4 + r) * HH * DD * DD;
                ra.Mw[r] = m_rel + (size_t)(l * 4 + r) * HH * DD * DD;
            }
            relt_all<<<RTALL, 128>>>(ra);
        }
        cudaEventRecord(evR[l], 0);

        // s2 chain B: edge_ind -> aproj_ind
        cudaStreamWaitEvent(s2, evR[l], 0);
        edge_ind<<<EBLK, 256, 0, s2>>>(p_rel + l * 32);
        {
            dim3 gi(NBI + NBN, 2);
            gemm_ap_ind<<<gi, 256, 0, s2>>>(ab, skip, l);
        }
        cudaEventRecord(evS[l], s2);

        // main chain A: edge_pat -> aproj_pat
        cudaStreamWaitEvent(0, evQ[l], 0);
        if (l == 0) cudaStreamWaitEvent(0, evCsr, 0);
        edge_pat<<<EPB, 256>>>(p_rel + l * 32);
        {
            dim3 gp(NBP, 2);
            gemm_ap_pat<<<gp, 256>>>(ab, skip, l);
        }

        cudaStreamWaitEvent(0, evS[l], 0);
        if (l == 0) cudaEventRecord(evX[1], 0);
    }

    {
        dim3 g(NBP, 2);
        gemm_o<<<g, 256>>>(b_out, out);
    }

    cudaEventDestroy(evFork);
    cudaEventDestroy(evCsr);
    cudaEventDestroy(evX0);
    cudaEventDestroy(evX1);
    cudaEventDestroy(evQ0);
    cudaEventDestroy(evQ1);
    cudaEventDestroy(evR0);
    cudaEventDestroy(evR1);
    cudaEventDestroy(evS0);
    cudaEventDestroy(evS1);
    cudaStreamDestroy(s2);
}

// round 17
// speedup vs baseline: 3.1807x; 1.0754x over previous
#include <cuda_runtime.h>
#include <cuda_fp16.h>
#include <math.h>
#include <stdint.h>

#define NPAT 50000
#define NICD 591
#define NNDC 2042
#define NTOTAL 52633
#define NSOFT 102633
#define CDIM 128
#define HH 8
#define DD 16
#define NEDGE 250000
#define OUTD 90

#define SOFF0 0
#define SOFF1 NICD
#define SOFF2 (NICD + NPAT)
#define SOFF3 (NICD + NPAT + NNDC)

#define NBP 391
#define NBI 5
#define NBN 16
#define NBALL (NBP + NBI + NBN)

#define EPB 6250
#define EBLK (NICD + NNDC)

#define NWMAT 26

#define SCAN_TILE 1024
#define NSCB ((NSOFT + SCAN_TILE - 1) / SCAN_TILE)

// ---------------- scratch ----------------
__device__ float g_x[NTOTAL * CDIM];
__device__ float g_q[NTOTAL * CDIM];
__device__ __half g_krP0[NPAT * CDIM];
__device__ __half g_vrP0[NPAT * CDIM];
__device__ __half g_krP1[NPAT * CDIM];
__device__ __half g_vrP1[NPAT * CDIM];
__device__ __half g_krI[NICD * CDIM];
__device__ __half g_vrI[NICD * CDIM];
__device__ __half g_krN[NNDC * CDIM];
__device__ __half g_vrN[NNDC * CDIM];
__device__ uint32_t g_xh[NTOTAL * 64];
__device__ uint32_t g_gh[NTOTAL * 64];
__device__ uint32_t g_wh[NWMAT * 8192];
__device__ uint32_t g_wl[NWMAT * 8192];
__device__ int g_cnt[NSOFT];
__device__ int g_off[NSOFT];
__device__ int g_cur[NSOFT];
__device__ int g_csr[4 * NEDGE];
__device__ int g_bsum[NSCB];
__device__ int g_bbase[NSCB];

__device__ __forceinline__ float geluf(float x) {
    float t = tanhf(0.7978845608028654f * (x + 0.044715f * x * x * x));
    return 0.5f * x * (1.0f + t);
}

__device__ __forceinline__ uint32_t cvt_bf16x2(float v0, float v1) {
    uint32_t h;
    asm("cvt.rn.bf16x2.f32 %0, %1, %2;" : "=r"(h) : "f"(v1), "f"(v0));
    return h;
}

__device__ __forceinline__ void split_pair(float v0, float v1, uint32_t& h, uint32_t& l) {
    uint32_t hh = cvt_bf16x2(v0, v1);
    float h0 = __uint_as_float(hh << 16);
    float h1 = __uint_as_float(hh & 0xffff0000u);
    l = cvt_bf16x2(v0 - h0, v1 - h1);
    h = hh;
}

__device__ __forceinline__ void mma_bf16(float* c, const uint32_t* a, const uint32_t* b) {
    asm volatile("mma.sync.aligned.m16n8k16.row.col.f32.bf16.bf16.f32 "
                 "{%0,%1,%2,%3}, {%4,%5,%6,%7}, {%8,%9}, {%0,%1,%2,%3};"
                 : "+f"(c[0]), "+f"(c[1]), "+f"(c[2]), "+f"(c[3])
                 : "r"(a[0]), "r"(a[1]), "r"(a[2]), "r"(a[3]),
                   "r"(b[0]), "r"(b[1]));
}

// ---------------- pre-split weights ----------------
struct WSplit { const float* src[NWMAT]; int nn[NWMAT]; };
__global__ void split_weights(WSplit ws) {
    int m = blockIdx.y;
    int idx = blockIdx.x * 256 + threadIdx.x;
    int kp = idx >> 7, n = idx & 127;
    const float* s = ws.src[m];
    int N = ws.nn[m];
    float v0 = (n < N) ? s[(size_t)(2 * kp) * N + n] : 0.0f;
    float v1 = (n < N) ? s[(size_t)(2 * kp + 1) * N + n] : 0.0f;
    uint32_t h, l;
    split_pair(v0, v1, h, l);
    g_wh[m * 8192 + idx] = h;
    g_wl[m * 8192 + idx] = l;
}

// ---------------- input prep ----------------
__global__ void prep_inputs(const float* __restrict__ xp,
                            const float* __restrict__ ei, const int* __restrict__ xi,
                            const float* __restrict__ en, const int* __restrict__ xn) {
    int idx = blockIdx.x * 256 + threadIdx.x;
    const int n1 = NPAT * 64;
    const int n2 = n1 + NICD * 64;
    const int n3 = n2 + NNDC * 64;
    if (idx < n1) {
        float2 v = *reinterpret_cast<const float2*>(&xp[(size_t)(idx >> 6) * CDIM + 2 * (idx & 63)]);
        g_gh[idx] = cvt_bf16x2(v.x, v.y);
    } else if (idx < n3) {
        int j, node;
        const float* emb;
        const int* map;
        if (idx < n2) { j = idx - n1; emb = ei; map = xi; node = NPAT + (j >> 6); }
        else          { j = idx - n2; emb = en; map = xn; node = NPAT + NICD + (j >> 6); }
        int r = j >> 6, kp = j & 63;
        float2 v = *reinterpret_cast<const float2*>(&emb[(size_t)map[r] * CDIM + 2 * kp]);
        v.x = fmaxf(v.x, 0.0f);
        v.y = fmaxf(v.y, 0.0f);
        g_x[(size_t)node * CDIM + 2 * kp] = v.x;
        g_x[(size_t)node * CDIM + 2 * kp + 1] = v.y;
        g_xh[(size_t)node * 64 + kp] = cvt_bf16x2(v.x, v.y);
    }
}

// ---------------- GEMM mainloop macro-ish core (A bf16 1-term, W 2-term) ----------------
#define GEMM_MAINLOOP(XH, WH, WL)                                                            \
    for (int kc2 = 0; kc2 < 64; kc2 += 16) {                                                 \
        uint4 ha = make_uint4(0, 0, 0, 0), hb = ha;                                          \
        if (aok) {                                                                           \
            const uint32_t* ph = &(XH)[(size_t)(row0 + ar) * 64 + kc2 + akh * 8];            \
            ha = *reinterpret_cast<const uint4*>(ph);                                        \
            hb = *reinterpret_cast<const uint4*>(ph + 4);                                    \
        }                                                                                    \
        *reinterpret_cast<uint4*>(&Ah[ar][akh * 8]) = ha;                                    \
        *reinterpret_cast<uint4*>(&Ah[ar][akh * 8 + 4]) = hb;                                \
        *reinterpret_cast<uint4*>(&Bh[bkp][nl0]) =                                           \
            *reinterpret_cast<const uint4*>(&(WH)[(size_t)(kc2 + bkp) * 128 + ncol0 + nl0]); \
        *reinterpret_cast<uint4*>(&Bl[bkp][nl0]) =                                           \
            *reinterpret_cast<const uint4*>(&(WL)[(size_t)(kc2 + bkp) * 128 + ncol0 + nl0]); \
        __syncthreads();                                                                     \
        _Pragma("unroll")                                                                    \
        for (int ks = 0; ks < 2; ks++) {                                                     \
            const int kb2 = ks * 8;                                                          \
            uint32_t ah[2][4];                                                               \
            _Pragma("unroll")                                                                \
            for (int am = 0; am < 2; am++) {                                                 \
                int rb = warp_m * 32 + am * 16 + gi;                                         \
                ah[am][0] = Ah[rb][kb2 + tig];                                               \
                ah[am][1] = Ah[rb + 8][kb2 + tig];                                           \
                ah[am][2] = Ah[rb][kb2 + 4 + tig];                                           \
                ah[am][3] = Ah[rb + 8][kb2 + 4 + tig];                                       \
            }                                                                                \
            _Pragma("unroll")                                                                \
            for (int an = 0; an < 4; an++) {                                                 \
                int nc = warp_n * 32 + an * 8 + gi;                                          \
                uint32_t bh2[2], bl2[2];                                                     \
                bh2[0] = Bh[kb2 + tig][nc];                                                  \
                bh2[1] = Bh[kb2 + 4 + tig][nc];                                              \
                bl2[0] = Bl[kb2 + tig][nc];                                                  \
                bl2[1] = Bl[kb2 + 4 + tig][nc];                                              \
                _Pragma("unroll")                                                            \
                for (int am = 0; am < 2; am++) {                                             \
                    mma_bf16(c[am][an], ah[am], bh2);                                        \
                    mma_bf16(c[am][an], ah[am], bl2);                                        \
                }                                                                            \
            }                                                                                \
        }                                                                                    \
        __syncthreads();                                                                     \
    }

#define GEMM_PROLOG                                  \
    const int tid = threadIdx.x;                     \
    const int lane = tid & 31;                       \
    const int wid = tid >> 5;                        \
    const int warp_m = wid >> 1;                     \
    const int warp_n = wid & 1;                      \
    const int gi = lane >> 2;                        \
    const int tig = lane & 3;                        \
    float c[2][4][4];                                \
    _Pragma("unroll") for (int am = 0; am < 2; am++) \
    _Pragma("unroll") for (int an = 0; an < 4; an++) \
    _Pragma("unroll") for (int j2 = 0; j2 < 4; j2++) c[am][an][j2] = 0.0f; \
    const int ar = tid >> 1;                         \
    const int akh = tid & 1;                         \
    const bool aok = (row0 + ar) < M;                \
    const int bkp = tid >> 4;                        \
    const int nl0 = (tid & 15) * 4;

// ---------------- generic GEMM (in/ap/Q/out paths) ----------------
// MODE: 0 plain fp32 (Q), 1 relu+bf16 out (inproj), 2 blend+bf16 out (aproj), 3 sigmoid N=90
template<int MODE>
__device__ __forceinline__ void gemm_body(
    const uint32_t* __restrict__ XH,
    const uint32_t* __restrict__ WH, const uint32_t* __restrict__ WL,
    const float* __restrict__ bias,
    float* __restrict__ OutF, int ldo,
    uint32_t* __restrict__ OutH,
    const float* __restrict__ skipPtr, const float* __restrict__ xold,
    int M, int row0, int ncol0)
{
    __shared__ uint32_t Ah[128][20];
    __shared__ uint32_t Bh[16][72];
    __shared__ uint32_t Bl[16][72];

    GEMM_PROLOG
    GEMM_MAINLOOP(XH, WH, WL)

    float sa = 0.f, sb = 0.f;
    if (MODE == 2) {
        float s = 1.0f / (1.0f + __expf(-*skipPtr));
        sa = s; sb = 1.0f - s;
    }
#pragma unroll
    for (int am = 0; am < 2; am++) {
#pragma unroll
        for (int an = 0; an < 4; an++) {
            int col = ncol0 + warp_n * 32 + an * 8 + tig * 2;
#pragma unroll
            for (int half = 0; half < 2; half++) {
                int row = row0 + warp_m * 32 + am * 16 + gi + half * 8;
                if (row >= M) continue;
                float b0 = (MODE == 3) ? ((col < OUTD) ? bias[col] : 0.0f) : bias[col];
                float b1 = (MODE == 3) ? ((col + 1 < OUTD) ? bias[col + 1] : 0.0f) : bias[col + 1];
                float v0 = c[am][an][half * 2 + 0] + b0;
                float v1 = c[am][an][half * 2 + 1] + b1;
                if (MODE == 1) { v0 = fmaxf(v0, 0.0f); v1 = fmaxf(v1, 0.0f); }
                else if (MODE == 2) {
                    v0 = sa * v0 + sb * xold[(size_t)row * CDIM + col];
                    v1 = sa * v1 + sb * xold[(size_t)row * CDIM + col + 1];
                } else if (MODE == 3) {
                    v0 = 1.0f / (1.0f + __expf(-v0));
                    v1 = 1.0f / (1.0f + __expf(-v1));
                }
                if (MODE == 3) {
                    if (col < OUTD)     OutF[(size_t)row * ldo + col] = v0;
                    if (col + 1 < OUTD) OutF[(size_t)row * ldo + col + 1] = v1;
                } else {
                    OutF[(size_t)row * CDIM + col] = v0;
                    OutF[(size_t)row * CDIM + col + 1] = v1;
                    if (MODE == 1 || MODE == 2)
                        OutH[(size_t)row * 64 + (col >> 1)] = cvt_bf16x2(v0, v1);
                }
            }
        }
    }
}

// ---------------- fused K/V GEMM + relation transform ----------------
// grid (NBALL, 2 = K|V, 2 = N-half). Heads are column-aligned: cols [z*64, z*64+64) = heads [z*4, z*4+4).
// Epilogue stages the tile (bias added), then applies per-head 16x16 A (K) / M (V) and writes fp16 kr/vr.
__global__ __launch_bounds__(256, 4) void gemm_kv_fused(
    const float* __restrict__ kb, const float* __restrict__ vb,
    const float* __restrict__ a_rel, const float* __restrict__ m_rel, int l)
{
    __shared__ uint32_t Ah[128][20];
    __shared__ uint32_t Bh[16][72];
    __shared__ uint32_t Bl[16][72];
    __shared__ float tile[128][68];

    const int bx = blockIdx.x;
    int ty, bl;
    if (bx < NBP)            { ty = 0; bl = bx; }
    else if (bx < NBP + NBI) { ty = 1; bl = bx - NBP; }
    else                     { ty = 2; bl = bx - NBP - NBI; }
    const int M = (ty == 0) ? NPAT : (ty == 1) ? NICD : NNDC;
    const int toff = (ty == 0) ? 0 : (ty == 1) ? NPAT : NPAT + NICD;
    const int j = blockIdx.y;          // 0 = K, 1 = V
    const int ncol0 = blockIdx.z * 64;
    const int row0 = bl * 128;
    const int widx = 1 + l * 9 + (j == 0 ? 0 : 2) * 3 + ty;
    const float* bias = ((j == 0) ? kb : vb) + (size_t)(l * 3 + ty) * CDIM;
    const uint32_t* XH = g_xh + (size_t)toff * 64;
    const uint32_t* WH = g_wh + (size_t)widx * 8192;
    const uint32_t* WL = g_wl + (size_t)widx * 8192;

    GEMM_PROLOG
    GEMM_MAINLOOP(XH, WH, WL)

    // stage tile (bias added), local columns 0..63
#pragma unroll
    for (int am = 0; am < 2; am++) {
#pragma unroll
        for (int an = 0; an < 4; an++) {
            int coll = warp_n * 32 + an * 8 + tig * 2;
#pragma unroll
            for (int half = 0; half < 2; half++) {
                int rowl = warp_m * 32 + am * 16 + gi + half * 8;
                tile[rowl][coll]     = c[am][an][half * 2 + 0] + bias[ncol0 + coll];
                tile[rowl][coll + 1] = c[am][an][half * 2 + 1] + bias[ncol0 + coll + 1];
            }
        }
    }
    __syncthreads();

    // relation transform: thread -> (row-group, head-in-block, e)
    const float* T = (j == 0) ? a_rel : m_rel;
    const int h4 = (tid >> 4) & 3;
    const int e = tid & 15;
    const int rg = tid >> 6;
    const int ghead = blockIdx.z * 4 + h4;

    const int r0 = (ty == 0) ? 0 : (ty == 1) ? 1 : 3;
    __half* out0;
    __half* out1 = nullptr;
    if (ty == 0) {
        out0 = (j == 0) ? g_krP0 : g_vrP0;
        out1 = (j == 0) ? g_krP1 : g_vrP1;
    } else if (ty == 1) out0 = (j == 0) ? g_krI : g_vrI;
    else                out0 = (j == 0) ? g_krN : g_vrN;

    float t0[16], t1[16];
    const float* T0 = T + (size_t)(l * 4 + r0) * HH * DD * DD;
#pragma unroll
    for (int d = 0; d < 16; d++) t0[d] = T0[(ghead * 16 + d) * 16 + e];
    if (ty == 0) {
        const float* T1 = T + (size_t)(l * 4 + 2) * HH * DD * DD;
#pragma unroll
        for (int d = 0; d < 16; d++) t1[d] = T1[(ghead * 16 + d) * 16 + e];
    }

    for (int rr = 0; rr < 32; rr++) {
        int row = rg * 32 + rr;
        int grow = row0 + row;
        if (grow >= M) break;
        float acc0 = 0.f, acc1 = 0.f;
#pragma unroll
        for (int d = 0; d < 16; d++) {
            float kv = tile[row][h4 * 16 + d];
            acc0 = fmaf(kv, t0[d], acc0);
            if (ty == 0) acc1 = fmaf(kv, t1[d], acc1);
        }
        size_t o = (size_t)grow * CDIM + ghead * 16 + e;
        out0[o] = __float2half(acc0);
        if (ty == 0) out1[o] = __float2half(acc1);
    }
}

// ---------------- GEMM wrappers ----------------
__global__ __launch_bounds__(256, 4) void gemm_in(const float* __restrict__ bias)
{
    gemm_body<1>(g_gh, g_wh, g_wl, bias,
                 g_x, CDIM, g_xh, nullptr, nullptr,
                 NPAT, blockIdx.x * 128, blockIdx.y * 64);
}

// Q projection only
__global__ __launch_bounds__(256, 4) void gemm_q(
    const float* __restrict__ qb, int l)
{
    const int bx = blockIdx.x;
    int ty, bl;
    if (bx < NBP)            { ty = 0; bl = bx; }
    else if (bx < NBP + NBI) { ty = 1; bl = bx - NBP; }
    else                     { ty = 2; bl = bx - NBP - NBI; }
    const int M = (ty == 0) ? NPAT : (ty == 1) ? NICD : NNDC;
    const int toff = (ty == 0) ? 0 : (ty == 1) ? NPAT : NPAT + NICD;
    const int widx = 1 + l * 9 + 1 * 3 + ty;
    gemm_body<0>(g_xh + (size_t)toff * 64,
                 g_wh + (size_t)widx * 8192, g_wl + (size_t)widx * 8192,
                 qb + (size_t)(l * 3 + ty) * CDIM,
                 g_q + (size_t)toff * CDIM, CDIM, nullptr, nullptr, nullptr,
                 M, bl * 128, blockIdx.y * 64);
}

__global__ __launch_bounds__(256, 4) void gemm_ap_pat(
    const float* __restrict__ ab, const float* __restrict__ skip, int l)
{
    const int widx = 19 + l * 3;
    gemm_body<2>(g_gh,
                 g_wh + (size_t)widx * 8192, g_wl + (size_t)widx * 8192,
                 ab + (size_t)(l * 3) * CDIM,
                 g_x, CDIM, g_xh,
                 skip + (l * 3), g_x,
                 NPAT, blockIdx.x * 128, blockIdx.y * 64);
}

__global__ __launch_bounds__(256, 4) void gemm_ap_ind(
    const float* __restrict__ ab, const float* __restrict__ skip, int l)
{
    const int bx = blockIdx.x;
    int ty, bl;
    if (bx < NBI) { ty = 1; bl = bx; }
    else          { ty = 2; bl = bx - NBI; }
    const int M = (ty == 1) ? NICD : NNDC;
    const int toff = (ty == 1) ? NPAT : NPAT + NICD;
    const int widx = 19 + l * 3 + ty;
    gemm_body<2>(g_gh + (size_t)toff * 64,
                 g_wh + (size_t)widx * 8192, g_wl + (size_t)widx * 8192,
                 ab + (size_t)(l * 3 + ty) * CDIM,
                 g_x + (size_t)toff * CDIM, CDIM,
                 g_xh + (size_t)toff * 64,
                 skip + (l * 3 + ty), g_x + (size_t)toff * CDIM,
                 M, bl * 128, blockIdx.y * 64);
}

__global__ __launch_bounds__(256, 4) void gemm_o(
    const float* __restrict__ bias, float* __restrict__ out)
{
    gemm_body<3>(g_xh, g_wh + (size_t)25 * 8192, g_wl + (size_t)25 * 8192, bias,
                 out, OUTD, nullptr, nullptr, nullptr,
                 NPAT, blockIdx.x * 128, blockIdx.y * 64);
}

// ---------------- CSR build ----------------
__global__ void csr_clear() {
    int i = blockIdx.x * blockDim.x + threadIdx.x;
    if (i < NSOFT) { g_cnt[i] = 0; g_cur[i] = 0; }
}

__global__ void csr_hist_pat(const int* __restrict__ d1, const int* __restrict__ d3) {
    int i = blockIdx.x * blockDim.x + threadIdx.x;
    if (i < NEDGE / 4) {
        int4 a = reinterpret_cast<const int4*>(d1)[i];
        atomicAdd(&g_cnt[SOFF1 + a.x], 1);
        atomicAdd(&g_cnt[SOFF1 + a.y], 1);
        atomicAdd(&g_cnt[SOFF1 + a.z], 1);
        atomicAdd(&g_cnt[SOFF1 + a.w], 1);
        int4 b = reinterpret_cast<const int4*>(d3)[i];
        atomicAdd(&g_cnt[SOFF3 + b.x], 1);
        atomicAdd(&g_cnt[SOFF3 + b.y], 1);
        atomicAdd(&g_cnt[SOFF3 + b.z], 1);
        atomicAdd(&g_cnt[SOFF3 + b.w], 1);
    }
}

__global__ __launch_bounds__(256) void csr_hist_sm(const int* __restrict__ dst0,
                                                   const int* __restrict__ dst2) {
    __shared__ int h[NNDC];
    const int r = blockIdx.y;
    const int ndst = r ? NNDC : NICD;
    const int so = r ? SOFF2 : SOFF0;
    const int* __restrict__ dst = r ? dst2 : dst0;
    for (int i = threadIdx.x; i < ndst; i += 256) h[i] = 0;
    __syncthreads();
    const int tot = NEDGE / 4;
    for (int i = blockIdx.x * 256 + threadIdx.x; i < tot; i += gridDim.x * 256) {
        int4 a = reinterpret_cast<const int4*>(dst)[i];
        atomicAdd(&h[a.x], 1); atomicAdd(&h[a.y], 1);
        atomicAdd(&h[a.z], 1); atomicAdd(&h[a.w], 1);
    }
    __syncthreads();
    for (int i = threadIdx.x; i < ndst; i += 256)
        if (h[i]) atomicAdd(&g_cnt[so + i], h[i]);
}

__global__ __launch_bounds__(256) void scan_partial() {
    __shared__ int red[256];
    const int base = blockIdx.x * SCAN_TILE;
    int sum = 0;
#pragma unroll
    for (int j = 0; j < 4; j++) {
        int idx = base + j * 256 + threadIdx.x;
        sum += (idx < NSOFT) ? g_cnt[idx] : 0;
    }
    red[threadIdx.x] = sum;
    __syncthreads();
    for (int d = 128; d > 0; d >>= 1) {
        if (threadIdx.x < d) red[threadIdx.x] += red[threadIdx.x + d];
        __syncthreads();
    }
    if (threadIdx.x == 0) g_bsum[blockIdx.x] = red[0];
}

__global__ __launch_bounds__(128) void scan_base() {
    __shared__ int tmp[NSCB];
    int t = threadIdx.x;
    if (t < NSCB) tmp[t] = g_bsum[t];
    __syncthreads();
    if (t == 0) {
        int acc = 0;
        for (int i = 0; i < NSCB; i++) { int v = tmp[i]; tmp[i] = acc; acc += v; }
    }
    __syncthreads();
    if (t < NSCB) g_bbase[t] = tmp[t];
}

__global__ __launch_bounds__(256) void scan_write() {
    __shared__ int wsum[8];
    const int base = blockIdx.x * SCAN_TILE;
    const int t = threadIdx.x;
    const int lane = t & 31;
    const int w = t >> 5;
    int v[4];
    const int idx0 = base + t * 4;
#pragma unroll
    for (int j = 0; j < 4; j++) {
        int idx = idx0 + j;
        v[j] = (idx < NSOFT) ? g_cnt[idx] : 0;
    }
    int s1 = v[0] + v[1];
    int s2 = s1 + v[2];
    int tot = s2 + v[3];
    int x = tot;
#pragma unroll
    for (int d = 1; d < 32; d <<= 1) {
        int y = __shfl_up_sync(0xffffffff, x, d);
        if (lane >= d) x += y;
    }
    if (lane == 31) wsum[w] = x;
    __syncthreads();
    if (w == 0 && lane < 8) {
        int orig = wsum[lane];
        int ws = orig;
#pragma unroll
        for (int d = 1; d < 8; d <<= 1) {
            int y = __shfl_up_sync(0xff, ws, d);
            if (lane >= d) ws += y;
        }
        wsum[lane] = ws - orig;
    }
    __syncthreads();
    int ebase = g_bbase[blockIdx.x] + wsum[w] + (x - tot);
    int offs[4] = {0, v[0], s1, s2};
#pragma unroll
    for (int j = 0; j < 4; j++) {
        int idx = idx0 + j;
        if (idx < NSOFT) g_off[idx] = ebase + offs[j];
    }
}

__global__ void csr_scatter_pat(const int* __restrict__ s1, const int* __restrict__ d1,
                                const int* __restrict__ s3, const int* __restrict__ d3) {
    int i = blockIdx.x * blockDim.x + threadIdx.x;
    if (i < NEDGE) {
        int b1 = SOFF1 + d1[i];
        g_csr[g_off[b1] + atomicAdd(&g_cur[b1], 1)] = s1[i];
        int b3 = SOFF3 + d3[i];
        g_csr[g_off[b3] + atomicAdd(&g_cur[b3], 1)] = s3[i];
    }
}

__global__ __launch_bounds__(256) void csr_scatter_sm(
    const int* __restrict__ src0, const int* __restrict__ dst0,
    const int* __restrict__ src2, const int* __restrict__ dst2) {
    __shared__ int h[NNDC];
    __shared__ int base[NNDC];
    const int r = blockIdx.y;
    const int ndst = r ? NNDC : NICD;
    const int so = r ? SOFF2 : SOFF0;
    const int* __restrict__ dst = r ? dst2 : dst0;
    const int* __restrict__ src = r ? src2 : src0;
    const int chunk = (NEDGE + gridDim.x - 1) / gridDim.x;
    const int e0 = blockIdx.x * chunk;
    int e1 = e0 + chunk; if (e1 > NEDGE) e1 = NEDGE;

    for (int i = threadIdx.x; i < ndst; i += 256) h[i] = 0;
    __syncthreads();
    for (int e = e0 + threadIdx.x; e < e1; e += 256) atomicAdd(&h[dst[e]], 1);
    __syncthreads();
    for (int i = threadIdx.x; i < ndst; i += 256) {
        int cc = h[i];
        base[i] = cc ? atomicAdd(&g_cur[so + i], cc) : 0;
    }
    __syncthreads();
    for (int i = threadIdx.x; i < ndst; i += 256) h[i] = 0;
    __syncthreads();
    for (int e = e0 + threadIdx.x; e < e1; e += 256) {
        int d = dst[e];
        int loc = atomicAdd(&h[d], 1);
        g_csr[g_off[so + d] + base[d] + loc] = src[e];
    }
}

// ---------------- edge kernels (fp16 kr/vr gathers) ----------------
__device__ __forceinline__ void ld_half4(const __half* p, float& f0, float& f1,
                                         float& f2, float& f3) {
    uint2 raw = *reinterpret_cast<const uint2*>(p);
    float2 a = __half22float2(*reinterpret_cast<const __half2*>(&raw.x));
    float2 b = __half22float2(*reinterpret_cast<const __half2*>(&raw.y));
    f0 = a.x; f1 = a.y; f2 = b.x; f3 = b.y;
}

__global__ __launch_bounds__(256) void edge_pat(const float* __restrict__ prel)
{
    const int tid = threadIdx.x;
    const int w = tid >> 5;
    const int lane = tid & 31;
    const int h = lane >> 2;
    int d = blockIdx.x * 8 + w;

    float4 qv = *reinterpret_cast<const float4*>(&g_q[(size_t)d * CDIM + lane * 4]);
    float ax = 0.f, ay = 0.f, az = 0.f, aw2 = 0.f;
#pragma unroll
    for (int rr = 0; rr < 2; rr++) {
        const int rel = rr ? 3 : 1;
        const __half* krb = rr ? g_krN : g_krI;
        const __half* vrb = rr ? g_vrN : g_vrI;
        int base = (rr ? SOFF3 : SOFF1) + d;
        int st = g_off[base], n = g_cnt[base];
        float pf = prel[rel * 8 + h] * 0.25f;
        float es = 0.f, a0 = 0.f, a1 = 0.f, a2 = 0.f, a3 = 0.f;
        for (int i = 0; i < n; i++) {
            int s = g_csr[st + i];
            float k0, k1, k2, k3;
            ld_half4(&krb[(size_t)s * CDIM + lane * 4], k0, k1, k2, k3);
            float dot = qv.x * k0 + qv.y * k1 + qv.z * k2 + qv.w * k3;
            dot += __shfl_xor_sync(0xffffffff, dot, 1);
            dot += __shfl_xor_sync(0xffffffff, dot, 2);
            float e = __expf(dot * pf);
            float v0, v1, v2, v3;
            ld_half4(&vrb[(size_t)s * CDIM + lane * 4], v0, v1, v2, v3);
            es += e;
            a0 += e * v0; a1 += e * v1; a2 += e * v2; a3 += e * v3;
        }
        if (n > 0) {
            float inv = 1.0f / es;
            ax += a0 * inv; ay += a1 * inv; az += a2 * inv; aw2 += a3 * inv;
        }
    }
    float v0 = geluf(ax), v1 = geluf(ay), v2 = geluf(az), v3 = geluf(aw2);
    *reinterpret_cast<uint2*>(&g_gh[(size_t)d * 64 + lane * 2]) =
        make_uint2(cvt_bf16x2(v0, v1), cvt_bf16x2(v2, v3));
}

__global__ __launch_bounds__(256) void edge_ind(const float* __restrict__ prel)
{
    __shared__ float sacc[8][128];
    __shared__ float ses[8][8];
    const int bb = blockIdx.x;
    const int tid = threadIdx.x;
    const int w = tid >> 5;
    const int lane = tid & 31;
    const int h = lane >> 2;

    int base;
    size_t nodeoff;
    const __half *krb, *vrb;
    float pf;
    if (bb < NICD) {
        base = SOFF0 + bb;
        nodeoff = (size_t)(NPAT + bb);
        krb = g_krP0; vrb = g_vrP0;
        pf = prel[0 * 8 + h] * 0.25f;
    } else {
        int d = bb - NICD;
        base = SOFF2 + d;
        nodeoff = (size_t)(NPAT + NICD + d);
        krb = g_krP1; vrb = g_vrP1;
        pf = prel[2 * 8 + h] * 0.25f;
    }
    float4 qv = *reinterpret_cast<const float4*>(&g_q[nodeoff * CDIM + lane * 4]);
    int st = g_off[base], n = g_cnt[base];
    float es = 0.f, a0 = 0.f, a1 = 0.f, a2 = 0.f, a3 = 0.f;
    for (int i = w; i < n; i += 8) {
        int s = g_csr[st + i];
        float k0, k1, k2, k3;
        ld_half4(&krb[(size_t)s * CDIM + lane * 4], k0, k1, k2, k3);
        float dot = qv.x * k0 + qv.y * k1 + qv.z * k2 + qv.w * k3;
        dot += __shfl_xor_sync(0xffffffff, dot, 1);
        dot += __shfl_xor_sync(0xffffffff, dot, 2);
        float e = __expf(dot * pf);
        float v0, v1, v2, v3;
        ld_half4(&vrb[(size_t)s * CDIM + lane * 4], v0, v1, v2, v3);
        es += e;
        a0 += e * v0; a1 += e * v1; a2 += e * v2; a3 += e * v3;
    }
    *reinterpret_cast<float4*>(&sacc[w][lane * 4]) = make_float4(a0, a1, a2, a3);
    if ((lane & 3) == 0) ses[w][h] = es;
    __syncthreads();
    if (tid < 64) {
        int col0 = 2 * tid;
        float s0 = 0.f, s1 = 0.f, e = 0.f;
#pragma unroll
        for (int ww = 0; ww < 8; ww++) {
            s0 += sacc[ww][col0];
            s1 += sacc[ww][col0 + 1];
            e  += ses[ww][tid >> 3];
        }
        float v0 = (e > 0.f) ? s0 / e : 0.0f;
        float v1 = (e > 0.f) ? s1 / e : 0.0f;
        v0 = geluf(v0); v1 = geluf(v1);
        g_gh[nodeoff * 64 + tid] = cvt_bf16x2(v0, v1);
    }
}

// ---------------- host ----------------
extern "C" void kernel_launch(void* const* d_in, const int* in_sizes, int n_in,
                              void* d_out, int out_size)
{
    const float* x_patient = (const float*)d_in[0];
    const float* w_in      = (const float*)d_in[1];
    const float* b_in      = (const float*)d_in[2];
    const float* emb_icd   = (const float*)d_in[3];
    const float* emb_ndc   = (const float*)d_in[4];
    const float* kw = (const float*)d_in[5];
    const float* kb = (const float*)d_in[6];
    const float* qw = (const float*)d_in[7];
    const float* qb = (const float*)d_in[8];
    const float* vw = (const float*)d_in[9];
    const float* vb = (const float*)d_in[10];
    const float* aw = (const float*)d_in[11];
    const float* ab = (const float*)d_in[12];
    const float* skip  = (const float*)d_in[13];
    const float* a_rel = (const float*)d_in[14];
    const float* m_rel = (const float*)d_in[15];
    const float* p_rel = (const float*)d_in[16];
    const float* w_out = (const float*)d_in[17];
    const float* b_out = (const float*)d_in[18];
    const int* x_icd = (const int*)d_in[19];
    const int* x_ndc = (const int*)d_in[20];
    const int* esrc[4] = {(const int*)d_in[21], (const int*)d_in[23],
                          (const int*)d_in[25], (const int*)d_in[27]};
    const int* edst[4] = {(const int*)d_in[22], (const int*)d_in[24],
                          (const int*)d_in[26], (const int*)d_in[28]};
    float* out = (float*)d_out;

    cudaStream_t s2;
    cudaStreamCreateWithFlags(&s2, cudaStreamNonBlocking);
    cudaEvent_t evFork, evCsr, evX0, evX1, evQ0, evQ1, evR0, evR1, evS0, evS1;
    cudaEventCreateWithFlags(&evFork, cudaEventDisableTiming);
    cudaEventCreateWithFlags(&evCsr,  cudaEventDisableTiming);
    cudaEventCreateWithFlags(&evX0,   cudaEventDisableTiming);
    cudaEventCreateWithFlags(&evX1,   cudaEventDisableTiming);
    cudaEventCreateWithFlags(&evQ0,   cudaEventDisableTiming);
    cudaEventCreateWithFlags(&evQ1,   cudaEventDisableTiming);
    cudaEventCreateWithFlags(&evR0,   cudaEventDisableTiming);
    cudaEventCreateWithFlags(&evR1,   cudaEventDisableTiming);
    cudaEventCreateWithFlags(&evS0,   cudaEventDisableTiming);
    cudaEventCreateWithFlags(&evS1,   cudaEventDisableTiming);
    cudaEvent_t evX[2] = {evX0, evX1};
    cudaEvent_t evQ[2] = {evQ0, evQ1};
    cudaEvent_t evR[2] = {evR0, evR1};
    cudaEvent_t evS[2] = {evS0, evS1};

    // ---- fork CSR build onto s2 ----
    cudaEventRecord(evFork, 0);
    cudaStreamWaitEvent(s2, evFork, 0);
    csr_clear<<<(NSOFT + 255) / 256, 256, 0, s2>>>();
    csr_hist_pat<<<(NEDGE / 4 + 255) / 256, 256, 0, s2>>>(edst[1], edst[3]);
    {
        dim3 gh(48, 2);
        csr_hist_sm<<<gh, 256, 0, s2>>>(edst[0], edst[2]);
    }
    scan_partial<<<NSCB, 256, 0, s2>>>();
    scan_base<<<1, 128, 0, s2>>>();
    scan_write<<<NSCB, 256, 0, s2>>>();
    csr_scatter_pat<<<(NEDGE + 255) / 256, 256, 0, s2>>>(esrc[1], edst[1], esrc[3], edst[3]);
    {
        dim3 gs(64, 2);
        csr_scatter_sm<<<gs, 256, 0, s2>>>(esrc[0], edst[0], esrc[2], edst[2]);
    }
    cudaEventRecord(evCsr, s2);

    // ---- main: weights / inputs / in-proj ----
    {
        WSplit ws;
        ws.src[0] = w_in; ws.nn[0] = CDIM;
        const float* wsrc[3] = {kw, qw, vw};
        for (int l = 0; l < 2; l++)
            for (int j = 0; j < 3; j++)
                for (int ty = 0; ty < 3; ty++) {
                    ws.src[1 + l * 9 + j * 3 + ty] = wsrc[j] + (size_t)(l * 3 + ty) * CDIM * CDIM;
                    ws.nn[1 + l * 9 + j * 3 + ty] = CDIM;
                }
        for (int l = 0; l < 2; l++)
            for (int ty = 0; ty < 3; ty++) {
                ws.src[19 + l * 3 + ty] = aw + (size_t)(l * 3 + ty) * CDIM * CDIM;
                ws.nn[19 + l * 3 + ty] = CDIM;
            }
        ws.src[25] = w_out; ws.nn[25] = OUTD;
        dim3 g(32, NWMAT);
        split_weights<<<g, 256>>>(ws);
    }
    prep_inputs<<<(NTOTAL * 64 + 255) / 256, 256>>>(x_patient, emb_icd, x_icd, emb_ndc, x_ndc);
    {
        dim3 g(NBP, 2);
        gemm_in<<<g, 256>>>(b_in);
    }
    cudaEventRecord(evX[0], 0);

    for (int l = 0; l < 2; l++) {
        // s2: Q GEMM
        cudaStreamWaitEvent(s2, evX[l], 0);
        {
            dim3 gq(NBALL, 2);
            gemm_q<<<gq, 256, 0, s2>>>(qb, l);
        }
        cudaEventRecord(evQ[l], s2);

        // main: fused K/V GEMM + relation transform (produces fp16 kr/vr directly)
        {
            dim3 gkv(NBALL, 2, 2);
            gemm_kv_fused<<<gkv, 256>>>(kb, vb, a_rel, m_rel, l);
        }
        cudaEventRecord(evR[l], 0);

        // s2 chain B: edge_ind -> aproj_ind
        cudaStreamWaitEvent(s2, evR[l], 0);
        edge_ind<<<EBLK, 256, 0, s2>>>(p_rel + l * 32);
        {
            dim3 gi(NBI + NBN, 2);
            gemm_ap_ind<<<gi, 256, 0, s2>>>(ab, skip, l);
        }
        cudaEventRecord(evS[l], s2);

        // main chain A: edge_pat -> aproj_pat
        cudaStreamWaitEvent(0, evQ[l], 0);
        if (l == 0) cudaStreamWaitEvent(0, evCsr, 0);
        edge_pat<<<EPB, 256>>>(p_rel + l * 32);
        {
            dim3 gp(NBP, 2);
            gemm_ap_pat<<<gp, 256>>>(ab, skip, l);
        }

        cudaStreamWaitEvent(0, evS[l], 0);
        if (l == 0) cudaEventRecord(evX[1], 0);
    }

    {
        dim3 g(NBP, 2);
        gemm_o<<<g, 256>>>(b_out, out);
    }

    cudaEventDestroy(evFork);
    cudaEventDestroy(evCsr);
    cudaEventDestroy(evX0);
    cudaEventDestroy(evX1);
    cudaEventDestroy(evQ0);
    cudaEventDestroy(evQ1);
    cudaEventDestroy(evR0);
    cudaEventDestroy(evR1);
    cudaEventDestroy(evS0);
    cudaEventDestroy(evS1);
    cudaStreamDestroy(s2);
}